// round 4
// baseline (speedup 1.0000x reference)
#include <cuda_runtime.h>
#include <cuda_fp16.h>
#include <cuda_bf16.h>
#include <math.h>

#define N_NODES 50000
#define N_EDGES 800000
#define C 128
#define TE 128           // edges per tile
#define HST 136          // h tile stride (halfs): conflict-free B-frag LDS (HST/2 mod 32 == 4)
#define DST 132          // D^T tile stride (floats)

// ---------------- scratch (static device globals; no allocations) -------------
__device__ float g_pq[(size_t)N_NODES * 256];      // [N][256]: p (+b1) | q
__device__ float g_agg[(size_t)N_NODES * C];       // max-aggregation buffer
__device__ float g_x[(size_t)N_NODES * C];         // inter-layer node features
__device__ float g_Wc[C * 256];                    // node-gemm combined W1
__device__ __half g_w2hi[C * C];                   // W2^T hi plane [n][k] fp16
__device__ __half g_w2lo[C * C];                   // W2^T lo plane [n][k] fp16

// ---------------- float atomic max (signed-max / unsigned-min trick) ----------
__device__ __forceinline__ void atomicMaxF(float* a, float v) {
    if (v >= 0.0f) atomicMax((int*)a, __float_as_int(v));
    else           atomicMin((unsigned int*)a, __float_as_uint(v));
}

// ---------------- HMMA m16n8k16 fp16 ------------------------------------------
__device__ __forceinline__ void mma16816(float& d0, float& d1, float& d2, float& d3,
                                         unsigned a0, unsigned a1, unsigned a2, unsigned a3,
                                         unsigned b0, unsigned b1)
{
    asm volatile(
        "mma.sync.aligned.m16n8k16.row.col.f32.f16.f16.f32 "
        "{%0,%1,%2,%3},{%4,%5,%6,%7},{%8,%9},{%0,%1,%2,%3};\n"
        : "+f"(d0), "+f"(d1), "+f"(d2), "+f"(d3)
        : "r"(a0), "r"(a1), "r"(a2), "r"(a3), "r"(b0), "r"(b1));
}

// ---------------- prep: Wc from W1 --------------------------------------------
__global__ void prep_kernel(const float* __restrict__ W1, float* __restrict__ Wc) {
    int k = blockIdx.x;
    int j = threadIdx.x;
    if (j < C) Wc[k * 256 + j] = W1[k * C + j] - W1[(C + k) * C + j];
    else       Wc[k * 256 + j] = W1[(C + k) * C + (j - C)];
}

// ---------------- prep: split W2^T into fp16 hi/lo planes ----------------------
__global__ void w2split_kernel(const float* __restrict__ W2,
                               __half* __restrict__ hi,
                               __half* __restrict__ lo) {
    int n = blockIdx.x;
    int k = threadIdx.x;
    float w = W2[k * C + n];
    __half h = __float2half_rn(w);
    hi[n * C + k] = h;
    lo[n * C + k] = __float2half_rn(w - __half2float(h));
}

// ---------------- node GEMM: pq = x @ Wc (+ b1 on p half) ---------------------
__global__ void __launch_bounds__(256) node_gemm_kernel(
    const float* __restrict__ x, const float* __restrict__ Wc,
    const float* __restrict__ b1, float* __restrict__ pq, int N)
{
    __shared__ float xs[32 * C];
    int m0 = blockIdx.x * 32;
    int tid = threadIdx.x;

    for (int i = tid; i < 32 * C / 4; i += 256) {
        int r = i / (C / 4);
        int cc = i % (C / 4);
        float4 v = make_float4(0.f, 0.f, 0.f, 0.f);
        if (m0 + r < N) v = ((const float4*)(x + (size_t)(m0 + r) * C))[cc];
        ((float4*)xs)[i] = v;
    }
    __syncthreads();

    int col = tid;
    float acc[32];
#pragma unroll
    for (int r = 0; r < 32; r++) acc[r] = 0.f;

#pragma unroll 4
    for (int k = 0; k < C; k++) {
        float w = Wc[k * 256 + col];
#pragma unroll
        for (int r = 0; r < 32; r++) acc[r] = fmaf(xs[r * C + k], w, acc[r]);
    }

    float bias = (col < C) ? b1[col] : 0.f;
#pragma unroll
    for (int r = 0; r < 32; r++)
        if (m0 + r < N) pq[(size_t)(m0 + r) * 256 + col] = acc[r] + bias;
}

// ---------------- edge GEMM (tensor cores, fp16 A-split) + max aggregation ----
// 256 threads / 8 warps, 2 CTAs per SM. Warp w: channels w*16..+16, all 128 edges.
// u = relu(p[dst]+q[src]) @ W2;  W2 = Ah + Al (fp16 planes, regs);  h in fp16.
__global__ void __launch_bounds__(256, 2) edge_mma_kernel(
    const float* __restrict__ pq, const int* __restrict__ src,
    const int* __restrict__ dst,
    const __half* __restrict__ W2hi, const __half* __restrict__ W2lo,
    float* __restrict__ agg, int E)
{
    extern __shared__ char smraw[];
    __half* h_s = (__half*)smraw;                  // [TE][HST] fp16 h tile
    float* DT = (float*)(h_s + TE * HST);          // [C][DST]  u^T
    __shared__ int sidx[2 * TE];

    int tid = threadIdx.x;
    int wid = tid >> 5, lane = tid & 31;
    int g = lane >> 2, tig = lane & 3;
    int m0 = wid * 16;   // this warp's 16 output channels

    // Preload A fragments (W2^T hi/lo, all 8 k-steps) into registers.
    unsigned ah[8][4], al[8][4];
    {
        const unsigned* Hp = (const unsigned*)W2hi;
        const unsigned* Lp = (const unsigned*)W2lo;
#pragma unroll
        for (int ks = 0; ks < 8; ks++) {
            int k0 = ks * 16;
            int i00 = (m0 + g) * (C / 2) + (k0 + tig * 2) / 2;
            ah[ks][0] = Hp[i00];
            ah[ks][1] = Hp[i00 + 8 * (C / 2)];
            ah[ks][2] = Hp[i00 + 4];
            ah[ks][3] = Hp[i00 + 8 * (C / 2) + 4];
            al[ks][0] = Lp[i00];
            al[ks][1] = Lp[i00 + 8 * (C / 2)];
            al[ks][2] = Lp[i00 + 4];
            al[ks][3] = Lp[i00 + 8 * (C / 2) + 4];
        }
    }

    int ntiles = (E + TE - 1) / TE;
    for (int tile = blockIdx.x; tile < ntiles; tile += gridDim.x) {
        int e0 = tile * TE;
        __syncthreads();   // prev tile fully consumed

        // load indices (256 threads cover dst|src)
        {
            int e = (tid < TE) ? tid : (tid - TE);
            int gi = e0 + e;
            const int* arr = (tid < TE) ? dst : src;
            sidx[tid] = (gi < E) ? arr[gi] : 0;
        }
        __syncthreads();

        // gather + relu + fp16 convert: 2 threads/edge, 64 channels each
        {
            int e = tid >> 1;
            int ch = (tid & 1) * 64;
            const float4* prow = (const float4*)(pq + (size_t)sidx[e] * 256 + ch);
            const float4* qrow = (const float4*)(pq + (size_t)sidx[TE + e] * 256 + C + ch);
            uint2* hp = (uint2*)(h_s + e * HST + ch);
#pragma unroll
            for (int i = 0; i < 16; i++) {
                float4 a = prow[i];
                float4 b = qrow[i];
                __half2 hA = __floats2half2_rn(fmaxf(a.x + b.x, 0.f), fmaxf(a.y + b.y, 0.f));
                __half2 hB = __floats2half2_rn(fmaxf(a.z + b.z, 0.f), fmaxf(a.w + b.w, 0.f));
                hp[i] = make_uint2(*(unsigned*)&hA, *(unsigned*)&hB);
            }
        }
        __syncthreads();

        // MMA: 16 edge-subtiles of 8, K=128 (8 k-steps), 2 terms (Ah*B + Al*B)
#pragma unroll 1
        for (int et = 0; et < 16; et++) {
            int e0t = et * 8;
            float d0 = 0.f, d1 = 0.f, d2 = 0.f, d3 = 0.f;
#pragma unroll
            for (int ks = 0; ks < 8; ks++) {
                int k0 = ks * 16;
                const unsigned* bp = (const unsigned*)(h_s + (e0t + g) * HST + k0 + tig * 2);
                unsigned b0 = bp[0], b1 = bp[4];
                mma16816(d0, d1, d2, d3, ah[ks][0], ah[ks][1], ah[ks][2], ah[ks][3], b0, b1);
                mma16816(d0, d1, d2, d3, al[ks][0], al[ks][1], al[ks][2], al[ks][3], b0, b1);
            }
            *(float2*)&DT[(m0 + g) * DST + e0t + tig * 2]     = make_float2(d0, d1);
            *(float2*)&DT[(m0 + g + 8) * DST + e0t + tig * 2] = make_float2(d2, d3);
        }
        __syncthreads();

        // epilogue: edge-major lanes -> conflict-free DT column reads
        {
            int e = tid & 127;
            int ch = (tid >> 7) * 64;
            if (e0 + e < E) {
                int dn = sidx[e];
                float* arow = agg + (size_t)dn * C + ch;
#pragma unroll
                for (int i = 0; i < 16; i++) {
                    float4 cur = ((const float4*)arow)[i];
                    float v0 = DT[(ch + i * 4 + 0) * DST + e];
                    float v1 = DT[(ch + i * 4 + 1) * DST + e];
                    float v2 = DT[(ch + i * 4 + 2) * DST + e];
                    float v3 = DT[(ch + i * 4 + 3) * DST + e];
                    if (!(v0 <= cur.x)) atomicMaxF(arow + i * 4 + 0, v0);
                    if (!(v1 <= cur.y)) atomicMaxF(arow + i * 4 + 1, v1);
                    if (!(v2 <= cur.z)) atomicMaxF(arow + i * 4 + 2, v2);
                    if (!(v3 <= cur.w)) atomicMaxF(arow + i * 4 + 3, v3);
                }
            }
        }
    }
}

// ---------------- finalize: handle empty nodes, +b2, optional relu ------------
__global__ void finalize_kernel(const float* __restrict__ agg,
                                const float* __restrict__ b2,
                                float* __restrict__ out, int N, int do_relu)
{
    int idx = blockIdx.x * blockDim.x + threadIdx.x;
    if (idx >= N * C) return;
    int c = idx & (C - 1);
    float v = agg[idx];
    float o = isfinite(v) ? (v + b2[c]) : 0.f;
    if (do_relu) o = fmaxf(o, 0.f);
    out[idx] = o;
}

// ---------------- launch -------------------------------------------------------
extern "C" void kernel_launch(void* const* d_in, const int* in_sizes, int n_in,
                              void* d_out, int out_size)
{
    const float* x  = (const float*)d_in[0];
    const int*   ei = (const int*)d_in[1];
    int N = in_sizes[0] / C;
    int E = in_sizes[1] / 2;
    const int* srcp = ei;
    const int* dstp = ei + E;

    float *pq, *aggp, *xcur, *Wc;
    __half *w2hi, *w2lo;
    cudaGetSymbolAddress((void**)&pq,   g_pq);
    cudaGetSymbolAddress((void**)&aggp, g_agg);
    cudaGetSymbolAddress((void**)&xcur, g_x);
    cudaGetSymbolAddress((void**)&Wc,   g_Wc);
    cudaGetSymbolAddress((void**)&w2hi, g_w2hi);
    cudaGetSymbolAddress((void**)&w2lo, g_w2lo);

    const size_t SMEM = (size_t)(TE * HST) * sizeof(__half)
                      + (size_t)(C * DST) * sizeof(float);
    cudaFuncSetAttribute(edge_mma_kernel, cudaFuncAttributeMaxDynamicSharedMemorySize, (int)SMEM);

    const float* Ws[3][4] = {
        {(const float*)d_in[2],  (const float*)d_in[3],  (const float*)d_in[4],  (const float*)d_in[5]},
        {(const float*)d_in[6],  (const float*)d_in[7],  (const float*)d_in[8],  (const float*)d_in[9]},
        {(const float*)d_in[10], (const float*)d_in[11], (const float*)d_in[12], (const float*)d_in[13]},
    };

    const float* xin = x;
    for (int l = 0; l < 3; l++) {
        const float* W1 = Ws[l][0];
        const float* b1 = Ws[l][1];
        const float* W2 = Ws[l][2];
        const float* b2 = Ws[l][3];
        float* xout = (l == 2) ? (float*)d_out : xcur;

        prep_kernel<<<C, 256>>>(W1, Wc);
        w2split_kernel<<<C, C>>>(W2, w2hi, w2lo);
        node_gemm_kernel<<<(N + 31) / 32, 256>>>(xin, Wc, b1, pq, N);
        cudaMemsetAsync(aggp, 0xFF, (size_t)N * C * sizeof(float));
        edge_mma_kernel<<<296, 256, SMEM>>>(pq, srcp, dstp, w2hi, w2lo, aggp, E);
        finalize_kernel<<<(N * C + 255) / 256, 256>>>(aggp, b2, xout, N, (l < 2) ? 1 : 0);

        xin = xcur;
    }
}

// round 5
// speedup vs baseline: 1.3636x; 1.3636x over previous
#include <cuda_runtime.h>
#include <cuda_fp16.h>
#include <math.h>

#define N_NODES 50000
#define N_EDGES 800000
#define C 128
#define TE 128           // edges per tile
#define HST 136          // h tile stride (halfs): conflict-free B-frag LDS
#define DST 132          // D^T tile stride (floats)

// ---------------- scratch (static device globals; no allocations) -------------
__device__ float g_pq[(size_t)N_NODES * 256];      // [N][256]: p (+b1) | q
__device__ float g_agg[(size_t)N_NODES * C];       // max-aggregation buffer
__device__ float g_x[(size_t)N_NODES * C];         // inter-layer node features
__device__ float g_Wc[C * 256];                    // node-gemm combined W1
__device__ __half g_w2hi[C * C];                   // W2^T hi plane [n][k] fp16
__device__ __half g_w2lo[C * C];                   // W2^T lo plane [n][k] fp16
__device__ __half g_h[(size_t)N_EDGES * C];        // dense per-edge hidden (fp16)

// ---------------- float atomic max (signed-max / unsigned-min trick) ----------
__device__ __forceinline__ void atomicMaxF(float* a, float v) {
    if (v >= 0.0f) atomicMax((int*)a, __float_as_int(v));
    else           atomicMin((unsigned int*)a, __float_as_uint(v));
}

// ---------------- HMMA m16n8k16 fp16 ------------------------------------------
__device__ __forceinline__ void mma16816(float& d0, float& d1, float& d2, float& d3,
                                         unsigned a0, unsigned a1, unsigned a2, unsigned a3,
                                         unsigned b0, unsigned b1)
{
    asm volatile(
        "mma.sync.aligned.m16n8k16.row.col.f32.f16.f16.f32 "
        "{%0,%1,%2,%3},{%4,%5,%6,%7},{%8,%9},{%0,%1,%2,%3};\n"
        : "+f"(d0), "+f"(d1), "+f"(d2), "+f"(d3)
        : "r"(a0), "r"(a1), "r"(a2), "r"(a3), "r"(b0), "r"(b1));
}

// ---------------- cp.async helpers ---------------------------------------------
__device__ __forceinline__ void cpasync16(unsigned saddr, const void* gptr) {
    asm volatile("cp.async.cg.shared.global [%0], [%1], 16;\n" :: "r"(saddr), "l"(gptr));
}
__device__ __forceinline__ void cpcommit() { asm volatile("cp.async.commit_group;\n"); }
__device__ __forceinline__ void cpwait1()  { asm volatile("cp.async.wait_group 1;\n"); }

// ---------------- prep: Wc from W1 --------------------------------------------
__global__ void prep_kernel(const float* __restrict__ W1, float* __restrict__ Wc) {
    int k = blockIdx.x;
    int j = threadIdx.x;
    if (j < C) Wc[k * 256 + j] = W1[k * C + j] - W1[(C + k) * C + j];
    else       Wc[k * 256 + j] = W1[(C + k) * C + (j - C)];
}

// ---------------- prep: split W2^T into fp16 hi/lo planes ----------------------
__global__ void w2split_kernel(const float* __restrict__ W2,
                               __half* __restrict__ hi, __half* __restrict__ lo) {
    int n = blockIdx.x;
    int k = threadIdx.x;
    float w = W2[k * C + n];
    __half h = __float2half_rn(w);
    hi[n * C + k] = h;
    lo[n * C + k] = __float2half_rn(w - __half2float(h));
}

// ---------------- node GEMM: pq = x @ Wc (+ b1 on p half) ---------------------
__global__ void __launch_bounds__(256) node_gemm_kernel(
    const float* __restrict__ x, const float* __restrict__ Wc,
    const float* __restrict__ b1, float* __restrict__ pq, int N)
{
    __shared__ float xs[32 * C];
    int m0 = blockIdx.x * 32;
    int tid = threadIdx.x;

    for (int i = tid; i < 32 * C / 4; i += 256) {
        int r = i / (C / 4);
        int cc = i % (C / 4);
        float4 v = make_float4(0.f, 0.f, 0.f, 0.f);
        if (m0 + r < N) v = ((const float4*)(x + (size_t)(m0 + r) * C))[cc];
        ((float4*)xs)[i] = v;
    }
    __syncthreads();

    int col = tid;
    float acc[32];
#pragma unroll
    for (int r = 0; r < 32; r++) acc[r] = 0.f;

#pragma unroll 4
    for (int k = 0; k < C; k++) {
        float w = Wc[k * 256 + col];
#pragma unroll
        for (int r = 0; r < 32; r++) acc[r] = fmaf(xs[r * C + k], w, acc[r]);
    }

    float bias = (col < C) ? b1[col] : 0.f;
#pragma unroll
    for (int r = 0; r < 32; r++)
        if (m0 + r < N) pq[(size_t)(m0 + r) * 256 + col] = acc[r] + bias;
}

// ---------------- gather: h[e] = fp16(relu(p[dst[e]] + q[src[e]])) -------------
__global__ void __launch_bounds__(256) gather_kernel(
    const float* __restrict__ pq, const int* __restrict__ src,
    const int* __restrict__ dst, __half* __restrict__ h, int E)
{
    int idx = blockIdx.x * blockDim.x + threadIdx.x;
    int e = idx >> 2;
    if (e >= E) return;
    int part = idx & 3;   // 32 channels
    int dn = __ldg(dst + e), sn = __ldg(src + e);
    const float4* p = (const float4*)(pq + (size_t)dn * 256 + part * 32);
    const float4* q = (const float4*)(pq + (size_t)sn * 256 + C + part * 32);

    unsigned buf[16];
#pragma unroll
    for (int i = 0; i < 8; i++) {
        float4 a = p[i], b = q[i];
        __half2 h0 = __floats2half2_rn(fmaxf(a.x + b.x, 0.f), fmaxf(a.y + b.y, 0.f));
        __half2 h1 = __floats2half2_rn(fmaxf(a.z + b.z, 0.f), fmaxf(a.w + b.w, 0.f));
        buf[i * 2 + 0] = *(unsigned*)&h0;
        buf[i * 2 + 1] = *(unsigned*)&h1;
    }
    uint4* out = (uint4*)(h + (size_t)e * C + part * 32);
#pragma unroll
    for (int i = 0; i < 4; i++)
        out[i] = make_uint4(buf[i * 4], buf[i * 4 + 1], buf[i * 4 + 2], buf[i * 4 + 3]);
}

// ---------------- dense edge GEMM (cp.async pipelined) + scatter max -----------
// 512 threads / 16 warps, 1 CTA/SM. Warp w: channels ((w&7)*16), edges ((w>>3)*64..+64).
__global__ void __launch_bounds__(512, 1) edge_mma_kernel(
    const __half* __restrict__ hgl, const int* __restrict__ dst,
    const __half* __restrict__ W2hi, const __half* __restrict__ W2lo,
    float* __restrict__ agg, int E)
{
    extern __shared__ char smraw[];
    float* DT = (float*)smraw;                       // [C][DST]
    __half* hbuf0 = (__half*)(DT + C * DST);         // [TE][HST]
    __half* hbuf1 = hbuf0 + TE * HST;                // [TE][HST]
    int* sidx0 = (int*)(hbuf1 + TE * HST);           // [TE]
    int* sidx1 = sidx0 + TE;

    int tid = threadIdx.x;
    int wid = tid >> 5, lane = tid & 31;
    int g = lane >> 2, tig = lane & 3;
    int m0 = (wid & 7) * 16;
    int ebase = (wid >> 3) * 64;

    __half* hb[2] = {hbuf0, hbuf1};
    int* sib[2] = {sidx0, sidx1};
    unsigned hb_s[2] = {(unsigned)__cvta_generic_to_shared(hbuf0),
                        (unsigned)__cvta_generic_to_shared(hbuf1)};
    unsigned si_s[2] = {(unsigned)__cvta_generic_to_shared(sidx0),
                        (unsigned)__cvta_generic_to_shared(sidx1)};

    // Preload A fragments (W2^T hi/lo, all 8 k-steps) into registers.
    unsigned ah[8][4], al[8][4];
    {
        const unsigned* Hp = (const unsigned*)W2hi;
        const unsigned* Lp = (const unsigned*)W2lo;
#pragma unroll
        for (int ks = 0; ks < 8; ks++) {
            int k0 = ks * 16;
            int i00 = (m0 + g) * (C / 2) + (k0 + tig * 2) / 2;
            ah[ks][0] = Hp[i00];
            ah[ks][1] = Hp[i00 + 8 * (C / 2)];
            ah[ks][2] = Hp[i00 + 4];
            ah[ks][3] = Hp[i00 + 8 * (C / 2) + 4];
            al[ks][0] = Lp[i00];
            al[ks][1] = Lp[i00 + 8 * (C / 2)];
            al[ks][2] = Lp[i00 + 4];
            al[ks][3] = Lp[i00 + 8 * (C / 2) + 4];
        }
    }

    int ntiles = (E + TE - 1) / TE;

    // tile loader: h rows (4x16B per thread) + dst indices, one commit group
    auto load_tile = [&](int tile, int b) {
        int e0 = tile * TE;
        int e = tid >> 2;
        int ego = e0 + e;
        if (ego > E - 1) ego = E - 1;
        const __half* gsrc = hgl + (size_t)ego * C + (tid & 3) * 32;
        unsigned sdst = hb_s[b] + (unsigned)((e * HST + (tid & 3) * 32) * 2);
#pragma unroll
        for (int j = 0; j < 4; j++)
            cpasync16(sdst + j * 16, gsrc + j * 8);
        if (tid < TE / 4) {
            int o = tid * 4;
            if (e0 + o + 3 < E) {
                cpasync16(si_s[b] + o * 4, dst + e0 + o);
            } else {
                for (int j = 0; j < 4; j++)
                    sib[b][o + j] = (e0 + o + j < E) ? dst[e0 + o + j] : 0;
            }
        }
        cpcommit();
    };

    // prologue
    if (blockIdx.x < ntiles) load_tile(blockIdx.x, 0);

    int i = 0;
    for (int tile = blockIdx.x; tile < ntiles; tile += gridDim.x, i++) {
        int cur = i & 1;
        int nt = tile + gridDim.x;
        if (nt < ntiles) load_tile(nt, cur ^ 1);
        else cpcommit();                 // keep group count in step
        cpwait1();                       // tile 'cur' data resident
        __syncthreads();

        int e0 = tile * TE;
        int dn = sib[cur][tid & 127];    // register-cache dst for epilogue

        const __half* h_s = hb[cur];
#pragma unroll 1
        for (int et = 0; et < 8; et++) {
            int e0t = ebase + et * 8;
            float d0 = 0.f, d1 = 0.f, d2 = 0.f, d3 = 0.f;
#pragma unroll
            for (int ks = 0; ks < 8; ks++) {
                int k0 = ks * 16;
                const unsigned* bp = (const unsigned*)(h_s + (e0t + g) * HST + k0 + tig * 2);
                unsigned b0 = bp[0], b1 = bp[4];
                mma16816(d0, d1, d2, d3, ah[ks][0], ah[ks][1], ah[ks][2], ah[ks][3], b0, b1);
                mma16816(d0, d1, d2, d3, al[ks][0], al[ks][1], al[ks][2], al[ks][3], b0, b1);
            }
            *(float2*)&DT[(m0 + g) * DST + e0t + tig * 2]     = make_float2(d0, d1);
            *(float2*)&DT[(m0 + g + 8) * DST + e0t + tig * 2] = make_float2(d2, d3);
        }
        __syncthreads();

        // epilogue: e = tid&127, 32 channels per thread; filtered atomic max
        {
            int e = tid & 127;
            int ch = (tid >> 7) * 32;
            if (e0 + e < E) {
                float* arow = agg + (size_t)dn * C + ch;
#pragma unroll
                for (int ii = 0; ii < 8; ii++) {
                    float4 cur4 = ((const float4*)arow)[ii];
                    float v0 = DT[(ch + ii * 4 + 0) * DST + e];
                    float v1 = DT[(ch + ii * 4 + 1) * DST + e];
                    float v2 = DT[(ch + ii * 4 + 2) * DST + e];
                    float v3 = DT[(ch + ii * 4 + 3) * DST + e];
                    if (!(v0 <= cur4.x)) atomicMaxF(arow + ii * 4 + 0, v0);
                    if (!(v1 <= cur4.y)) atomicMaxF(arow + ii * 4 + 1, v1);
                    if (!(v2 <= cur4.z)) atomicMaxF(arow + ii * 4 + 2, v2);
                    if (!(v3 <= cur4.w)) atomicMaxF(arow + ii * 4 + 3, v3);
                }
            }
        }
    }
}

// ---------------- finalize: handle empty nodes, +b2, optional relu ------------
__global__ void finalize_kernel(const float* __restrict__ agg,
                                const float* __restrict__ b2,
                                float* __restrict__ out, int N, int do_relu)
{
    int idx = blockIdx.x * blockDim.x + threadIdx.x;
    if (idx >= N * C) return;
    int c = idx & (C - 1);
    float v = agg[idx];
    float o = isfinite(v) ? (v + b2[c]) : 0.f;
    if (do_relu) o = fmaxf(o, 0.f);
    out[idx] = o;
}

// ---------------- launch -------------------------------------------------------
extern "C" void kernel_launch(void* const* d_in, const int* in_sizes, int n_in,
                              void* d_out, int out_size)
{
    const float* x  = (const float*)d_in[0];
    const int*   ei = (const int*)d_in[1];
    int N = in_sizes[0] / C;
    int E = in_sizes[1] / 2;
    const int* srcp = ei;
    const int* dstp = ei + E;

    float *pq, *aggp, *xcur, *Wc;
    __half *w2hi, *w2lo, *hbuf;
    cudaGetSymbolAddress((void**)&pq,   g_pq);
    cudaGetSymbolAddress((void**)&aggp, g_agg);
    cudaGetSymbolAddress((void**)&xcur, g_x);
    cudaGetSymbolAddress((void**)&Wc,   g_Wc);
    cudaGetSymbolAddress((void**)&w2hi, g_w2hi);
    cudaGetSymbolAddress((void**)&w2lo, g_w2lo);
    cudaGetSymbolAddress((void**)&hbuf, g_h);

    const size_t SMEM = (size_t)(C * DST) * sizeof(float)
                      + (size_t)(2 * TE * HST) * sizeof(__half)
                      + 2 * TE * sizeof(int);
    cudaFuncSetAttribute(edge_mma_kernel, cudaFuncAttributeMaxDynamicSharedMemorySize, (int)SMEM);

    const float* Ws[3][4] = {
        {(const float*)d_in[2],  (const float*)d_in[3],  (const float*)d_in[4],  (const float*)d_in[5]},
        {(const float*)d_in[6],  (const float*)d_in[7],  (const float*)d_in[8],  (const float*)d_in[9]},
        {(const float*)d_in[10], (const float*)d_in[11], (const float*)d_in[12], (const float*)d_in[13]},
    };

    const float* xin = x;
    for (int l = 0; l < 3; l++) {
        const float* W1 = Ws[l][0];
        const float* b1 = Ws[l][1];
        const float* W2 = Ws[l][2];
        const float* b2 = Ws[l][3];
        float* xout = (l == 2) ? (float*)d_out : xcur;

        prep_kernel<<<C, 256>>>(W1, Wc);
        w2split_kernel<<<C, C>>>(W2, w2hi, w2lo);
        node_gemm_kernel<<<(N + 31) / 32, 256>>>(xin, Wc, b1, pq, N);
        gather_kernel<<<(E * 4 + 255) / 256, 256>>>(pq, srcp, dstp, hbuf, E);
        cudaMemsetAsync(aggp, 0xFF, (size_t)N * C * sizeof(float));
        edge_mma_kernel<<<148, 512, SMEM>>>(hbuf, dstp, w2hi, w2lo, aggp, E);
        finalize_kernel<<<(N * C + 255) / 256, 256>>>(aggp, b2, xout, N, (l < 2) ? 1 : 0);

        xin = xcur;
    }
}

// round 6
// speedup vs baseline: 1.8164x; 1.3320x over previous
#include <cuda_runtime.h>
#include <cuda_fp16.h>
#include <math.h>

#define N_NODES 50000
#define N_EDGES 800000
#define C 128
#define TE 128           // edges per tile
#define HST 136          // h tile stride (halfs): conflict-free B-frag LDS
#define DST 132          // D^T tile stride (floats)

// ---------------- scratch (static device globals; no allocations) -------------
__device__ float g_pq[(size_t)N_NODES * 256];      // [N][256]: p (+b1) | q
__device__ float g_x[(size_t)N_NODES * C];         // inter-layer node features
__device__ float g_Wc[C * 256];                    // node-gemm combined W1
__device__ __half g_w2hi[C * C];                   // W2^T hi plane [n][k] fp16
__device__ __half g_w2lo[C * C];                   // W2^T lo plane [n][k] fp16
__device__ __half g_h[(size_t)N_EDGES * C];        // dense per-edge hidden (fp16)
__device__ float  g_u[(size_t)N_EDGES * C];        // dense per-edge output (fp32)
__device__ int g_off[N_NODES + 1];                 // CSR row pointers (by dst)
__device__ int g_cur[N_NODES];                     // scatter cursors
__device__ int g_bsum[64];                         // scan block sums
__device__ int g_srcs[N_EDGES];                    // src sorted by dst
__device__ int g_dsts[N_EDGES];                    // dst sorted (ascending)

// ---------------- HMMA m16n8k16 fp16 ------------------------------------------
__device__ __forceinline__ void mma16816(float& d0, float& d1, float& d2, float& d3,
                                         unsigned a0, unsigned a1, unsigned a2, unsigned a3,
                                         unsigned b0, unsigned b1)
{
    asm volatile(
        "mma.sync.aligned.m16n8k16.row.col.f32.f16.f16.f32 "
        "{%0,%1,%2,%3},{%4,%5,%6,%7},{%8,%9},{%0,%1,%2,%3};\n"
        : "+f"(d0), "+f"(d1), "+f"(d2), "+f"(d3)
        : "r"(a0), "r"(a1), "r"(a2), "r"(a3), "r"(b0), "r"(b1));
}

// ---------------- cp.async helpers ---------------------------------------------
__device__ __forceinline__ void cpasync16(unsigned saddr, const void* gptr) {
    asm volatile("cp.async.cg.shared.global [%0], [%1], 16;\n" :: "r"(saddr), "l"(gptr));
}
__device__ __forceinline__ void cpcommit() { asm volatile("cp.async.commit_group;\n"); }
__device__ __forceinline__ void cpwait1()  { asm volatile("cp.async.wait_group 1;\n"); }

// ---------------- sort-by-dst preprocessing ------------------------------------
__global__ void hist_kernel(const int* __restrict__ dst, int* __restrict__ off, int E) {
    int e = blockIdx.x * blockDim.x + threadIdx.x;
    if (e < E) atomicAdd(&off[dst[e] + 1], 1);
}

__global__ void scan1_kernel(int* __restrict__ a, int* __restrict__ bsum, int n) {
    __shared__ int s[1024];
    int i = blockIdx.x * 1024 + threadIdx.x;
    int v = (i < n) ? a[i] : 0;
    s[threadIdx.x] = v;
    __syncthreads();
    for (int d = 1; d < 1024; d <<= 1) {
        int t = (threadIdx.x >= d) ? s[threadIdx.x - d] : 0;
        __syncthreads();
        s[threadIdx.x] += t;
        __syncthreads();
    }
    if (i < n) a[i] = s[threadIdx.x];
    if (threadIdx.x == 1023) bsum[blockIdx.x] = s[1023];
}

__global__ void scan2_kernel(int* __restrict__ bsum, int nb) {
    int acc = 0;
    for (int i = 0; i < nb; i++) { int t = bsum[i]; bsum[i] = acc; acc += t; }
}

__global__ void scan3_kernel(int* __restrict__ a, const int* __restrict__ bsum,
                             int* __restrict__ cur, int n, int N) {
    int i = blockIdx.x * 1024 + threadIdx.x;
    if (i < n) {
        int v = a[i] + bsum[blockIdx.x];
        a[i] = v;
        if (i < N) cur[i] = v;
    }
}

__global__ void scatter_kernel(const int* __restrict__ src, const int* __restrict__ dst,
                               int* __restrict__ cur, int* __restrict__ ssrc,
                               int* __restrict__ sdst, int E) {
    int e = blockIdx.x * blockDim.x + threadIdx.x;
    if (e < E) {
        int d = dst[e];
        int pos = atomicAdd(&cur[d], 1);
        sdst[pos] = d;
        ssrc[pos] = src[e];
    }
}

// ---------------- prep: Wc from W1 --------------------------------------------
__global__ void prep_kernel(const float* __restrict__ W1, float* __restrict__ Wc) {
    int k = blockIdx.x;
    int j = threadIdx.x;
    if (j < C) Wc[k * 256 + j] = W1[k * C + j] - W1[(C + k) * C + j];
    else       Wc[k * 256 + j] = W1[(C + k) * C + (j - C)];
}

// ---------------- prep: split W2^T into fp16 hi/lo planes ----------------------
__global__ void w2split_kernel(const float* __restrict__ W2,
                               __half* __restrict__ hi, __half* __restrict__ lo) {
    int n = blockIdx.x;
    int k = threadIdx.x;
    float w = W2[k * C + n];
    __half h = __float2half_rn(w);
    hi[n * C + k] = h;
    lo[n * C + k] = __float2half_rn(w - __half2float(h));
}

// ---------------- node GEMM: pq = x @ Wc (+ b1 on p half) ---------------------
__global__ void __launch_bounds__(256) node_gemm_kernel(
    const float* __restrict__ x, const float* __restrict__ Wc,
    const float* __restrict__ b1, float* __restrict__ pq, int N)
{
    __shared__ float xs[32 * C];
    int m0 = blockIdx.x * 32;
    int tid = threadIdx.x;

    for (int i = tid; i < 32 * C / 4; i += 256) {
        int r = i / (C / 4);
        int cc = i % (C / 4);
        float4 v = make_float4(0.f, 0.f, 0.f, 0.f);
        if (m0 + r < N) v = ((const float4*)(x + (size_t)(m0 + r) * C))[cc];
        ((float4*)xs)[i] = v;
    }
    __syncthreads();

    int col = tid;
    float acc[32];
#pragma unroll
    for (int r = 0; r < 32; r++) acc[r] = 0.f;

#pragma unroll 4
    for (int k = 0; k < C; k++) {
        float w = Wc[k * 256 + col];
#pragma unroll
        for (int r = 0; r < 32; r++) acc[r] = fmaf(xs[r * C + k], w, acc[r]);
    }

    float bias = (col < C) ? b1[col] : 0.f;
#pragma unroll
    for (int r = 0; r < 32; r++)
        if (m0 + r < N) pq[(size_t)(m0 + r) * 256 + col] = acc[r] + bias;
}

// ---------------- gather: h[e] = fp16(relu(p[dst[e]] + q[src[e]])) -------------
__global__ void __launch_bounds__(256) gather_kernel(
    const float* __restrict__ pq, const int* __restrict__ src,
    const int* __restrict__ dst, __half* __restrict__ h, int E)
{
    int idx = blockIdx.x * blockDim.x + threadIdx.x;
    int e = idx >> 2;
    if (e >= E) return;
    int part = idx & 3;   // 32 channels
    int dn = __ldg(dst + e), sn = __ldg(src + e);
    const float4* p = (const float4*)(pq + (size_t)dn * 256 + part * 32);
    const float4* q = (const float4*)(pq + (size_t)sn * 256 + C + part * 32);

    unsigned buf[16];
#pragma unroll
    for (int i = 0; i < 8; i++) {
        float4 a = p[i], b = q[i];
        __half2 h0 = __floats2half2_rn(fmaxf(a.x + b.x, 0.f), fmaxf(a.y + b.y, 0.f));
        __half2 h1 = __floats2half2_rn(fmaxf(a.z + b.z, 0.f), fmaxf(a.w + b.w, 0.f));
        buf[i * 2 + 0] = *(unsigned*)&h0;
        buf[i * 2 + 1] = *(unsigned*)&h1;
    }
    uint4* out = (uint4*)(h + (size_t)e * C + part * 32);
#pragma unroll
    for (int i = 0; i < 4; i++)
        out[i] = make_uint4(buf[i * 4], buf[i * 4 + 1], buf[i * 4 + 2], buf[i * 4 + 3]);
}

// ---------------- dense edge GEMM (cp.async pipelined): u = h @ W2 -------------
// 512 threads / 16 warps, 1 CTA/SM. Warp w: channels ((w&7)*16), edges ((w>>3)*64..+64).
__global__ void __launch_bounds__(512, 1) edge_gemm_kernel(
    const __half* __restrict__ hgl,
    const __half* __restrict__ W2hi, const __half* __restrict__ W2lo,
    float* __restrict__ u, int E)
{
    extern __shared__ char smraw[];
    float* DT = (float*)smraw;                       // [C][DST]
    __half* hbuf0 = (__half*)(DT + C * DST);         // [TE][HST]
    __half* hbuf1 = hbuf0 + TE * HST;                // [TE][HST]

    int tid = threadIdx.x;
    int wid = tid >> 5, lane = tid & 31;
    int g = lane >> 2, tig = lane & 3;
    int m0 = (wid & 7) * 16;
    int ebase = (wid >> 3) * 64;

    const __half* hb[2] = {hbuf0, hbuf1};
    unsigned hb_s[2] = {(unsigned)__cvta_generic_to_shared(hbuf0),
                        (unsigned)__cvta_generic_to_shared(hbuf1)};

    // Preload A fragments (W2^T hi/lo, all 8 k-steps) into registers.
    unsigned ah[8][4], al[8][4];
    {
        const unsigned* Hp = (const unsigned*)W2hi;
        const unsigned* Lp = (const unsigned*)W2lo;
#pragma unroll
        for (int ks = 0; ks < 8; ks++) {
            int k0 = ks * 16;
            int i00 = (m0 + g) * (C / 2) + (k0 + tig * 2) / 2;
            ah[ks][0] = Hp[i00];
            ah[ks][1] = Hp[i00 + 8 * (C / 2)];
            ah[ks][2] = Hp[i00 + 4];
            ah[ks][3] = Hp[i00 + 8 * (C / 2) + 4];
            al[ks][0] = Lp[i00];
            al[ks][1] = Lp[i00 + 8 * (C / 2)];
            al[ks][2] = Lp[i00 + 4];
            al[ks][3] = Lp[i00 + 8 * (C / 2) + 4];
        }
    }

    int ntiles = (E + TE - 1) / TE;

    auto load_tile = [&](int tile, int b) {
        int e0 = tile * TE;
        int e = tid >> 2;
        int ego = e0 + e;
        if (ego > E - 1) ego = E - 1;
        const __half* gsrc = hgl + (size_t)ego * C + (tid & 3) * 32;
        unsigned sdst = hb_s[b] + (unsigned)((e * HST + (tid & 3) * 32) * 2);
#pragma unroll
        for (int j = 0; j < 4; j++)
            cpasync16(sdst + j * 16, gsrc + j * 8);
        cpcommit();
    };

    if (blockIdx.x < ntiles) load_tile(blockIdx.x, 0);

    int i = 0;
    for (int tile = blockIdx.x; tile < ntiles; tile += gridDim.x, i++) {
        int cur = i & 1;
        int nt = tile + gridDim.x;
        if (nt < ntiles) load_tile(nt, cur ^ 1);
        else cpcommit();
        cpwait1();
        __syncthreads();

        int e0 = tile * TE;
        const __half* h_s = hb[cur];
#pragma unroll 1
        for (int et = 0; et < 8; et++) {
            int e0t = ebase + et * 8;
            float d0 = 0.f, d1 = 0.f, d2 = 0.f, d3 = 0.f;
#pragma unroll
            for (int ks = 0; ks < 8; ks++) {
                int k0 = ks * 16;
                const unsigned* bp = (const unsigned*)(h_s + (e0t + g) * HST + k0 + tig * 2);
                unsigned b0 = bp[0], b1 = bp[4];
                mma16816(d0, d1, d2, d3, ah[ks][0], ah[ks][1], ah[ks][2], ah[ks][3], b0, b1);
                mma16816(d0, d1, d2, d3, al[ks][0], al[ks][1], al[ks][2], al[ks][3], b0, b1);
            }
            *(float2*)&DT[(m0 + g) * DST + e0t + tig * 2]     = make_float2(d0, d1);
            *(float2*)&DT[(m0 + g + 8) * DST + e0t + tig * 2] = make_float2(d2, d3);
        }
        __syncthreads();

        // coalesced store DT -> u
        {
            int e = tid >> 2;
            int p4 = tid & 3;
            if (e0 + e < E) {
                float* urow = u + (size_t)(e0 + e) * C;
#pragma unroll
                for (int ii = 0; ii < 8; ii++) {
                    int ch = p4 * 4 + ii * 16;
                    float4 v = make_float4(DT[(ch + 0) * DST + e],
                                           DT[(ch + 1) * DST + e],
                                           DT[(ch + 2) * DST + e],
                                           DT[(ch + 3) * DST + e]);
                    *(float4*)(urow + ch) = v;
                }
            }
        }
    }
}

// ---------------- segmented max: out[n] = max over run + b2 (or 0 if empty) ----
__global__ void __launch_bounds__(256) segmax_kernel(
    const float* __restrict__ u, const int* __restrict__ off,
    const float* __restrict__ b2, float* __restrict__ out, int N, int do_relu)
{
    int warp = (blockIdx.x * blockDim.x + threadIdx.x) >> 5;
    int lane = threadIdx.x & 31;
    if (warp >= N) return;
    int s = off[warp], t = off[warp + 1];

    float4 acc = make_float4(-INFINITY, -INFINITY, -INFINITY, -INFINITY);
    int j = s;
    for (; j + 1 < t; j += 2) {
        float4 a = *(const float4*)(u + (size_t)j * C + lane * 4);
        float4 b = *(const float4*)(u + (size_t)(j + 1) * C + lane * 4);
        acc.x = fmaxf(acc.x, fmaxf(a.x, b.x));
        acc.y = fmaxf(acc.y, fmaxf(a.y, b.y));
        acc.z = fmaxf(acc.z, fmaxf(a.z, b.z));
        acc.w = fmaxf(acc.w, fmaxf(a.w, b.w));
    }
    if (j < t) {
        float4 a = *(const float4*)(u + (size_t)j * C + lane * 4);
        acc.x = fmaxf(acc.x, a.x);
        acc.y = fmaxf(acc.y, a.y);
        acc.z = fmaxf(acc.z, a.z);
        acc.w = fmaxf(acc.w, a.w);
    }

    float4 o;
    if (t > s) {
        float4 bb = ((const float4*)b2)[lane];
        o = make_float4(acc.x + bb.x, acc.y + bb.y, acc.z + bb.z, acc.w + bb.w);
        if (do_relu) {
            o.x = fmaxf(o.x, 0.f); o.y = fmaxf(o.y, 0.f);
            o.z = fmaxf(o.z, 0.f); o.w = fmaxf(o.w, 0.f);
        }
    } else {
        o = make_float4(0.f, 0.f, 0.f, 0.f);
    }
    *(float4*)(out + (size_t)warp * C + lane * 4) = o;
}

// ---------------- launch -------------------------------------------------------
extern "C" void kernel_launch(void* const* d_in, const int* in_sizes, int n_in,
                              void* d_out, int out_size)
{
    const float* x  = (const float*)d_in[0];
    const int*   ei = (const int*)d_in[1];
    int N = in_sizes[0] / C;
    int E = in_sizes[1] / 2;
    const int* srcp = ei;
    const int* dstp = ei + E;

    float *pq, *xcur, *Wc, *ubuf;
    __half *w2hi, *w2lo, *hbuf;
    int *off, *curp, *bsum, *srcs, *dsts;
    cudaGetSymbolAddress((void**)&pq,   g_pq);
    cudaGetSymbolAddress((void**)&xcur, g_x);
    cudaGetSymbolAddress((void**)&Wc,   g_Wc);
    cudaGetSymbolAddress((void**)&w2hi, g_w2hi);
    cudaGetSymbolAddress((void**)&w2lo, g_w2lo);
    cudaGetSymbolAddress((void**)&hbuf, g_h);
    cudaGetSymbolAddress((void**)&ubuf, g_u);
    cudaGetSymbolAddress((void**)&off,  g_off);
    cudaGetSymbolAddress((void**)&curp, g_cur);
    cudaGetSymbolAddress((void**)&bsum, g_bsum);
    cudaGetSymbolAddress((void**)&srcs, g_srcs);
    cudaGetSymbolAddress((void**)&dsts, g_dsts);

    // ---- sort edges by dst (once; reused by all 3 layers) ----
    int nscan = N + 1;
    int nb = (nscan + 1023) / 1024;
    cudaMemsetAsync(off, 0, (size_t)(N + 1) * sizeof(int));
    hist_kernel<<<(E + 255) / 256, 256>>>(dstp, off, E);
    scan1_kernel<<<nb, 1024>>>(off, bsum, nscan);
    scan2_kernel<<<1, 1>>>(bsum, nb);
    scan3_kernel<<<nb, 1024>>>(off, bsum, curp, nscan, N);
    scatter_kernel<<<(E + 255) / 256, 256>>>(srcp, dstp, curp, srcs, dsts, E);

    const size_t SMEM = (size_t)(C * DST) * sizeof(float)
                      + (size_t)(2 * TE * HST) * sizeof(__half);
    cudaFuncSetAttribute(edge_gemm_kernel, cudaFuncAttributeMaxDynamicSharedMemorySize, (int)SMEM);

    const float* Ws[3][4] = {
        {(const float*)d_in[2],  (const float*)d_in[3],  (const float*)d_in[4],  (const float*)d_in[5]},
        {(const float*)d_in[6],  (const float*)d_in[7],  (const float*)d_in[8],  (const float*)d_in[9]},
        {(const float*)d_in[10], (const float*)d_in[11], (const float*)d_in[12], (const float*)d_in[13]},
    };

    const float* xin = x;
    for (int l = 0; l < 3; l++) {
        const float* W1 = Ws[l][0];
        const float* b1 = Ws[l][1];
        const float* W2 = Ws[l][2];
        const float* b2 = Ws[l][3];
        float* xout = (l == 2) ? (float*)d_out : xcur;

        prep_kernel<<<C, 256>>>(W1, Wc);
        w2split_kernel<<<C, C>>>(W2, w2hi, w2lo);
        node_gemm_kernel<<<(N + 31) / 32, 256>>>(xin, Wc, b1, pq, N);
        gather_kernel<<<(E * 4 + 255) / 256, 256>>>(pq, srcs, dsts, hbuf, E);
        edge_gemm_kernel<<<148, 512, SMEM>>>(hbuf, w2hi, w2lo, ubuf, E);
        segmax_kernel<<<(N * 32 + 255) / 256, 256>>>(ubuf, off, b2, xout, N, (l < 2) ? 1 : 0);

        xin = xcur;
    }
}

// round 7
// speedup vs baseline: 2.0527x; 1.1301x over previous
#include <cuda_runtime.h>
#include <cuda_fp16.h>
#include <math.h>

#define N_NODES 50000
#define N_EDGES 800000
#define C 128
#define TE 128           // edges per tile
#define HST 136          // h tile stride (halfs): conflict-free B-frag LDS
#define DSTE 132         // D tile stride (floats), edge-major [e][ch]

// ---------------- scratch (static device globals; no allocations) -------------
__device__ float g_pq[(size_t)N_NODES * 256];      // [N][256]: p (+b1) | q
__device__ float g_agg[(size_t)N_NODES * C];       // max-aggregation buffer
__device__ float g_x[(size_t)N_NODES * C];         // inter-layer node features
__device__ float g_Wc[C * 256];                    // node-gemm combined W1
__device__ __half g_w2hi[C * C];                   // W2^T hi plane [n][k] fp16
__device__ __half g_w2lo[C * C];                   // W2^T lo plane [n][k] fp16
__device__ __half g_h[(size_t)N_EDGES * C];        // dense per-edge hidden (fp16)
__device__ int g_off[N_NODES + 1];                 // CSR row pointers (by dst)
__device__ int g_cur[N_NODES];                     // scatter cursors
__device__ int g_bsum[64];                         // scan block sums
__device__ int g_srcs[N_EDGES];                    // src sorted by dst
__device__ int g_dsts[N_EDGES];                    // dst sorted (ascending)

// ---------------- float atomic max (signed-max / unsigned-min trick) ----------
__device__ __forceinline__ void atomicMaxF(float* a, float v) {
    if (v >= 0.0f) atomicMax((int*)a, __float_as_int(v));
    else           atomicMin((unsigned int*)a, __float_as_uint(v));
}

// ---------------- HMMA m16n8k16 fp16 ------------------------------------------
__device__ __forceinline__ void mma16816(float& d0, float& d1, float& d2, float& d3,
                                         unsigned a0, unsigned a1, unsigned a2, unsigned a3,
                                         unsigned b0, unsigned b1)
{
    asm volatile(
        "mma.sync.aligned.m16n8k16.row.col.f32.f16.f16.f32 "
        "{%0,%1,%2,%3},{%4,%5,%6,%7},{%8,%9},{%0,%1,%2,%3};\n"
        : "+f"(d0), "+f"(d1), "+f"(d2), "+f"(d3)
        : "r"(a0), "r"(a1), "r"(a2), "r"(a3), "r"(b0), "r"(b1));
}

// ---------------- cp.async helpers ---------------------------------------------
__device__ __forceinline__ void cpasync16(unsigned saddr, const void* gptr) {
    asm volatile("cp.async.cg.shared.global [%0], [%1], 16;\n" :: "r"(saddr), "l"(gptr));
}
__device__ __forceinline__ void cpcommit() { asm volatile("cp.async.commit_group;\n"); }
__device__ __forceinline__ void cpwait1()  { asm volatile("cp.async.wait_group 1;\n"); }

// ---------------- sort-by-dst preprocessing ------------------------------------
__global__ void hist_kernel(const int* __restrict__ dst, int* __restrict__ off, int E) {
    int e = blockIdx.x * blockDim.x + threadIdx.x;
    if (e < E) atomicAdd(&off[dst[e] + 1], 1);
}

__global__ void scan1_kernel(int* __restrict__ a, int* __restrict__ bsum, int n) {
    __shared__ int s[1024];
    int i = blockIdx.x * 1024 + threadIdx.x;
    int v = (i < n) ? a[i] : 0;
    s[threadIdx.x] = v;
    __syncthreads();
    for (int d = 1; d < 1024; d <<= 1) {
        int t = (threadIdx.x >= d) ? s[threadIdx.x - d] : 0;
        __syncthreads();
        s[threadIdx.x] += t;
        __syncthreads();
    }
    if (i < n) a[i] = s[threadIdx.x];
    if (threadIdx.x == 1023) bsum[blockIdx.x] = s[1023];
}

__global__ void scan2_kernel(int* __restrict__ bsum, int nb) {
    int acc = 0;
    for (int i = 0; i < nb; i++) { int t = bsum[i]; bsum[i] = acc; acc += t; }
}

__global__ void scan3_kernel(int* __restrict__ a, const int* __restrict__ bsum,
                             int* __restrict__ cur, int n, int N) {
    int i = blockIdx.x * 1024 + threadIdx.x;
    if (i < n) {
        int v = a[i] + bsum[blockIdx.x];
        a[i] = v;
        if (i < N) cur[i] = v;
    }
}

__global__ void scatter_kernel(const int* __restrict__ src, const int* __restrict__ dst,
                               int* __restrict__ cur, int* __restrict__ ssrc,
                               int* __restrict__ sdst, int E) {
    int e = blockIdx.x * blockDim.x + threadIdx.x;
    if (e < E) {
        int d = dst[e];
        int pos = atomicAdd(&cur[d], 1);
        sdst[pos] = d;
        ssrc[pos] = src[e];
    }
}

// ---------------- prep: Wc from W1 --------------------------------------------
__global__ void prep_kernel(const float* __restrict__ W1, float* __restrict__ Wc) {
    int k = blockIdx.x;
    int j = threadIdx.x;
    if (j < C) Wc[k * 256 + j] = W1[k * C + j] - W1[(C + k) * C + j];
    else       Wc[k * 256 + j] = W1[(C + k) * C + (j - C)];
}

// ---------------- prep: split W2^T into fp16 hi/lo planes ----------------------
__global__ void w2split_kernel(const float* __restrict__ W2,
                               __half* __restrict__ hi, __half* __restrict__ lo) {
    int n = blockIdx.x;
    int k = threadIdx.x;
    float w = W2[k * C + n];
    __half h = __float2half_rn(w);
    hi[n * C + k] = h;
    lo[n * C + k] = __float2half_rn(w - __half2float(h));
}

// ---------------- node GEMM: pq = x @ Wc (+ b1 on p half) ---------------------
__global__ void __launch_bounds__(256) node_gemm_kernel(
    const float* __restrict__ x, const float* __restrict__ Wc,
    const float* __restrict__ b1, float* __restrict__ pq, int N)
{
    __shared__ float xs[32 * C];
    int m0 = blockIdx.x * 32;
    int tid = threadIdx.x;

    for (int i = tid; i < 32 * C / 4; i += 256) {
        int r = i / (C / 4);
        int cc = i % (C / 4);
        float4 v = make_float4(0.f, 0.f, 0.f, 0.f);
        if (m0 + r < N) v = ((const float4*)(x + (size_t)(m0 + r) * C))[cc];
        ((float4*)xs)[i] = v;
    }
    __syncthreads();

    int col = tid;
    float acc[32];
#pragma unroll
    for (int r = 0; r < 32; r++) acc[r] = 0.f;

#pragma unroll 4
    for (int k = 0; k < C; k++) {
        float w = Wc[k * 256 + col];
#pragma unroll
        for (int r = 0; r < 32; r++) acc[r] = fmaf(xs[r * C + k], w, acc[r]);
    }

    float bias = (col < C) ? b1[col] : 0.f;
#pragma unroll
    for (int r = 0; r < 32; r++)
        if (m0 + r < N) pq[(size_t)(m0 + r) * 256 + col] = acc[r] + bias;
}

// ---------------- gather: h[e] = fp16(relu(p[dst[e]] + q[src[e]])) -------------
__global__ void __launch_bounds__(256) gather_kernel(
    const float* __restrict__ pq, const int* __restrict__ src,
    const int* __restrict__ dst, __half* __restrict__ h, int E)
{
    int idx = blockIdx.x * blockDim.x + threadIdx.x;
    int e = idx >> 2;
    if (e >= E) return;
    int part = idx & 3;   // 32 channels
    int dn = __ldg(dst + e), sn = __ldg(src + e);
    const float4* p = (const float4*)(pq + (size_t)dn * 256 + part * 32);
    const float4* q = (const float4*)(pq + (size_t)sn * 256 + C + part * 32);

    unsigned buf[16];
#pragma unroll
    for (int i = 0; i < 8; i++) {
        float4 a = p[i], b = q[i];
        __half2 h0 = __floats2half2_rn(fmaxf(a.x + b.x, 0.f), fmaxf(a.y + b.y, 0.f));
        __half2 h1 = __floats2half2_rn(fmaxf(a.z + b.z, 0.f), fmaxf(a.w + b.w, 0.f));
        buf[i * 2 + 0] = *(unsigned*)&h0;
        buf[i * 2 + 1] = *(unsigned*)&h1;
    }
    uint4* out = (uint4*)(h + (size_t)e * C + part * 32);
#pragma unroll
    for (int i = 0; i < 4; i++)
        out[i] = make_uint4(buf[i * 4], buf[i * 4 + 1], buf[i * 4 + 2], buf[i * 4 + 3]);
}

// ---------------- dense edge GEMM + fused segmented-max epilogue ---------------
// 512 threads / 16 warps, 1 CTA/SM. Warp w: channels ((w&7)*16), edges ((w>>3)*64..+64).
// Epilogue: edges sorted by dst -> per-thread running max over 32-edge quarter,
// one atomicMaxF per (segment, channel).
__global__ void __launch_bounds__(512, 1) edge_gemm_kernel(
    const __half* __restrict__ hgl, const int* __restrict__ dsts,
    const __half* __restrict__ W2hi, const __half* __restrict__ W2lo,
    float* __restrict__ agg, int E)
{
    extern __shared__ char smraw[];
    float* DT = (float*)smraw;                       // [TE][DSTE] edge-major
    __half* hbuf0 = (__half*)(DT + TE * DSTE);       // [TE][HST]
    __half* hbuf1 = hbuf0 + TE * HST;                // [TE][HST]
    int* sidx0 = (int*)(hbuf1 + TE * HST);           // [TE]
    int* sidx1 = sidx0 + TE;

    int tid = threadIdx.x;
    int wid = tid >> 5, lane = tid & 31;
    int g = lane >> 2, tig = lane & 3;
    int m0 = (wid & 7) * 16;
    int ebase = (wid >> 3) * 64;

    const __half* hb[2] = {hbuf0, hbuf1};
    int* sib[2] = {sidx0, sidx1};
    unsigned hb_s[2] = {(unsigned)__cvta_generic_to_shared(hbuf0),
                        (unsigned)__cvta_generic_to_shared(hbuf1)};
    unsigned si_s[2] = {(unsigned)__cvta_generic_to_shared(sidx0),
                        (unsigned)__cvta_generic_to_shared(sidx1)};

    // Preload A fragments (W2^T hi/lo, all 8 k-steps) into registers.
    unsigned ah[8][4], al[8][4];
    {
        const unsigned* Hp = (const unsigned*)W2hi;
        const unsigned* Lp = (const unsigned*)W2lo;
#pragma unroll
        for (int ks = 0; ks < 8; ks++) {
            int k0 = ks * 16;
            int i00 = (m0 + g) * (C / 2) + (k0 + tig * 2) / 2;
            ah[ks][0] = Hp[i00];
            ah[ks][1] = Hp[i00 + 8 * (C / 2)];
            ah[ks][2] = Hp[i00 + 4];
            ah[ks][3] = Hp[i00 + 8 * (C / 2) + 4];
            al[ks][0] = Lp[i00];
            al[ks][1] = Lp[i00 + 8 * (C / 2)];
            al[ks][2] = Lp[i00 + 4];
            al[ks][3] = Lp[i00 + 8 * (C / 2) + 4];
        }
    }

    int ntiles = (E + TE - 1) / TE;

    auto load_tile = [&](int tile, int b) {
        int e0 = tile * TE;
        int e = tid >> 2;
        int ego = e0 + e;
        if (ego > E - 1) ego = E - 1;
        const __half* gsrc = hgl + (size_t)ego * C + (tid & 3) * 32;
        unsigned sdst = hb_s[b] + (unsigned)((e * HST + (tid & 3) * 32) * 2);
#pragma unroll
        for (int j = 0; j < 4; j++)
            cpasync16(sdst + j * 16, gsrc + j * 8);
        if (tid < TE / 4) {
            int o = tid * 4;
            if (e0 + o + 3 < E) {
                cpasync16(si_s[b] + o * 4, dsts + e0 + o);
            } else {
                for (int j = 0; j < 4; j++)
                    sib[b][o + j] = (e0 + o + j < E) ? dsts[e0 + o + j] : -1;
            }
        }
        cpcommit();
    };

    if (blockIdx.x < ntiles) load_tile(blockIdx.x, 0);

    int i = 0;
    for (int tile = blockIdx.x; tile < ntiles; tile += gridDim.x, i++) {
        int cur = i & 1;
        int nt = tile + gridDim.x;
        if (nt < ntiles) load_tile(nt, cur ^ 1);
        else cpcommit();
        cpwait1();
        __syncthreads();

        const __half* h_s = hb[cur];
        const int* si = sib[cur];
#pragma unroll 1
        for (int et = 0; et < 8; et++) {
            int e0t = ebase + et * 8;
            float d0 = 0.f, d1 = 0.f, d2 = 0.f, d3 = 0.f;
#pragma unroll
            for (int ks = 0; ks < 8; ks++) {
                int k0 = ks * 16;
                const unsigned* bp = (const unsigned*)(h_s + (e0t + g) * HST + k0 + tig * 2);
                unsigned b0 = bp[0], b1 = bp[4];
                mma16816(d0, d1, d2, d3, ah[ks][0], ah[ks][1], ah[ks][2], ah[ks][3], b0, b1);
                mma16816(d0, d1, d2, d3, al[ks][0], al[ks][1], al[ks][2], al[ks][3], b0, b1);
            }
            // edge-major scalar stores, conflict-free
            int eA = e0t + tig * 2, eB = eA + 1;
            DT[eA * DSTE + m0 + g]     = d0;
            DT[eB * DSTE + m0 + g]     = d1;
            DT[eA * DSTE + m0 + g + 8] = d2;
            DT[eB * DSTE + m0 + g + 8] = d3;
        }
        __syncthreads();

        // fused segmented max: thread = (channel, 32-edge quarter)
        {
            int ch = tid & 127;
            int q = tid >> 7;
            int base = q * 32;
            int prev = si[base];
            float runmax = DT[base * DSTE + ch];
#pragma unroll
            for (int ii = 1; ii < 32; ii++) {
                int d = si[base + ii];
                float v = DT[(base + ii) * DSTE + ch];
                if (d != prev) {
                    if (prev >= 0) atomicMaxF(agg + (size_t)prev * C + ch, runmax);
                    prev = d;
                    runmax = v;
                } else {
                    runmax = fmaxf(runmax, v);
                }
            }
            if (prev >= 0) atomicMaxF(agg + (size_t)prev * C + ch, runmax);
        }
        __syncthreads();
    }
}

// ---------------- finalize: empty nodes -> 0, +b2, optional relu ---------------
__global__ void finalize_kernel(const float* __restrict__ agg,
                                const float* __restrict__ b2,
                                float* __restrict__ out, int N, int do_relu)
{
    int idx = blockIdx.x * blockDim.x + threadIdx.x;
    if (idx >= N * C) return;
    int c = idx & (C - 1);
    float v = agg[idx];
    float o = isfinite(v) ? (v + b2[c]) : 0.f;
    if (do_relu) o = fmaxf(o, 0.f);
    out[idx] = o;
}

// ---------------- launch -------------------------------------------------------
extern "C" void kernel_launch(void* const* d_in, const int* in_sizes, int n_in,
                              void* d_out, int out_size)
{
    const float* x  = (const float*)d_in[0];
    const int*   ei = (const int*)d_in[1];
    int N = in_sizes[0] / C;
    int E = in_sizes[1] / 2;
    const int* srcp = ei;
    const int* dstp = ei + E;

    float *pq, *aggp, *xcur, *Wc;
    __half *w2hi, *w2lo, *hbuf;
    int *off, *curp, *bsum, *srcs, *dsts;
    cudaGetSymbolAddress((void**)&pq,   g_pq);
    cudaGetSymbolAddress((void**)&aggp, g_agg);
    cudaGetSymbolAddress((void**)&xcur, g_x);
    cudaGetSymbolAddress((void**)&Wc,   g_Wc);
    cudaGetSymbolAddress((void**)&w2hi, g_w2hi);
    cudaGetSymbolAddress((void**)&w2lo, g_w2lo);
    cudaGetSymbolAddress((void**)&hbuf, g_h);
    cudaGetSymbolAddress((void**)&off,  g_off);
    cudaGetSymbolAddress((void**)&curp, g_cur);
    cudaGetSymbolAddress((void**)&bsum, g_bsum);
    cudaGetSymbolAddress((void**)&srcs, g_srcs);
    cudaGetSymbolAddress((void**)&dsts, g_dsts);

    // ---- sort edges by dst (once; reused by all 3 layers) ----
    int nscan = N + 1;
    int nb = (nscan + 1023) / 1024;
    cudaMemsetAsync(off, 0, (size_t)(N + 1) * sizeof(int));
    hist_kernel<<<(E + 255) / 256, 256>>>(dstp, off, E);
    scan1_kernel<<<nb, 1024>>>(off, bsum, nscan);
    scan2_kernel<<<1, 1>>>(bsum, nb);
    scan3_kernel<<<nb, 1024>>>(off, bsum, curp, nscan, N);
    scatter_kernel<<<(E + 255) / 256, 256>>>(srcp, dstp, curp, srcs, dsts, E);

    const size_t SMEM = (size_t)(TE * DSTE) * sizeof(float)
                      + (size_t)(2 * TE * HST) * sizeof(__half)
                      + 2 * TE * sizeof(int);
    cudaFuncSetAttribute(edge_gemm_kernel, cudaFuncAttributeMaxDynamicSharedMemorySize, (int)SMEM);

    const float* Ws[3][4] = {
        {(const float*)d_in[2],  (const float*)d_in[3],  (const float*)d_in[4],  (const float*)d_in[5]},
        {(const float*)d_in[6],  (const float*)d_in[7],  (const float*)d_in[8],  (const float*)d_in[9]},
        {(const float*)d_in[10], (const float*)d_in[11], (const float*)d_in[12], (const float*)d_in[13]},
    };

    const float* xin = x;
    for (int l = 0; l < 3; l++) {
        const float* W1 = Ws[l][0];
        const float* b1 = Ws[l][1];
        const float* W2 = Ws[l][2];
        const float* b2 = Ws[l][3];
        float* xout = (l == 2) ? (float*)d_out : xcur;

        prep_kernel<<<C, 256>>>(W1, Wc);
        w2split_kernel<<<C, C>>>(W2, w2hi, w2lo);
        node_gemm_kernel<<<(N + 31) / 32, 256>>>(xin, Wc, b1, pq, N);
        gather_kernel<<<(E * 4 + 255) / 256, 256>>>(pq, srcs, dsts, hbuf, E);
        cudaMemsetAsync(aggp, 0xFF, (size_t)N * C * sizeof(float));
        edge_gemm_kernel<<<148, 512, SMEM>>>(hbuf, dsts, w2hi, w2lo, aggp, E);
        finalize_kernel<<<(N * C + 255) / 256, 256>>>(aggp, b2, xout, N, (l < 2) ? 1 : 0);

        xin = xcur;
    }
}

// round 9
// speedup vs baseline: 2.2731x; 1.1074x over previous
#include <cuda_runtime.h>
#include <cuda_fp16.h>
#include <math.h>

#define N_NODES 50000
#define N_EDGES 800000
#define C 128
#define TE 128           // edges per tile
#define HST 136          // tile stride (halfs): conflict-free B-frag LDS
#define DSTE 132         // D tile stride (floats), edge-major [e][ch]

// ---------------- scratch (static device globals; no allocations) -------------
__device__ float g_pq[(size_t)N_NODES * 256];      // [N][256]: p (+b1) | q
__device__ float g_agg[(size_t)N_NODES * C];       // max-aggregation buffer
__device__ float g_x[(size_t)N_NODES * C];         // inter-layer node features
__device__ float g_Wc[C * 256];                    // node-gemm combined W1 (fp32)
__device__ __half g_wchi[256 * C];                 // Wc^T hi plane [out][k]
__device__ __half g_wclo[256 * C];                 // Wc^T lo plane [out][k]
__device__ __half g_w2hi[C * C];                   // W2^T hi plane [n][k]
__device__ __half g_w2lo[C * C];                   // W2^T lo plane [n][k]
__device__ __half g_h[(size_t)N_EDGES * C];        // dense per-edge hidden (fp16)
__device__ int g_off[N_NODES + 1];                 // CSR row pointers (by dst)
__device__ int g_cur[N_NODES];                     // scatter cursors
__device__ int g_bsum[64];                         // scan block sums
__device__ int g_srcs[N_EDGES];                    // src sorted by dst
__device__ int g_dsts[N_EDGES];                    // dst sorted (ascending)

// ---------------- float atomic max (signed-max / unsigned-min trick) ----------
__device__ __forceinline__ void atomicMaxF(float* a, float v) {
    if (v >= 0.0f) atomicMax((int*)a, __float_as_int(v));
    else           atomicMin((unsigned int*)a, __float_as_uint(v));
}

// ---------------- HMMA m16n8k16 fp16 ------------------------------------------
__device__ __forceinline__ void mma16816(float& d0, float& d1, float& d2, float& d3,
                                         unsigned a0, unsigned a1, unsigned a2, unsigned a3,
                                         unsigned b0, unsigned b1)
{
    asm volatile(
        "mma.sync.aligned.m16n8k16.row.col.f32.f16.f16.f32 "
        "{%0,%1,%2,%3},{%4,%5,%6,%7},{%8,%9},{%0,%1,%2,%3};\n"
        : "+f"(d0), "+f"(d1), "+f"(d2), "+f"(d3)
        : "r"(a0), "r"(a1), "r"(a2), "r"(a3), "r"(b0), "r"(b1));
}

// ---------------- cp.async helpers ---------------------------------------------
__device__ __forceinline__ void cpasync16(unsigned saddr, const void* gptr) {
    asm volatile("cp.async.cg.shared.global [%0], [%1], 16;\n" :: "r"(saddr), "l"(gptr));
}
__device__ __forceinline__ void cpcommit() { asm volatile("cp.async.commit_group;\n"); }
__device__ __forceinline__ void cpwait2()  { asm volatile("cp.async.wait_group 2;\n"); }

// ---------------- A-fragment preload (W^T hi/lo, 8 k-steps) --------------------
// i00 = row*64 + k0/2 + tig  (tig term is load-bearing: per-lane k offset)
__device__ __forceinline__ void load_a_frags(const __half* Whi, const __half* Wlo,
                                             int row, int tig,
                                             unsigned ah[8][4], unsigned al[8][4])
{
    const unsigned* Hp = (const unsigned*)Whi;
    const unsigned* Lp = (const unsigned*)Wlo;
#pragma unroll
    for (int ks = 0; ks < 8; ks++) {
        int k0 = ks * 16;
        int i00 = row * (C / 2) + (k0 >> 1) + tig;
        ah[ks][0] = Hp[i00];
        ah[ks][1] = Hp[i00 + 8 * (C / 2)];
        ah[ks][2] = Hp[i00 + 4];
        ah[ks][3] = Hp[i00 + 8 * (C / 2) + 4];
        al[ks][0] = Lp[i00];
        al[ks][1] = Lp[i00 + 8 * (C / 2)];
        al[ks][2] = Lp[i00 + 4];
        al[ks][3] = Lp[i00 + 8 * (C / 2) + 4];
    }
}

// ---------------- sort-by-dst preprocessing ------------------------------------
__global__ void hist_kernel(const int* __restrict__ dst, int* __restrict__ off, int E) {
    int e = blockIdx.x * blockDim.x + threadIdx.x;
    if (e < E) atomicAdd(&off[dst[e] + 1], 1);
}

__global__ void scan1_kernel(int* __restrict__ a, int* __restrict__ bsum, int n) {
    __shared__ int s[1024];
    int i = blockIdx.x * 1024 + threadIdx.x;
    int v = (i < n) ? a[i] : 0;
    s[threadIdx.x] = v;
    __syncthreads();
    for (int d = 1; d < 1024; d <<= 1) {
        int t = (threadIdx.x >= d) ? s[threadIdx.x - d] : 0;
        __syncthreads();
        s[threadIdx.x] += t;
        __syncthreads();
    }
    if (i < n) a[i] = s[threadIdx.x];
    if (threadIdx.x == 1023) bsum[blockIdx.x] = s[1023];
}

__global__ void scan2_kernel(int* __restrict__ bsum, int nb) {
    int acc = 0;
    for (int i = 0; i < nb; i++) { int t = bsum[i]; bsum[i] = acc; acc += t; }
}

__global__ void scan3_kernel(int* __restrict__ a, const int* __restrict__ bsum,
                             int* __restrict__ cur, int n, int N) {
    int i = blockIdx.x * 1024 + threadIdx.x;
    if (i < n) {
        int v = a[i] + bsum[blockIdx.x];
        a[i] = v;
        if (i < N) cur[i] = v;
    }
}

__global__ void scatter_kernel(const int* __restrict__ src, const int* __restrict__ dst,
                               int* __restrict__ cur, int* __restrict__ ssrc,
                               int* __restrict__ sdst, int E) {
    int e = blockIdx.x * blockDim.x + threadIdx.x;
    if (e < E) {
        int d = dst[e];
        int pos = atomicAdd(&cur[d], 1);
        sdst[pos] = d;
        ssrc[pos] = src[e];
    }
}

// ---------------- prep: Wc from W1 (fp32) --------------------------------------
__global__ void prep_kernel(const float* __restrict__ W1, float* __restrict__ Wc) {
    int k = blockIdx.x;
    int j = threadIdx.x;
    if (j < C) Wc[k * 256 + j] = W1[k * C + j] - W1[(C + k) * C + j];
    else       Wc[k * 256 + j] = W1[(C + k) * C + (j - C)];
}

// ---------------- prep: split Wc^T into fp16 hi/lo -----------------------------
__global__ void wcsplit_kernel(const float* __restrict__ Wc,
                               __half* __restrict__ hi, __half* __restrict__ lo) {
    int j = blockIdx.x;   // out channel 0..255
    int k = threadIdx.x;  // in channel 0..127
    float w = Wc[k * 256 + j];
    __half h = __float2half_rn(w);
    hi[j * C + k] = h;
    lo[j * C + k] = __float2half_rn(w - __half2float(h));
}

// ---------------- prep: split W2^T into fp16 hi/lo -----------------------------
__global__ void w2split_kernel(const float* __restrict__ W2,
                               __half* __restrict__ hi, __half* __restrict__ lo) {
    int n = blockIdx.x;
    int k = threadIdx.x;
    float w = W2[k * C + n];
    __half h = __float2half_rn(w);
    hi[n * C + k] = h;
    lo[n * C + k] = __float2half_rn(w - __half2float(h));
}

// ---------------- node GEMM (tensor, 3-term split): pq = x @ Wc + b1 -----------
// 512 threads / 16 warps. Warp w: out channels w*16..+16; 128-node tile.
__global__ void __launch_bounds__(512, 1) node_mma_kernel(
    const float* __restrict__ x,
    const __half* __restrict__ Whi, const __half* __restrict__ Wlo,
    const float* __restrict__ b1, float* __restrict__ pq, int N)
{
    extern __shared__ char sm[];
    __half* xh = (__half*)sm;          // [128][HST]
    __half* xl = xh + 128 * HST;       // [128][HST]

    int tid = threadIdx.x;
    int wid = tid >> 5, lane = tid & 31;
    int g = lane >> 2, tig = lane & 3;
    int m0 = wid * 16;

    unsigned ah[8][4], al[8][4];
    load_a_frags(Whi, Wlo, m0 + g, tig, ah, al);

    float bias0 = (m0 + g < C) ? b1[m0 + g] : 0.f;
    float bias1 = (m0 + g + 8 < C) ? b1[m0 + g + 8] : 0.f;

    int n0 = blockIdx.x * 128;

    // load + convert x tile to fp16 hi/lo planes
    {
        int e = tid >> 2;
        int part = tid & 3;
        int node = n0 + e;
        const float4* xr = (const float4*)(x + (size_t)node * C + part * 32);
        unsigned* xhp = (unsigned*)(xh + e * HST + part * 32);
        unsigned* xlp = (unsigned*)(xl + e * HST + part * 32);
#pragma unroll
        for (int i = 0; i < 8; i++) {
            float4 v = (node < N) ? xr[i] : make_float4(0.f, 0.f, 0.f, 0.f);
            __half2 hA = __floats2half2_rn(v.x, v.y);
            __half2 hB = __floats2half2_rn(v.z, v.w);
            __half2 lA = __floats2half2_rn(v.x - __half2float(hA.x), v.y - __half2float(hA.y));
            __half2 lB = __floats2half2_rn(v.z - __half2float(hB.x), v.w - __half2float(hB.y));
            xhp[i * 2 + 0] = *(unsigned*)&hA;
            xhp[i * 2 + 1] = *(unsigned*)&hB;
            xlp[i * 2 + 0] = *(unsigned*)&lA;
            xlp[i * 2 + 1] = *(unsigned*)&lB;
        }
    }
    __syncthreads();

#pragma unroll 1
    for (int et = 0; et < 16; et++) {
        int e0t = et * 8;
        float d0 = 0.f, d1 = 0.f, d2 = 0.f, d3 = 0.f;
#pragma unroll
        for (int ks = 0; ks < 8; ks++) {
            int k0 = ks * 16;
            const unsigned* bhp = (const unsigned*)(xh + (e0t + g) * HST + k0 + tig * 2);
            const unsigned* blp = (const unsigned*)(xl + (e0t + g) * HST + k0 + tig * 2);
            unsigned bh0 = bhp[0], bh1 = bhp[4];
            unsigned bl0 = blp[0], bl1 = blp[4];
            mma16816(d0, d1, d2, d3, ah[ks][0], ah[ks][1], ah[ks][2], ah[ks][3], bh0, bh1);
            mma16816(d0, d1, d2, d3, ah[ks][0], ah[ks][1], ah[ks][2], ah[ks][3], bl0, bl1);
            mma16816(d0, d1, d2, d3, al[ks][0], al[ks][1], al[ks][2], al[ks][3], bh0, bh1);
        }
        int eA = n0 + e0t + tig * 2;
        int eB = eA + 1;
        if (eA < N) {
            pq[(size_t)eA * 256 + m0 + g]     = d0 + bias0;
            pq[(size_t)eA * 256 + m0 + g + 8] = d2 + bias1;
        }
        if (eB < N) {
            pq[(size_t)eB * 256 + m0 + g]     = d1 + bias0;
            pq[(size_t)eB * 256 + m0 + g + 8] = d3 + bias1;
        }
    }
}

// ---------------- gather: h[e] = fp16(relu(p[dst[e]] + q[src[e]])) -------------
__global__ void __launch_bounds__(256) gather_kernel(
    const float* __restrict__ pq, const int* __restrict__ src,
    const int* __restrict__ dst, __half* __restrict__ h, int E)
{
    int idx = blockIdx.x * blockDim.x + threadIdx.x;
    int e = idx >> 2;
    if (e >= E) return;
    int part = idx & 3;   // 32 channels
    int dn = __ldg(dst + e), sn = __ldg(src + e);
    const float4* p = (const float4*)(pq + (size_t)dn * 256 + part * 32);
    const float4* q = (const float4*)(pq + (size_t)sn * 256 + C + part * 32);

    unsigned buf[16];
#pragma unroll
    for (int i = 0; i < 8; i++) {
        float4 a = p[i], b = q[i];
        __half2 h0 = __floats2half2_rn(fmaxf(a.x + b.x, 0.f), fmaxf(a.y + b.y, 0.f));
        __half2 h1 = __floats2half2_rn(fmaxf(a.z + b.z, 0.f), fmaxf(a.w + b.w, 0.f));
        buf[i * 2 + 0] = *(unsigned*)&h0;
        buf[i * 2 + 1] = *(unsigned*)&h1;
    }
    uint4* out = (uint4*)(h + (size_t)e * C + part * 32);
#pragma unroll
    for (int i = 0; i < 4; i++)
        out[i] = make_uint4(buf[i * 4], buf[i * 4 + 1], buf[i * 4 + 2], buf[i * 4 + 3]);
}

// ---------------- dense edge GEMM (3-stage cp.async) + fused segmax ------------
__global__ void __launch_bounds__(512, 1) edge_gemm_kernel(
    const __half* __restrict__ hgl, const int* __restrict__ dsts,
    const __half* __restrict__ W2hi, const __half* __restrict__ W2lo,
    float* __restrict__ agg, int E)
{
    extern __shared__ char smraw[];
    float* DT = (float*)smraw;                        // [TE][DSTE]
    __half* hbufs = (__half*)(DT + TE * DSTE);        // 3 x [TE][HST]
    int* sidxs = (int*)(hbufs + 3 * TE * HST);        // 3 x [TE]

    int tid = threadIdx.x;
    int wid = tid >> 5, lane = tid & 31;
    int g = lane >> 2, tig = lane & 3;
    int m0 = (wid & 7) * 16;
    int ebase = (wid >> 3) * 64;

    const __half* hb[3] = {hbufs, hbufs + TE * HST, hbufs + 2 * TE * HST};
    int* sib[3] = {sidxs, sidxs + TE, sidxs + 2 * TE};
    unsigned hb_s[3], si_s[3];
#pragma unroll
    for (int b = 0; b < 3; b++) {
        hb_s[b] = (unsigned)__cvta_generic_to_shared(hb[b]);
        si_s[b] = (unsigned)__cvta_generic_to_shared(sib[b]);
    }

    unsigned ah[8][4], al[8][4];
    load_a_frags(W2hi, W2lo, m0 + g, tig, ah, al);

    int ntiles = (E + TE - 1) / TE;

    auto load_tile = [&](int tile, int b) {
        int e0 = tile * TE;
        int e = tid >> 2;
        int ego = e0 + e;
        if (ego > E - 1) ego = E - 1;
        const __half* gsrc = hgl + (size_t)ego * C + (tid & 3) * 32;
        unsigned sdst = hb_s[b] + (unsigned)((e * HST + (tid & 3) * 32) * 2);
#pragma unroll
        for (int j = 0; j < 4; j++)
            cpasync16(sdst + j * 16, gsrc + j * 8);
        if (tid < TE / 4) {
            int o = tid * 4;
            if (e0 + o + 3 < E) {
                cpasync16(si_s[b] + o * 4, dsts + e0 + o);
            } else {
                for (int j = 0; j < 4; j++)
                    sib[b][o + j] = (e0 + o + j < E) ? dsts[e0 + o + j] : -1;
            }
        }
        cpcommit();
    };

    // prologue: 2 tiles in flight
    if (blockIdx.x < ntiles) load_tile(blockIdx.x, 0); else cpcommit();
    if (blockIdx.x + gridDim.x < ntiles) load_tile(blockIdx.x + gridDim.x, 1); else cpcommit();

    int i = 0;
    for (int tile = blockIdx.x; tile < ntiles; tile += gridDim.x, i++) {
        int cur = i % 3;
        int nt = tile + 2 * gridDim.x;
        if (nt < ntiles) load_tile(nt, (i + 2) % 3);
        else cpcommit();
        cpwait2();
        __syncthreads();

        const __half* h_s = hb[cur];
        const int* si = sib[cur];
#pragma unroll 1
        for (int et = 0; et < 8; et++) {
            int e0t = ebase + et * 8;
            float d0 = 0.f, d1 = 0.f, d2 = 0.f, d3 = 0.f;
#pragma unroll
            for (int ks = 0; ks < 8; ks++) {
                int k0 = ks * 16;
                const unsigned* bp = (const unsigned*)(h_s + (e0t + g) * HST + k0 + tig * 2);
                unsigned b0 = bp[0], b1 = bp[4];
                mma16816(d0, d1, d2, d3, ah[ks][0], ah[ks][1], ah[ks][2], ah[ks][3], b0, b1);
                mma16816(d0, d1, d2, d3, al[ks][0], al[ks][1], al[ks][2], al[ks][3], b0, b1);
            }
            int eA = e0t + tig * 2, eB = eA + 1;
            DT[eA * DSTE + m0 + g]     = d0;
            DT[eB * DSTE + m0 + g]     = d1;
            DT[eA * DSTE + m0 + g + 8] = d2;
            DT[eB * DSTE + m0 + g + 8] = d3;
        }
        __syncthreads();

        // fused segmented max: thread = (channel, 32-edge quarter)
        {
            int ch = tid & 127;
            int q = tid >> 7;
            int base = q * 32;
            int prev = si[base];
            float runmax = DT[base * DSTE + ch];
#pragma unroll
            for (int ii = 1; ii < 32; ii++) {
                int d = si[base + ii];
                float v = DT[(base + ii) * DSTE + ch];
                if (d != prev) {
                    if (prev >= 0) atomicMaxF(agg + (size_t)prev * C + ch, runmax);
                    prev = d;
                    runmax = v;
                } else {
                    runmax = fmaxf(runmax, v);
                }
            }
            if (prev >= 0) atomicMaxF(agg + (size_t)prev * C + ch, runmax);
        }
        __syncthreads();
    }
}

// ---------------- finalize: empty nodes -> 0, +b2, optional relu ---------------
__global__ void finalize_kernel(const float* __restrict__ agg,
                                const float* __restrict__ b2,
                                float* __restrict__ out, int N, int do_relu)
{
    int idx = blockIdx.x * blockDim.x + threadIdx.x;
    if (idx >= N * C) return;
    int c = idx & (C - 1);
    float v = agg[idx];
    float o = isfinite(v) ? (v + b2[c]) : 0.f;
    if (do_relu) o = fmaxf(o, 0.f);
    out[idx] = o;
}

// ---------------- launch -------------------------------------------------------
extern "C" void kernel_launch(void* const* d_in, const int* in_sizes, int n_in,
                              void* d_out, int out_size)
{
    const float* x  = (const float*)d_in[0];
    const int*   ei = (const int*)d_in[1];
    int N = in_sizes[0] / C;
    int E = in_sizes[1] / 2;
    const int* srcp = ei;
    const int* dstp = ei + E;

    float *pq, *aggp, *xcur, *Wc;
    __half *wchi, *wclo, *w2hi, *w2lo, *hbuf;
    int *off, *curp, *bsum, *srcs, *dsts;
    cudaGetSymbolAddress((void**)&pq,   g_pq);
    cudaGetSymbolAddress((void**)&aggp, g_agg);
    cudaGetSymbolAddress((void**)&xcur, g_x);
    cudaGetSymbolAddress((void**)&Wc,   g_Wc);
    cudaGetSymbolAddress((void**)&wchi, g_wchi);
    cudaGetSymbolAddress((void**)&wclo, g_wclo);
    cudaGetSymbolAddress((void**)&w2hi, g_w2hi);
    cudaGetSymbolAddress((void**)&w2lo, g_w2lo);
    cudaGetSymbolAddress((void**)&hbuf, g_h);
    cudaGetSymbolAddress((void**)&off,  g_off);
    cudaGetSymbolAddress((void**)&curp, g_cur);
    cudaGetSymbolAddress((void**)&bsum, g_bsum);
    cudaGetSymbolAddress((void**)&srcs, g_srcs);
    cudaGetSymbolAddress((void**)&dsts, g_dsts);

    // ---- sort edges by dst (once; reused by all 3 layers) ----
    int nscan = N + 1;
    int nb = (nscan + 1023) / 1024;
    cudaMemsetAsync(off, 0, (size_t)(N + 1) * sizeof(int));
    hist_kernel<<<(E + 255) / 256, 256>>>(dstp, off, E);
    scan1_kernel<<<nb, 1024>>>(off, bsum, nscan);
    scan2_kernel<<<1, 1>>>(bsum, nb);
    scan3_kernel<<<nb, 1024>>>(off, bsum, curp, nscan, N);
    scatter_kernel<<<(E + 255) / 256, 256>>>(srcp, dstp, curp, srcs, dsts, E);

    const size_t SMEM_E = (size_t)(TE * DSTE) * sizeof(float)
                        + (size_t)(3 * TE * HST) * sizeof(__half)
                        + 3 * TE * sizeof(int);
    cudaFuncSetAttribute(edge_gemm_kernel, cudaFuncAttributeMaxDynamicSharedMemorySize, (int)SMEM_E);
    const size_t SMEM_N = (size_t)(2 * 128 * HST) * sizeof(__half);
    cudaFuncSetAttribute(node_mma_kernel, cudaFuncAttributeMaxDynamicSharedMemorySize, (int)SMEM_N);

    const float* Ws[3][4] = {
        {(const float*)d_in[2],  (const float*)d_in[3],  (const float*)d_in[4],  (const float*)d_in[5]},
        {(const float*)d_in[6],  (const float*)d_in[7],  (const float*)d_in[8],  (const float*)d_in[9]},
        {(const float*)d_in[10], (const float*)d_in[11], (const float*)d_in[12], (const float*)d_in[13]},
    };

    const float* xin = x;
    for (int l = 0; l < 3; l++) {
        const float* W1 = Ws[l][0];
        const float* b1 = Ws[l][1];
        const float* W2 = Ws[l][2];
        const float* b2 = Ws[l][3];
        float* xout = (l == 2) ? (float*)d_out : xcur;

        prep_kernel<<<C, 256>>>(W1, Wc);
        wcsplit_kernel<<<256, C>>>(Wc, wchi, wclo);
        w2split_kernel<<<C, C>>>(W2, w2hi, w2lo);
        node_mma_kernel<<<(N + 127) / 128, 512, SMEM_N>>>(xin, wchi, wclo, b1, pq, N);
        gather_kernel<<<(E * 4 + 255) / 256, 256>>>(pq, srcs, dsts, hbuf, E);
        cudaMemsetAsync(aggp, 0xFF, (size_t)N * C * sizeof(float));
        edge_gemm_kernel<<<148, 512, SMEM_E>>>(hbuf, dsts, w2hi, w2lo, aggp, E);
        finalize_kernel<<<(N * C + 255) / 256, 256>>>(aggp, b2, xout, N, (l < 2) ? 1 : 0);

        xin = xcur;
    }
}

// round 10
// speedup vs baseline: 2.8297x; 1.2449x over previous
#include <cuda_runtime.h>
#include <cuda_fp16.h>
#include <math.h>

#define N_NODES 50000
#define N_EDGES 800000
#define C 128
#define TE 128           // node-gemm tile (nodes)
#define TE2 64           // edge tile (edges)
#define HST 136          // h tile stride (halfs): conflict-free B-frag LDS
#define DSTE 132         // D tile stride (floats), edge-major [e][ch]

// ---------------- scratch (static device globals; no allocations) -------------
__device__ float g_pq[(size_t)N_NODES * 256];      // [N][256]: p (+b1) | q
__device__ float g_agg[(size_t)N_NODES * C];       // max-aggregation buffer
__device__ float g_x[(size_t)N_NODES * C];         // inter-layer node features
__device__ float g_Wc[C * 256];                    // node-gemm combined W1 (fp32)
__device__ __half g_wchi[256 * C];                 // Wc^T hi plane [out][k]
__device__ __half g_wclo[256 * C];                 // Wc^T lo plane [out][k]
__device__ __half g_w2hi[C * C];                   // W2^T hi plane [n][k]
__device__ __half g_w2lo[C * C];                   // W2^T lo plane [n][k]
__device__ int g_off[N_NODES + 1];                 // CSR row pointers (by dst)
__device__ int g_cur[N_NODES];                     // scatter cursors
__device__ int g_bsum[64];                         // scan block sums
__device__ int g_srcs[N_EDGES];                    // src sorted by dst
__device__ int g_dsts[N_EDGES];                    // dst sorted (ascending)

// ---------------- float atomic max (signed-max / unsigned-min trick) ----------
__device__ __forceinline__ void atomicMaxF(float* a, float v) {
    if (v >= 0.0f) atomicMax((int*)a, __float_as_int(v));
    else           atomicMin((unsigned int*)a, __float_as_uint(v));
}

// ---------------- HMMA m16n8k16 fp16 ------------------------------------------
__device__ __forceinline__ void mma16816(float& d0, float& d1, float& d2, float& d3,
                                         unsigned a0, unsigned a1, unsigned a2, unsigned a3,
                                         unsigned b0, unsigned b1)
{
    asm volatile(
        "mma.sync.aligned.m16n8k16.row.col.f32.f16.f16.f32 "
        "{%0,%1,%2,%3},{%4,%5,%6,%7},{%8,%9},{%0,%1,%2,%3};\n"
        : "+f"(d0), "+f"(d1), "+f"(d2), "+f"(d3)
        : "r"(a0), "r"(a1), "r"(a2), "r"(a3), "r"(b0), "r"(b1));
}

// ---------------- cp.async helpers ---------------------------------------------
__device__ __forceinline__ void cpasync16(unsigned saddr, const void* gptr) {
    asm volatile("cp.async.cg.shared.global [%0], [%1], 16;\n" :: "r"(saddr), "l"(gptr));
}
__device__ __forceinline__ void cpcommit() { asm volatile("cp.async.commit_group;\n"); }
__device__ __forceinline__ void cpwait1()  { asm volatile("cp.async.wait_group 1;\n"); }

// ---------------- A-fragment preload (W^T hi/lo, 8 k-steps) --------------------
// i00 = row*64 + k0/2 + tig  (tig term is load-bearing: per-lane k offset)
__device__ __forceinline__ void load_a_frags(const __half* Whi, const __half* Wlo,
                                             int row, int tig,
                                             unsigned ah[8][4], unsigned al[8][4])
{
    const unsigned* Hp = (const unsigned*)Whi;
    const unsigned* Lp = (const unsigned*)Wlo;
#pragma unroll
    for (int ks = 0; ks < 8; ks++) {
        int k0 = ks * 16;
        int i00 = row * (C / 2) + (k0 >> 1) + tig;
        ah[ks][0] = Hp[i00];
        ah[ks][1] = Hp[i00 + 8 * (C / 2)];
        ah[ks][2] = Hp[i00 + 4];
        ah[ks][3] = Hp[i00 + 8 * (C / 2) + 4];
        al[ks][0] = Lp[i00];
        al[ks][1] = Lp[i00 + 8 * (C / 2)];
        al[ks][2] = Lp[i00 + 4];
        al[ks][3] = Lp[i00 + 8 * (C / 2) + 4];
    }
}

// ---------------- sort-by-dst preprocessing ------------------------------------
__global__ void hist_kernel(const int* __restrict__ dst, int* __restrict__ off, int E) {
    int e = blockIdx.x * blockDim.x + threadIdx.x;
    if (e < E) atomicAdd(&off[dst[e] + 1], 1);
}

__global__ void scan1_kernel(int* __restrict__ a, int* __restrict__ bsum, int n) {
    __shared__ int s[1024];
    int i = blockIdx.x * 1024 + threadIdx.x;
    int v = (i < n) ? a[i] : 0;
    s[threadIdx.x] = v;
    __syncthreads();
    for (int d = 1; d < 1024; d <<= 1) {
        int t = (threadIdx.x >= d) ? s[threadIdx.x - d] : 0;
        __syncthreads();
        s[threadIdx.x] += t;
        __syncthreads();
    }
    if (i < n) a[i] = s[threadIdx.x];
    if (threadIdx.x == 1023) bsum[blockIdx.x] = s[1023];
}

__global__ void scan2_kernel(int* __restrict__ bsum, int nb) {
    int acc = 0;
    for (int i = 0; i < nb; i++) { int t = bsum[i]; bsum[i] = acc; acc += t; }
}

__global__ void scan3_kernel(int* __restrict__ a, const int* __restrict__ bsum,
                             int* __restrict__ cur, int n, int N) {
    int i = blockIdx.x * 1024 + threadIdx.x;
    if (i < n) {
        int v = a[i] + bsum[blockIdx.x];
        a[i] = v;
        if (i < N) cur[i] = v;
    }
}

__global__ void scatter_kernel(const int* __restrict__ src, const int* __restrict__ dst,
                               int* __restrict__ cur, int* __restrict__ ssrc,
                               int* __restrict__ sdst, int E) {
    int e = blockIdx.x * blockDim.x + threadIdx.x;
    if (e < E) {
        int d = dst[e];
        int pos = atomicAdd(&cur[d], 1);
        sdst[pos] = d;
        ssrc[pos] = src[e];
    }
}

// ---------------- prep: Wc from W1 (fp32) --------------------------------------
__global__ void prep_kernel(const float* __restrict__ W1, float* __restrict__ Wc) {
    int k = blockIdx.x;
    int j = threadIdx.x;
    if (j < C) Wc[k * 256 + j] = W1[k * C + j] - W1[(C + k) * C + j];
    else       Wc[k * 256 + j] = W1[(C + k) * C + (j - C)];
}

// ---------------- prep: split Wc^T into fp16 hi/lo -----------------------------
__global__ void wcsplit_kernel(const float* __restrict__ Wc,
                               __half* __restrict__ hi, __half* __restrict__ lo) {
    int j = blockIdx.x;   // out channel 0..255
    int k = threadIdx.x;  // in channel 0..127
    float w = Wc[k * 256 + j];
    __half h = __float2half_rn(w);
    hi[j * C + k] = h;
    lo[j * C + k] = __float2half_rn(w - __half2float(h));
}

// ---------------- prep: split W2^T into fp16 hi/lo -----------------------------
__global__ void w2split_kernel(const float* __restrict__ W2,
                               __half* __restrict__ hi, __half* __restrict__ lo) {
    int n = blockIdx.x;
    int k = threadIdx.x;
    float w = W2[k * C + n];
    __half h = __float2half_rn(w);
    hi[n * C + k] = h;
    lo[n * C + k] = __float2half_rn(w - __half2float(h));
}

// ---------------- node GEMM (tensor, 3-term split): pq = x @ Wc + b1 -----------
__global__ void __launch_bounds__(512, 1) node_mma_kernel(
    const float* __restrict__ x,
    const __half* __restrict__ Whi, const __half* __restrict__ Wlo,
    const float* __restrict__ b1, float* __restrict__ pq, int N)
{
    extern __shared__ char sm[];
    __half* xh = (__half*)sm;          // [128][HST]
    __half* xl = xh + 128 * HST;       // [128][HST]

    int tid = threadIdx.x;
    int wid = tid >> 5, lane = tid & 31;
    int g = lane >> 2, tig = lane & 3;
    int m0 = wid * 16;

    unsigned ah[8][4], al[8][4];
    load_a_frags(Whi, Wlo, m0 + g, tig, ah, al);

    float bias0 = (m0 + g < C) ? b1[m0 + g] : 0.f;
    float bias1 = (m0 + g + 8 < C) ? b1[m0 + g + 8] : 0.f;

    int n0 = blockIdx.x * 128;

    {
        int e = tid >> 2;
        int part = tid & 3;
        int node = n0 + e;
        const float4* xr = (const float4*)(x + (size_t)node * C + part * 32);
        unsigned* xhp = (unsigned*)(xh + e * HST + part * 32);
        unsigned* xlp = (unsigned*)(xl + e * HST + part * 32);
#pragma unroll
        for (int i = 0; i < 8; i++) {
            float4 v = (node < N) ? xr[i] : make_float4(0.f, 0.f, 0.f, 0.f);
            __half2 hA = __floats2half2_rn(v.x, v.y);
            __half2 hB = __floats2half2_rn(v.z, v.w);
            __half2 lA = __floats2half2_rn(v.x - __half2float(hA.x), v.y - __half2float(hA.y));
            __half2 lB = __floats2half2_rn(v.z - __half2float(hB.x), v.w - __half2float(hB.y));
            xhp[i * 2 + 0] = *(unsigned*)&hA;
            xhp[i * 2 + 1] = *(unsigned*)&hB;
            xlp[i * 2 + 0] = *(unsigned*)&lA;
            xlp[i * 2 + 1] = *(unsigned*)&lB;
        }
    }
    __syncthreads();

#pragma unroll 1
    for (int et = 0; et < 16; et++) {
        int e0t = et * 8;
        float d0 = 0.f, d1 = 0.f, d2 = 0.f, d3 = 0.f;
#pragma unroll
        for (int ks = 0; ks < 8; ks++) {
            int k0 = ks * 16;
            const unsigned* bhp = (const unsigned*)(xh + (e0t + g) * HST + k0 + tig * 2);
            const unsigned* blp = (const unsigned*)(xl + (e0t + g) * HST + k0 + tig * 2);
            unsigned bh0 = bhp[0], bh1 = bhp[4];
            unsigned bl0 = blp[0], bl1 = blp[4];
            mma16816(d0, d1, d2, d3, ah[ks][0], ah[ks][1], ah[ks][2], ah[ks][3], bh0, bh1);
            mma16816(d0, d1, d2, d3, ah[ks][0], ah[ks][1], ah[ks][2], ah[ks][3], bl0, bl1);
            mma16816(d0, d1, d2, d3, al[ks][0], al[ks][1], al[ks][2], al[ks][3], bh0, bh1);
        }
        int eA = n0 + e0t + tig * 2;
        int eB = eA + 1;
        if (eA < N) {
            pq[(size_t)eA * 256 + m0 + g]     = d0 + bias0;
            pq[(size_t)eA * 256 + m0 + g + 8] = d2 + bias1;
        }
        if (eB < N) {
            pq[(size_t)eB * 256 + m0 + g]     = d1 + bias0;
            pq[(size_t)eB * 256 + m0 + g + 8] = d3 + bias1;
        }
    }
}

// ---------------- fused edge kernel: stage pq rows -> h -> GEMM -> segmax -------
// 512 threads / 16 warps, 1 CTA/SM, TE2=64 edges per tile.
// Stage: 128 rows (64 p[dst] + 64 q[src]) x 512B fp32, XOR-swizzled 16B quads.
// Warp w: channels ((w&7)*16), edges ((w>>3)*32 .. +32).
__global__ void __launch_bounds__(512, 1) edge_fused_kernel(
    const float* __restrict__ pq,
    const int* __restrict__ srcs, const int* __restrict__ dsts,
    const __half* __restrict__ W2hi, const __half* __restrict__ W2lo,
    float* __restrict__ agg, int E)
{
    extern __shared__ char smraw[];
    float* DT = (float*)smraw;                          // [TE2][DSTE] 33792B
    __half* h_s = (__half*)(DT + TE2 * DSTE);           // [TE2][HST] 17408B
    float* stage0 = (float*)(h_s + TE2 * HST);          // 128 rows x 32 quads x 16B
    float* stage1 = stage0 + 128 * 128;                 // (65536B each)
    int* sidx0 = (int*)(stage1 + 128 * 128);            // [TE2]
    int* sidx1 = sidx0 + TE2;

    int tid = threadIdx.x;
    int wid = tid >> 5, lane = tid & 31;
    int g = lane >> 2, tig = lane & 3;
    int m0 = (wid & 7) * 16;
    int ebase = (wid >> 3) * 32;

    const float* stg[2] = {stage0, stage1};
    int* sib[2] = {sidx0, sidx1};
    unsigned st_s[2] = {(unsigned)__cvta_generic_to_shared(stage0),
                        (unsigned)__cvta_generic_to_shared(stage1)};
    unsigned si_s[2] = {(unsigned)__cvta_generic_to_shared(sidx0),
                        (unsigned)__cvta_generic_to_shared(sidx1)};

    unsigned ah[8][4], al[8][4];
    load_a_frags(W2hi, W2lo, m0 + g, tig, ah, al);

    int ntiles = (E + TE2 - 1) / TE2;

    // stage loader: 8 passes, warp = one pq row (32 x 16B), swizzled slots
    auto load_tile = [&](int tile, int b) {
        int e0 = tile * TE2;
        int c = tid & 31;
#pragma unroll
        for (int pass = 0; pass < 8; pass++) {
            int row = pass * 16 + (tid >> 5);        // 0..127
            int er = row & 63;
            int ego = e0 + er;
            if (ego > E - 1) ego = E - 1;
            int node = (row < 64) ? __ldg(dsts + ego) : __ldg(srcs + ego);
            const char* gsrc = (const char*)(pq + (size_t)node * 256 + ((row < 64) ? 0 : C))
                             + c * 16;
            unsigned slot = (unsigned)(row * 32 + (c ^ (row & 7)));
            cpasync16(st_s[b] + slot * 16, gsrc);
        }
        if (tid < TE2 / 4) {
            int o = tid * 4;
            if (e0 + o + 3 < E) {
                cpasync16(si_s[b] + o * 4, dsts + e0 + o);
            } else {
                for (int j = 0; j < 4; j++)
                    sib[b][o + j] = (e0 + o + j < E) ? dsts[e0 + o + j] : -1;
            }
        }
        cpcommit();
    };

    if (blockIdx.x < ntiles) load_tile(blockIdx.x, 0); else cpcommit();

    int i = 0;
    for (int tile = blockIdx.x; tile < ntiles; tile += gridDim.x, i++) {
        int cur = i & 1;
        int nt = tile + gridDim.x;
        if (nt < ntiles) load_tile(nt, cur ^ 1);
        else cpcommit();
        cpwait1();
        __syncthreads();

        // convert: h[e][ch] = fp16(relu(p+q)); swizzled conflict-free reads
        {
            int e = tid >> 3;
            int cb = tid & 7;
            const uint4* stp = (const uint4*)stg[cur];
            __half* hrow = h_s + e * HST;
            int sw = e & 7;
#pragma unroll
            for (int j = 0; j < 4; j++) {
                int c = cb + 8 * j;
                uint4 pv = stp[e * 32 + (c ^ sw)];
                uint4 qv = stp[(64 + e) * 32 + (c ^ sw)];
                float4 p4 = *(float4*)&pv;
                float4 q4 = *(float4*)&qv;
                __half2 h0 = __floats2half2_rn(fmaxf(p4.x + q4.x, 0.f), fmaxf(p4.y + q4.y, 0.f));
                __half2 h1 = __floats2half2_rn(fmaxf(p4.z + q4.z, 0.f), fmaxf(p4.w + q4.w, 0.f));
                unsigned u0 = *(unsigned*)&h0, u1 = *(unsigned*)&h1;
                *(uint2*)(hrow + c * 4) = make_uint2(u0, u1);
            }
        }
        __syncthreads();

        // MMA: 4 edge-subtiles of 8 per warp, K=128, 2 terms
#pragma unroll 1
        for (int et = 0; et < 4; et++) {
            int e0t = ebase + et * 8;
            float d0 = 0.f, d1 = 0.f, d2 = 0.f, d3 = 0.f;
#pragma unroll
            for (int ks = 0; ks < 8; ks++) {
                int k0 = ks * 16;
                const unsigned* bp = (const unsigned*)(h_s + (e0t + g) * HST + k0 + tig * 2);
                unsigned b0 = bp[0], b1 = bp[4];
                mma16816(d0, d1, d2, d3, ah[ks][0], ah[ks][1], ah[ks][2], ah[ks][3], b0, b1);
                mma16816(d0, d1, d2, d3, al[ks][0], al[ks][1], al[ks][2], al[ks][3], b0, b1);
            }
            int eA = e0t + tig * 2, eB = eA + 1;
            DT[eA * DSTE + m0 + g]     = d0;
            DT[eB * DSTE + m0 + g]     = d1;
            DT[eA * DSTE + m0 + g + 8] = d2;
            DT[eB * DSTE + m0 + g + 8] = d3;
        }
        __syncthreads();

        // fused segmented max: thread = (channel, 16-edge group)
        {
            const int* si = sib[cur];
            int ch = tid & 127;
            int grp = tid >> 7;
            int base = grp * 16;
            int prev = si[base];
            float runmax = DT[base * DSTE + ch];
#pragma unroll
            for (int ii = 1; ii < 16; ii++) {
                int d = si[base + ii];
                float v = DT[(base + ii) * DSTE + ch];
                if (d != prev) {
                    if (prev >= 0) atomicMaxF(agg + (size_t)prev * C + ch, runmax);
                    prev = d;
                    runmax = v;
                } else {
                    runmax = fmaxf(runmax, v);
                }
            }
            if (prev >= 0) atomicMaxF(agg + (size_t)prev * C + ch, runmax);
        }
        __syncthreads();
    }
}

// ---------------- finalize: empty nodes -> 0, +b2, optional relu ---------------
__global__ void finalize_kernel(const float* __restrict__ agg,
                                const float* __restrict__ b2,
                                float* __restrict__ out, int N, int do_relu)
{
    int idx = blockIdx.x * blockDim.x + threadIdx.x;
    if (idx >= N * C) return;
    int c = idx & (C - 1);
    float v = agg[idx];
    float o = isfinite(v) ? (v + b2[c]) : 0.f;
    if (do_relu) o = fmaxf(o, 0.f);
    out[idx] = o;
}

// ---------------- launch -------------------------------------------------------
extern "C" void kernel_launch(void* const* d_in, const int* in_sizes, int n_in,
                              void* d_out, int out_size)
{
    const float* x  = (const float*)d_in[0];
    const int*   ei = (const int*)d_in[1];
    int N = in_sizes[0] / C;
    int E = in_sizes[1] / 2;
    const int* srcp = ei;
    const int* dstp = ei + E;

    float *pq, *aggp, *xcur, *Wc;
    __half *wchi, *wclo, *w2hi, *w2lo;
    int *off, *curp, *bsum, *srcs, *dsts;
    cudaGetSymbolAddress((void**)&pq,   g_pq);
    cudaGetSymbolAddress((void**)&aggp, g_agg);
    cudaGetSymbolAddress((void**)&xcur, g_x);
    cudaGetSymbolAddress((void**)&Wc,   g_Wc);
    cudaGetSymbolAddress((void**)&wchi, g_wchi);
    cudaGetSymbolAddress((void**)&wclo, g_wclo);
    cudaGetSymbolAddress((void**)&w2hi, g_w2hi);
    cudaGetSymbolAddress((void**)&w2lo, g_w2lo);
    cudaGetSymbolAddress((void**)&off,  g_off);
    cudaGetSymbolAddress((void**)&curp, g_cur);
    cudaGetSymbolAddress((void**)&bsum, g_bsum);
    cudaGetSymbolAddress((void**)&srcs, g_srcs);
    cudaGetSymbolAddress((void**)&dsts, g_dsts);

    // ---- sort edges by dst (once; reused by all 3 layers) ----
    int nscan = N + 1;
    int nb = (nscan + 1023) / 1024;
    cudaMemsetAsync(off, 0, (size_t)(N + 1) * sizeof(int));
    hist_kernel<<<(E + 255) / 256, 256>>>(dstp, off, E);
    scan1_kernel<<<nb, 1024>>>(off, bsum, nscan);
    scan2_kernel<<<1, 1>>>(bsum, nb);
    scan3_kernel<<<nb, 1024>>>(off, bsum, curp, nscan, N);
    scatter_kernel<<<(E + 255) / 256, 256>>>(srcp, dstp, curp, srcs, dsts, E);

    const size_t SMEM_E = (size_t)(TE2 * DSTE) * sizeof(float)        // DT
                        + (size_t)(TE2 * HST) * sizeof(__half)        // h
                        + (size_t)(2 * 128 * 128) * sizeof(float)     // 2 stage bufs
                        + 2 * TE2 * sizeof(int);                      // sidx
    cudaFuncSetAttribute(edge_fused_kernel, cudaFuncAttributeMaxDynamicSharedMemorySize, (int)SMEM_E);
    const size_t SMEM_N = (size_t)(2 * 128 * HST) * sizeof(__half);
    cudaFuncSetAttribute(node_mma_kernel, cudaFuncAttributeMaxDynamicSharedMemorySize, (int)SMEM_N);

    const float* Ws[3][4] = {
        {(const float*)d_in[2],  (const float*)d_in[3],  (const float*)d_in[4],  (const float*)d_in[5]},
        {(const float*)d_in[6],  (const float*)d_in[7],  (const float*)d_in[8],  (const float*)d_in[9]},
        {(const float*)d_in[10], (const float*)d_in[11], (const float*)d_in[12], (const float*)d_in[13]},
    };

    const float* xin = x;
    for (int l = 0; l < 3; l++) {
        const float* W1 = Ws[l][0];
        const float* b1 = Ws[l][1];
        const float* W2 = Ws[l][2];
        const float* b2 = Ws[l][3];
        float* xout = (l == 2) ? (float*)d_out : xcur;

        prep_kernel<<<C, 256>>>(W1, Wc);
        wcsplit_kernel<<<256, C>>>(Wc, wchi, wclo);
        w2split_kernel<<<C, C>>>(W2, w2hi, w2lo);
        node_mma_kernel<<<(N + 127) / 128, 512, SMEM_N>>>(xin, wchi, wclo, b1, pq, N);
        cudaMemsetAsync(aggp, 0xFF, (size_t)N * C * sizeof(float));
        edge_fused_kernel<<<148, 512, SMEM_E>>>(pq, srcs, dsts, w2hi, w2lo, aggp, E);
        finalize_kernel<<<(N * C + 255) / 256, 256>>>(aggp, b2, xout, N, (l < 2) ? 1 : 0);

        xin = xcur;
    }
}

// round 11
// speedup vs baseline: 3.2484x; 1.1480x over previous
#include <cuda_runtime.h>
#include <cuda_fp16.h>
#include <math.h>

#define N_NODES 50000
#define N_EDGES 800000
#define C 128
#define TE2 64           // edge tile (edges)
#define HST 136          // h tile stride (halfs): conflict-free B-frag LDS
#define DSTE 132         // D tile stride (floats), edge-major [e][ch]

// ---------------- scratch (static device globals; no allocations) -------------
__device__ __half g_pq[(size_t)N_NODES * 256];     // [N][256] fp16: p (+b1) | q
__device__ float g_agg[(size_t)N_NODES * C];       // max-aggregation buffer
__device__ float g_x[(size_t)N_NODES * C];         // inter-layer node features
__device__ float g_Wc[C * 256];                    // node-gemm combined W1 (fp32)
__device__ __half g_wchi[256 * C];                 // Wc^T hi plane [out][k]
__device__ __half g_wclo[256 * C];                 // Wc^T lo plane [out][k]
__device__ __half g_w2hi[C * C];                   // W2^T hi plane [n][k]
__device__ __half g_w2lo[C * C];                   // W2^T lo plane [n][k]
__device__ int g_off[N_NODES + 1];                 // CSR row pointers (by dst)
__device__ int g_cur[N_NODES];                     // scatter cursors
__device__ int g_bsum[64];                         // scan block sums
__device__ int g_srcs[N_EDGES];                    // src sorted by dst
__device__ int g_dsts[N_EDGES];                    // dst sorted (ascending)

// ---------------- float atomic max (signed-max / unsigned-min trick) ----------
__device__ __forceinline__ void atomicMaxF(float* a, float v) {
    if (v >= 0.0f) atomicMax((int*)a, __float_as_int(v));
    else           atomicMin((unsigned int*)a, __float_as_uint(v));
}

// ---------------- HMMA m16n8k16 fp16 ------------------------------------------
__device__ __forceinline__ void mma16816(float& d0, float& d1, float& d2, float& d3,
                                         unsigned a0, unsigned a1, unsigned a2, unsigned a3,
                                         unsigned b0, unsigned b1)
{
    asm volatile(
        "mma.sync.aligned.m16n8k16.row.col.f32.f16.f16.f32 "
        "{%0,%1,%2,%3},{%4,%5,%6,%7},{%8,%9},{%0,%1,%2,%3};\n"
        : "+f"(d0), "+f"(d1), "+f"(d2), "+f"(d3)
        : "r"(a0), "r"(a1), "r"(a2), "r"(a3), "r"(b0), "r"(b1));
}

// ---------------- cp.async helpers ---------------------------------------------
__device__ __forceinline__ void cpasync16(unsigned saddr, const void* gptr) {
    asm volatile("cp.async.cg.shared.global [%0], [%1], 16;\n" :: "r"(saddr), "l"(gptr));
}
__device__ __forceinline__ void cpcommit() { asm volatile("cp.async.commit_group;\n"); }
__device__ __forceinline__ void cpwait1()  { asm volatile("cp.async.wait_group 1;\n"); }

// ---------------- A-fragment preload (W^T hi/lo, 8 k-steps) --------------------
// i00 = row*64 + k0/2 + tig  (tig term is load-bearing: per-lane k offset)
__device__ __forceinline__ void load_a_frags(const __half* Whi, const __half* Wlo,
                                             int row, int tig,
                                             unsigned ah[8][4], unsigned al[8][4])
{
    const unsigned* Hp = (const unsigned*)Whi;
    const unsigned* Lp = (const unsigned*)Wlo;
#pragma unroll
    for (int ks = 0; ks < 8; ks++) {
        int k0 = ks * 16;
        int i00 = row * (C / 2) + (k0 >> 1) + tig;
        ah[ks][0] = Hp[i00];
        ah[ks][1] = Hp[i00 + 8 * (C / 2)];
        ah[ks][2] = Hp[i00 + 4];
        ah[ks][3] = Hp[i00 + 8 * (C / 2) + 4];
        al[ks][0] = Lp[i00];
        al[ks][1] = Lp[i00 + 8 * (C / 2)];
        al[ks][2] = Lp[i00 + 4];
        al[ks][3] = Lp[i00 + 8 * (C / 2) + 4];
    }
}

// ---------------- sort-by-dst preprocessing ------------------------------------
__global__ void hist_kernel(const int* __restrict__ dst, int* __restrict__ off, int E) {
    int e = blockIdx.x * blockDim.x + threadIdx.x;
    if (e < E) atomicAdd(&off[dst[e] + 1], 1);
}

__global__ void scan1_kernel(int* __restrict__ a, int* __restrict__ bsum, int n) {
    __shared__ int s[1024];
    int i = blockIdx.x * 1024 + threadIdx.x;
    int v = (i < n) ? a[i] : 0;
    s[threadIdx.x] = v;
    __syncthreads();
    for (int d = 1; d < 1024; d <<= 1) {
        int t = (threadIdx.x >= d) ? s[threadIdx.x - d] : 0;
        __syncthreads();
        s[threadIdx.x] += t;
        __syncthreads();
    }
    if (i < n) a[i] = s[threadIdx.x];
    if (threadIdx.x == 1023) bsum[blockIdx.x] = s[1023];
}

__global__ void scan2_kernel(int* __restrict__ bsum, int nb) {
    int acc = 0;
    for (int i = 0; i < nb; i++) { int t = bsum[i]; bsum[i] = acc; acc += t; }
}

__global__ void scan3_kernel(int* __restrict__ a, const int* __restrict__ bsum,
                             int* __restrict__ cur, int n, int N) {
    int i = blockIdx.x * 1024 + threadIdx.x;
    if (i < n) {
        int v = a[i] + bsum[blockIdx.x];
        a[i] = v;
        if (i < N) cur[i] = v;
    }
}

__global__ void scatter_kernel(const int* __restrict__ src, const int* __restrict__ dst,
                               int* __restrict__ cur, int* __restrict__ ssrc,
                               int* __restrict__ sdst, int E) {
    int e = blockIdx.x * blockDim.x + threadIdx.x;
    if (e < E) {
        int d = dst[e];
        int pos = atomicAdd(&cur[d], 1);
        sdst[pos] = d;
        ssrc[pos] = src[e];
    }
}

// ---------------- prep: Wc from W1 (fp32) --------------------------------------
__global__ void prep_kernel(const float* __restrict__ W1, float* __restrict__ Wc) {
    int k = blockIdx.x;
    int j = threadIdx.x;
    if (j < C) Wc[k * 256 + j] = W1[k * C + j] - W1[(C + k) * C + j];
    else       Wc[k * 256 + j] = W1[(C + k) * C + (j - C)];
}

// ---------------- prep: split Wc^T into fp16 hi/lo -----------------------------
__global__ void wcsplit_kernel(const float* __restrict__ Wc,
                               __half* __restrict__ hi, __half* __restrict__ lo) {
    int j = blockIdx.x;   // out channel 0..255
    int k = threadIdx.x;  // in channel 0..127
    float w = Wc[k * 256 + j];
    __half h = __float2half_rn(w);
    hi[j * C + k] = h;
    lo[j * C + k] = __float2half_rn(w - __half2float(h));
}

// ---------------- prep: split W2^T into fp16 hi/lo -----------------------------
__global__ void w2split_kernel(const float* __restrict__ W2,
                               __half* __restrict__ hi, __half* __restrict__ lo) {
    int n = blockIdx.x;
    int k = threadIdx.x;
    float w = W2[k * C + n];
    __half h = __float2half_rn(w);
    hi[n * C + k] = h;
    lo[n * C + k] = __float2half_rn(w - __half2float(h));
}

// ---------------- node GEMM (tensor, 3-term split): pq = fp16(x @ Wc + b1) -----
__global__ void __launch_bounds__(512, 1) node_mma_kernel(
    const float* __restrict__ x,
    const __half* __restrict__ Whi, const __half* __restrict__ Wlo,
    const float* __restrict__ b1, __half* __restrict__ pq, int N)
{
    extern __shared__ char sm[];
    __half* xh = (__half*)sm;          // [128][HST]
    __half* xl = xh + 128 * HST;       // [128][HST]

    int tid = threadIdx.x;
    int wid = tid >> 5, lane = tid & 31;
    int g = lane >> 2, tig = lane & 3;
    int m0 = wid * 16;

    unsigned ah[8][4], al[8][4];
    load_a_frags(Whi, Wlo, m0 + g, tig, ah, al);

    float bias0 = (m0 + g < C) ? b1[m0 + g] : 0.f;
    float bias1 = (m0 + g + 8 < C) ? b1[m0 + g + 8] : 0.f;

    int n0 = blockIdx.x * 128;

    {
        int e = tid >> 2;
        int part = tid & 3;
        int node = n0 + e;
        const float4* xr = (const float4*)(x + (size_t)node * C + part * 32);
        unsigned* xhp = (unsigned*)(xh + e * HST + part * 32);
        unsigned* xlp = (unsigned*)(xl + e * HST + part * 32);
#pragma unroll
        for (int i = 0; i < 8; i++) {
            float4 v = (node < N) ? xr[i] : make_float4(0.f, 0.f, 0.f, 0.f);
            __half2 hA = __floats2half2_rn(v.x, v.y);
            __half2 hB = __floats2half2_rn(v.z, v.w);
            __half2 lA = __floats2half2_rn(v.x - __half2float(hA.x), v.y - __half2float(hA.y));
            __half2 lB = __floats2half2_rn(v.z - __half2float(hB.x), v.w - __half2float(hB.y));
            xhp[i * 2 + 0] = *(unsigned*)&hA;
            xhp[i * 2 + 1] = *(unsigned*)&hB;
            xlp[i * 2 + 0] = *(unsigned*)&lA;
            xlp[i * 2 + 1] = *(unsigned*)&lB;
        }
    }
    __syncthreads();

#pragma unroll 1
    for (int et = 0; et < 16; et++) {
        int e0t = et * 8;
        float d0 = 0.f, d1 = 0.f, d2 = 0.f, d3 = 0.f;
#pragma unroll
        for (int ks = 0; ks < 8; ks++) {
            int k0 = ks * 16;
            const unsigned* bhp = (const unsigned*)(xh + (e0t + g) * HST + k0 + tig * 2);
            const unsigned* blp = (const unsigned*)(xl + (e0t + g) * HST + k0 + tig * 2);
            unsigned bh0 = bhp[0], bh1 = bhp[4];
            unsigned bl0 = blp[0], bl1 = blp[4];
            mma16816(d0, d1, d2, d3, ah[ks][0], ah[ks][1], ah[ks][2], ah[ks][3], bh0, bh1);
            mma16816(d0, d1, d2, d3, ah[ks][0], ah[ks][1], ah[ks][2], ah[ks][3], bl0, bl1);
            mma16816(d0, d1, d2, d3, al[ks][0], al[ks][1], al[ks][2], al[ks][3], bh0, bh1);
        }
        int eA = n0 + e0t + tig * 2;
        int eB = eA + 1;
        if (eA < N) {
            pq[(size_t)eA * 256 + m0 + g]     = __float2half_rn(d0 + bias0);
            pq[(size_t)eA * 256 + m0 + g + 8] = __float2half_rn(d2 + bias1);
        }
        if (eB < N) {
            pq[(size_t)eB * 256 + m0 + g]     = __float2half_rn(d1 + bias0);
            pq[(size_t)eB * 256 + m0 + g + 8] = __float2half_rn(d3 + bias1);
        }
    }
}

// ---------------- fused edge kernel: stage fp16 pq rows -> h -> GEMM -> segmax --
// 512 threads / 16 warps, 1 CTA/SM, TE2=64 edges per tile.
// Stage: 128 fp16 rows (64 p[dst] + 64 q[src]) x 256B, XOR-swizzled 16B quads.
__global__ void __launch_bounds__(512, 1) edge_fused_kernel(
    const __half* __restrict__ pq,
    const int* __restrict__ srcs, const int* __restrict__ dsts,
    const __half* __restrict__ W2hi, const __half* __restrict__ W2lo,
    float* __restrict__ agg, int E)
{
    extern __shared__ char smraw[];
    float* DT = (float*)smraw;                          // [TE2][DSTE] 33792B
    __half* h_s = (__half*)(DT + TE2 * DSTE);           // [TE2][HST] 17408B
    __half* stage0 = h_s + TE2 * HST;                   // 128 rows x 16 quads x 16B
    __half* stage1 = stage0 + 128 * 128;                // (32768B each)
    int* sidx0 = (int*)(stage1 + 128 * 128);            // [TE2]
    int* sidx1 = sidx0 + TE2;

    int tid = threadIdx.x;
    int wid = tid >> 5, lane = tid & 31;
    int g = lane >> 2, tig = lane & 3;
    int m0 = (wid & 7) * 16;
    int ebase = (wid >> 3) * 32;

    const __half* stg[2] = {stage0, stage1};
    int* sib[2] = {sidx0, sidx1};
    unsigned st_s[2] = {(unsigned)__cvta_generic_to_shared(stage0),
                        (unsigned)__cvta_generic_to_shared(stage1)};
    unsigned si_s[2] = {(unsigned)__cvta_generic_to_shared(sidx0),
                        (unsigned)__cvta_generic_to_shared(sidx1)};

    unsigned ah[8][4], al[8][4];
    load_a_frags(W2hi, W2lo, m0 + g, tig, ah, al);

    int ntiles = (E + TE2 - 1) / TE2;

    // stage loader: 4 passes, 16 threads per row (16 x 16B quads), swizzled slots
    auto load_tile = [&](int tile, int b) {
        int e0 = tile * TE2;
        int c = tid & 15;
#pragma unroll
        for (int pass = 0; pass < 4; pass++) {
            int row = pass * 32 + (tid >> 4);        // 0..127
            int er = row & 63;
            int ego = e0 + er;
            if (ego > E - 1) ego = E - 1;
            int node = (row < 64) ? __ldg(dsts + ego) : __ldg(srcs + ego);
            const char* gsrc = (const char*)(pq + (size_t)node * 256 + ((row < 64) ? 0 : C))
                             + c * 16;
            unsigned slot = (unsigned)(row * 16 + (c ^ (row & 7)));
            cpasync16(st_s[b] + slot * 16, gsrc);
        }
        if (tid < TE2 / 4) {
            int o = tid * 4;
            if (e0 + o + 3 < E) {
                cpasync16(si_s[b] + o * 4, dsts + e0 + o);
            } else {
                for (int j = 0; j < 4; j++)
                    sib[b][o + j] = (e0 + o + j < E) ? dsts[e0 + o + j] : -1;
            }
        }
        cpcommit();
    };

    if (blockIdx.x < ntiles) load_tile(blockIdx.x, 0); else cpcommit();

    int i = 0;
    for (int tile = blockIdx.x; tile < ntiles; tile += gridDim.x, i++) {
        int cur = i & 1;
        int nt = tile + gridDim.x;
        if (nt < ntiles) load_tile(nt, cur ^ 1);
        else cpcommit();
        cpwait1();
        __syncthreads();

        // convert: h[e][ch] = relu(p16 + q16); fp16 add (correctly rounded)
        {
            int e = tid >> 3;
            int cb = tid & 7;
            const uint4* stp = (const uint4*)stg[cur];
            __half* hrow = h_s + e * HST;
            int sw = e & 7;
            const __half2 z2 = __floats2half2_rn(0.f, 0.f);
#pragma unroll
            for (int j = 0; j < 2; j++) {
                int c = cb + 8 * j;   // quad index 0..15
                uint4 pv = stp[e * 16 + (c ^ sw)];
                uint4 qv = stp[(64 + e) * 16 + (c ^ sw)];
                __half2* p2 = (__half2*)&pv;
                __half2* q2 = (__half2*)&qv;
                uint4 out;
                __half2* o2 = (__half2*)&out;
#pragma unroll
                for (int k = 0; k < 4; k++)
                    o2[k] = __hmax2(__hadd2(p2[k], q2[k]), z2);
                *(uint4*)(hrow + c * 8) = out;
            }
        }
        __syncthreads();

        // MMA: 4 edge-subtiles of 8 per warp, K=128, 2 terms
#pragma unroll 1
        for (int et = 0; et < 4; et++) {
            int e0t = ebase + et * 8;
            float d0 = 0.f, d1 = 0.f, d2 = 0.f, d3 = 0.f;
#pragma unroll
            for (int ks = 0; ks < 8; ks++) {
                int k0 = ks * 16;
                const unsigned* bp = (const unsigned*)(h_s + (e0t + g) * HST + k0 + tig * 2);
                unsigned b0 = bp[0], b1 = bp[4];
                mma16816(d0, d1, d2, d3, ah[ks][0], ah[ks][1], ah[ks][2], ah[ks][3], b0, b1);
                mma16816(d0, d1, d2, d3, al[ks][0], al[ks][1], al[ks][2], al[ks][3], b0, b1);
            }
            int eA = e0t + tig * 2, eB = eA + 1;
            DT[eA * DSTE + m0 + g]     = d0;
            DT[eB * DSTE + m0 + g]     = d1;
            DT[eA * DSTE + m0 + g + 8] = d2;
            DT[eB * DSTE + m0 + g + 8] = d3;
        }
        __syncthreads();

        // fused segmented max: thread = (channel, 16-edge group)
        {
            const int* si = sib[cur];
            int ch = tid & 127;
            int grp = tid >> 7;
            int base = grp * 16;
            int prev = si[base];
            float runmax = DT[base * DSTE + ch];
#pragma unroll
            for (int ii = 1; ii < 16; ii++) {
                int d = si[base + ii];
                float v = DT[(base + ii) * DSTE + ch];
                if (d != prev) {
                    if (prev >= 0) atomicMaxF(agg + (size_t)prev * C + ch, runmax);
                    prev = d;
                    runmax = v;
                } else {
                    runmax = fmaxf(runmax, v);
                }
            }
            if (prev >= 0) atomicMaxF(agg + (size_t)prev * C + ch, runmax);
        }
        __syncthreads();
    }
}

// ---------------- finalize: empty nodes -> 0, +b2, optional relu ---------------
__global__ void finalize_kernel(const float* __restrict__ agg,
                                const float* __restrict__ b2,
                                float* __restrict__ out, int N, int do_relu)
{
    int idx = blockIdx.x * blockDim.x + threadIdx.x;
    if (idx >= N * C) return;
    int c = idx & (C - 1);
    float v = agg[idx];
    float o = isfinite(v) ? (v + b2[c]) : 0.f;
    if (do_relu) o = fmaxf(o, 0.f);
    out[idx] = o;
}

// ---------------- launch -------------------------------------------------------
extern "C" void kernel_launch(void* const* d_in, const int* in_sizes, int n_in,
                              void* d_out, int out_size)
{
    const float* x  = (const float*)d_in[0];
    const int*   ei = (const int*)d_in[1];
    int N = in_sizes[0] / C;
    int E = in_sizes[1] / 2;
    const int* srcp = ei;
    const int* dstp = ei + E;

    float *aggp, *xcur, *Wc;
    __half *pq, *wchi, *wclo, *w2hi, *w2lo;
    int *off, *curp, *bsum, *srcs, *dsts;
    cudaGetSymbolAddress((void**)&pq,   g_pq);
    cudaGetSymbolAddress((void**)&aggp, g_agg);
    cudaGetSymbolAddress((void**)&xcur, g_x);
    cudaGetSymbolAddress((void**)&Wc,   g_Wc);
    cudaGetSymbolAddress((void**)&wchi, g_wchi);
    cudaGetSymbolAddress((void**)&wclo, g_wclo);
    cudaGetSymbolAddress((void**)&w2hi, g_w2hi);
    cudaGetSymbolAddress((void**)&w2lo, g_w2lo);
    cudaGetSymbolAddress((void**)&off,  g_off);
    cudaGetSymbolAddress((void**)&curp, g_cur);
    cudaGetSymbolAddress((void**)&bsum, g_bsum);
    cudaGetSymbolAddress((void**)&srcs, g_srcs);
    cudaGetSymbolAddress((void**)&dsts, g_dsts);

    // ---- sort edges by dst (once; reused by all 3 layers) ----
    int nscan = N + 1;
    int nb = (nscan + 1023) / 1024;
    cudaMemsetAsync(off, 0, (size_t)(N + 1) * sizeof(int));
    hist_kernel<<<(E + 255) / 256, 256>>>(dstp, off, E);
    scan1_kernel<<<nb, 1024>>>(off, bsum, nscan);
    scan2_kernel<<<1, 1>>>(bsum, nb);
    scan3_kernel<<<nb, 1024>>>(off, bsum, curp, nscan, N);
    scatter_kernel<<<(E + 255) / 256, 256>>>(srcp, dstp, curp, srcs, dsts, E);

    const size_t SMEM_E = (size_t)(TE2 * DSTE) * sizeof(float)        // DT
                        + (size_t)(TE2 * HST) * sizeof(__half)        // h
                        + (size_t)(2 * 128 * 128) * sizeof(__half)    // 2 stage bufs
                        + 2 * TE2 * sizeof(int);                      // sidx
    cudaFuncSetAttribute(edge_fused_kernel, cudaFuncAttributeMaxDynamicSharedMemorySize, (int)SMEM_E);
    const size_t SMEM_N = (size_t)(2 * 128 * HST) * sizeof(__half);
    cudaFuncSetAttribute(node_mma_kernel, cudaFuncAttributeMaxDynamicSharedMemorySize, (int)SMEM_N);

    const float* Ws[3][4] = {
        {(const float*)d_in[2],  (const float*)d_in[3],  (const float*)d_in[4],  (const float*)d_in[5]},
        {(const float*)d_in[6],  (const float*)d_in[7],  (const float*)d_in[8],  (const float*)d_in[9]},
        {(const float*)d_in[10], (const float*)d_in[11], (const float*)d_in[12], (const float*)d_in[13]},
    };

    const float* xin = x;
    for (int l = 0; l < 3; l++) {
        const float* W1 = Ws[l][0];
        const float* b1 = Ws[l][1];
        const float* W2 = Ws[l][2];
        const float* b2 = Ws[l][3];
        float* xout = (l == 2) ? (float*)d_out : xcur;

        prep_kernel<<<C, 256>>>(W1, Wc);
        wcsplit_kernel<<<256, C>>>(Wc, wchi, wclo);
        w2split_kernel<<<C, C>>>(W2, w2hi, w2lo);
        node_mma_kernel<<<(N + 127) / 128, 512, SMEM_N>>>(xin, wchi, wclo, b1, pq, N);
        cudaMemsetAsync(aggp, 0xFF, (size_t)N * C * sizeof(float));
        edge_fused_kernel<<<148, 512, SMEM_E>>>(pq, srcs, dsts, w2hi, w2lo, aggp, E);
        finalize_kernel<<<(N * C + 255) / 256, 256>>>(aggp, b2, xout, N, (l < 2) ? 1 : 0);

        xin = xcur;
    }
}

// round 12
// speedup vs baseline: 3.3065x; 1.0179x over previous
#include <cuda_runtime.h>
#include <cuda_fp16.h>
#include <math.h>

#define N_NODES 50000
#define N_EDGES 800000
#define C 128
#define TE2 64           // edge tile (edges)
#define HST 136          // h tile stride (halfs): conflict-free B-frag LDS
#define DSTE 132         // D tile stride (floats), edge-major [e][ch]

// ---------------- scratch (static device globals; no allocations) -------------
__device__ __half g_pq[(size_t)N_NODES * 256];     // [N][256] fp16: p (+b1) | q
__device__ float g_agg[(size_t)N_NODES * C];       // max-aggregation buffer
__device__ float g_x[(size_t)N_NODES * C];         // inter-layer node features
__device__ float g_Wc[C * 256];                    // node-gemm combined W1 (fp32)
__device__ __half g_wchi[256 * C];                 // Wc^T hi plane [out][k]
__device__ __half g_wclo[256 * C];                 // Wc^T lo plane [out][k]
__device__ __half g_w2hi[C * C];                   // W2^T hi plane [n][k]
__device__ __half g_w2lo[C * C];                   // W2^T lo plane [n][k]
__device__ int g_off[N_NODES + 1];                 // CSR row pointers (by dst)
__device__ int g_cur[N_NODES];                     // scatter cursors
__device__ int g_bsum[64];                         // scan block sums
__device__ int g_srcs[N_EDGES];                    // src sorted by dst
__device__ int g_dsts[N_EDGES];                    // dst sorted (ascending)

// ---------------- float atomic max (signed-max / unsigned-min trick) ----------
__device__ __forceinline__ void atomicMaxF(float* a, float v) {
    if (v >= 0.0f) atomicMax((int*)a, __float_as_int(v));
    else           atomicMin((unsigned int*)a, __float_as_uint(v));
}

// ---------------- HMMA m16n8k16 fp16 ------------------------------------------
__device__ __forceinline__ void mma16816(float& d0, float& d1, float& d2, float& d3,
                                         unsigned a0, unsigned a1, unsigned a2, unsigned a3,
                                         unsigned b0, unsigned b1)
{
    asm volatile(
        "mma.sync.aligned.m16n8k16.row.col.f32.f16.f16.f32 "
        "{%0,%1,%2,%3},{%4,%5,%6,%7},{%8,%9},{%0,%1,%2,%3};\n"
        : "+f"(d0), "+f"(d1), "+f"(d2), "+f"(d3)
        : "r"(a0), "r"(a1), "r"(a2), "r"(a3), "r"(b0), "r"(b1));
}

// ---------------- cp.async helpers ---------------------------------------------
__device__ __forceinline__ void cpasync16(unsigned saddr, const void* gptr) {
    asm volatile("cp.async.cg.shared.global [%0], [%1], 16;\n" :: "r"(saddr), "l"(gptr));
}
__device__ __forceinline__ void cpcommit() { asm volatile("cp.async.commit_group;\n"); }
__device__ __forceinline__ void cpwait1()  { asm volatile("cp.async.wait_group 1;\n"); }

// ---------------- A-fragment preload (W^T hi/lo, 8 k-steps) --------------------
// i00 = row*64 + k0/2 + tig  (tig term is load-bearing: per-lane k offset)
__device__ __forceinline__ void load_a_frags(const __half* Whi, const __half* Wlo,
                                             int row, int tig,
                                             unsigned ah[8][4], unsigned al[8][4])
{
    const unsigned* Hp = (const unsigned*)Whi;
    const unsigned* Lp = (const unsigned*)Wlo;
#pragma unroll
    for (int ks = 0; ks < 8; ks++) {
        int k0 = ks * 16;
        int i00 = row * (C / 2) + (k0 >> 1) + tig;
        ah[ks][0] = Hp[i00];
        ah[ks][1] = Hp[i00 + 8 * (C / 2)];
        ah[ks][2] = Hp[i00 + 4];
        ah[ks][3] = Hp[i00 + 8 * (C / 2) + 4];
        al[ks][0] = Lp[i00];
        al[ks][1] = Lp[i00 + 8 * (C / 2)];
        al[ks][2] = Lp[i00 + 4];
        al[ks][3] = Lp[i00 + 8 * (C / 2) + 4];
    }
}

// ---------------- sort-by-dst preprocessing ------------------------------------
__global__ void hist_kernel(const int* __restrict__ dst, int* __restrict__ off, int E) {
    int e = blockIdx.x * blockDim.x + threadIdx.x;
    if (e < E) atomicAdd(&off[dst[e] + 1], 1);
}

__global__ void scan1_kernel(int* __restrict__ a, int* __restrict__ bsum, int n) {
    __shared__ int s[1024];
    int i = blockIdx.x * 1024 + threadIdx.x;
    int v = (i < n) ? a[i] : 0;
    s[threadIdx.x] = v;
    __syncthreads();
    for (int d = 1; d < 1024; d <<= 1) {
        int t = (threadIdx.x >= d) ? s[threadIdx.x - d] : 0;
        __syncthreads();
        s[threadIdx.x] += t;
        __syncthreads();
    }
    if (i < n) a[i] = s[threadIdx.x];
    if (threadIdx.x == 1023) bsum[blockIdx.x] = s[1023];
}

__global__ void scan2_kernel(int* __restrict__ bsum, int nb) {
    int acc = 0;
    for (int i = 0; i < nb; i++) { int t = bsum[i]; bsum[i] = acc; acc += t; }
}

__global__ void scan3_kernel(int* __restrict__ a, const int* __restrict__ bsum,
                             int* __restrict__ cur, int n, int N) {
    int i = blockIdx.x * 1024 + threadIdx.x;
    if (i < n) {
        int v = a[i] + bsum[blockIdx.x];
        a[i] = v;
        if (i < N) cur[i] = v;
    }
}

__global__ void scatter_kernel(const int* __restrict__ src, const int* __restrict__ dst,
                               int* __restrict__ cur, int* __restrict__ ssrc,
                               int* __restrict__ sdst, int E) {
    int e = blockIdx.x * blockDim.x + threadIdx.x;
    if (e < E) {
        int d = dst[e];
        int pos = atomicAdd(&cur[d], 1);
        sdst[pos] = d;
        ssrc[pos] = src[e];
    }
}

// ---------------- prep: Wc from W1 (fp32) --------------------------------------
__global__ void prep_kernel(const float* __restrict__ W1, float* __restrict__ Wc) {
    int k = blockIdx.x;
    int j = threadIdx.x;
    if (j < C) Wc[k * 256 + j] = W1[k * C + j] - W1[(C + k) * C + j];
    else       Wc[k * 256 + j] = W1[(C + k) * C + (j - C)];
}

// ---------------- prep: split Wc^T into fp16 hi/lo -----------------------------
__global__ void wcsplit_kernel(const float* __restrict__ Wc,
                               __half* __restrict__ hi, __half* __restrict__ lo) {
    int j = blockIdx.x;   // out channel 0..255
    int k = threadIdx.x;  // in channel 0..127
    float w = Wc[k * 256 + j];
    __half h = __float2half_rn(w);
    hi[j * C + k] = h;
    lo[j * C + k] = __float2half_rn(w - __half2float(h));
}

// ---------------- prep: split W2^T into fp16 hi/lo -----------------------------
__global__ void w2split_kernel(const float* __restrict__ W2,
                               __half* __restrict__ hi, __half* __restrict__ lo) {
    int n = blockIdx.x;
    int k = threadIdx.x;
    float w = W2[k * C + n];
    __half h = __float2half_rn(w);
    hi[n * C + k] = h;
    lo[n * C + k] = __float2half_rn(w - __half2float(h));
}

// ---------------- node GEMM (tensor, 3-term split): pq = fp16(x @ Wc + b1) -----
__global__ void __launch_bounds__(512, 1) node_mma_kernel(
    const float* __restrict__ x,
    const __half* __restrict__ Whi, const __half* __restrict__ Wlo,
    const float* __restrict__ b1, __half* __restrict__ pq, int N)
{
    extern __shared__ char sm[];
    __half* xh = (__half*)sm;          // [128][HST]
    __half* xl = xh + 128 * HST;       // [128][HST]

    int tid = threadIdx.x;
    int wid = tid >> 5, lane = tid & 31;
    int g = lane >> 2, tig = lane & 3;
    int m0 = wid * 16;

    unsigned ah[8][4], al[8][4];
    load_a_frags(Whi, Wlo, m0 + g, tig, ah, al);

    float bias0 = (m0 + g < C) ? b1[m0 + g] : 0.f;
    float bias1 = (m0 + g + 8 < C) ? b1[m0 + g + 8] : 0.f;

    int n0 = blockIdx.x * 128;

    {
        int e = tid >> 2;
        int part = tid & 3;
        int node = n0 + e;
        const float4* xr = (const float4*)(x + (size_t)node * C + part * 32);
        unsigned* xhp = (unsigned*)(xh + e * HST + part * 32);
        unsigned* xlp = (unsigned*)(xl + e * HST + part * 32);
#pragma unroll
        for (int i = 0; i < 8; i++) {
            float4 v = (node < N) ? xr[i] : make_float4(0.f, 0.f, 0.f, 0.f);
            __half2 hA = __floats2half2_rn(v.x, v.y);
            __half2 hB = __floats2half2_rn(v.z, v.w);
            __half2 lA = __floats2half2_rn(v.x - __half2float(hA.x), v.y - __half2float(hA.y));
            __half2 lB = __floats2half2_rn(v.z - __half2float(hB.x), v.w - __half2float(hB.y));
            xhp[i * 2 + 0] = *(unsigned*)&hA;
            xhp[i * 2 + 1] = *(unsigned*)&hB;
            xlp[i * 2 + 0] = *(unsigned*)&lA;
            xlp[i * 2 + 1] = *(unsigned*)&lB;
        }
    }
    __syncthreads();

#pragma unroll 1
    for (int et = 0; et < 16; et++) {
        int e0t = et * 8;
        float d0 = 0.f, d1 = 0.f, d2 = 0.f, d3 = 0.f;
#pragma unroll
        for (int ks = 0; ks < 8; ks++) {
            int k0 = ks * 16;
            const unsigned* bhp = (const unsigned*)(xh + (e0t + g) * HST + k0 + tig * 2);
            const unsigned* blp = (const unsigned*)(xl + (e0t + g) * HST + k0 + tig * 2);
            unsigned bh0 = bhp[0], bh1 = bhp[4];
            unsigned bl0 = blp[0], bl1 = blp[4];
            mma16816(d0, d1, d2, d3, ah[ks][0], ah[ks][1], ah[ks][2], ah[ks][3], bh0, bh1);
            mma16816(d0, d1, d2, d3, ah[ks][0], ah[ks][1], ah[ks][2], ah[ks][3], bl0, bl1);
            mma16816(d0, d1, d2, d3, al[ks][0], al[ks][1], al[ks][2], al[ks][3], bh0, bh1);
        }
        int eA = n0 + e0t + tig * 2;
        int eB = eA + 1;
        if (eA < N) {
            pq[(size_t)eA * 256 + m0 + g]     = __float2half_rn(d0 + bias0);
            pq[(size_t)eA * 256 + m0 + g + 8] = __float2half_rn(d2 + bias1);
        }
        if (eB < N) {
            pq[(size_t)eB * 256 + m0 + g]     = __float2half_rn(d1 + bias0);
            pq[(size_t)eB * 256 + m0 + g + 8] = __float2half_rn(d3 + bias1);
        }
    }
}

// ---------------- fused edge kernel: dedup-staged pq -> h -> GEMM -> segmax -----
// 512 threads / 16 warps, 1 CTA/SM, TE2=64 edges per tile.
// q rows staged per edge; p rows staged ONCE per dst-run (slot = run start).
// Indices register-prefetched 2 tiles ahead (hides chained LDG off[dst]).
__global__ void __launch_bounds__(512, 1) edge_fused_kernel(
    const __half* __restrict__ pq,
    const int* __restrict__ srcs, const int* __restrict__ dsts,
    const int* __restrict__ off,
    const __half* __restrict__ W2hi, const __half* __restrict__ W2lo,
    float* __restrict__ agg, int E)
{
    extern __shared__ char smraw[];
    float* DT = (float*)smraw;                          // [TE2][DSTE] 33792B
    __half* h_s = (__half*)(DT + TE2 * DSTE);           // [TE2][HST] 17408B
    __half* stage0 = h_s + TE2 * HST;                   // 128 rows x 16 quads x 16B
    __half* stage1 = stage0 + 128 * 128;                // (32768B each)
    int* sidx0 = (int*)(stage1 + 128 * 128);            // [TE2]
    int* sidx1 = sidx0 + TE2;
    int* sps0 = sidx1 + TE2;                            // [TE2] p slot per edge
    int* sps1 = sps0 + TE2;

    int tid = threadIdx.x;
    int wid = tid >> 5, lane = tid & 31;
    int g = lane >> 2, tig = lane & 3;
    int m0 = (wid & 7) * 16;
    int ebase = (wid >> 3) * 32;

    int row = tid >> 3;        // edge within tile this thread helps stage (0..63)
    int cq = tid & 7;          // quad sub-index (2 quads: cq, cq+8)

    const __half* stg[2] = {stage0, stage1};
    int* sib[2] = {sidx0, sidx1};
    int* spsb[2] = {sps0, sps1};
    unsigned st_s[2] = {(unsigned)__cvta_generic_to_shared(stage0),
                        (unsigned)__cvta_generic_to_shared(stage1)};
    unsigned si_s[2] = {(unsigned)__cvta_generic_to_shared(sidx0),
                        (unsigned)__cvta_generic_to_shared(sidx1)};

    unsigned ah[8][4], al[8][4];
    load_a_frags(W2hi, W2lo, m0 + g, tig, ah, al);

    int ntiles = (E + TE2 - 1) / TE2;

    // register prefetch of indices for a tile (chained LDG: dst -> off[dst])
    int pd, ps, po;
    auto prefetch = [&](int tile) {
        int ego = tile * TE2 + row;
        if (ego > E - 1) ego = E - 1;
        pd = __ldg(dsts + ego);
        ps = __ldg(srcs + ego);
        po = __ldg(off + pd);
    };

    // loader consumes prefetched regs; issues ~1100 cp.asyncs (q full, p dedup)
    auto load_tile = [&](int tile, int b) {
        int e0 = tile * TE2;
        // q row (slot 64+row)
        {
            const char* qsrc = (const char*)(pq + (size_t)ps * 256 + C);
            unsigned base = st_s[b] + (unsigned)((64 + row) * 16) * 16;
            int sw = row & 7;
            cpasync16(base + (unsigned)((cq ^ sw) * 16), qsrc + cq * 16);
            cpasync16(base + (unsigned)(((cq + 8) ^ sw) * 16), qsrc + (cq + 8) * 16);
        }
        // p row: only the run-start edge stages it (slot = run start in tile)
        int sp = po - e0;
        if (sp < 0) sp = 0;
        if (row == sp) {
            const char* psrc = (const char*)(pq + (size_t)pd * 256);
            unsigned base = st_s[b] + (unsigned)(sp * 16) * 16;
            int sw = sp & 7;
            cpasync16(base + (unsigned)((cq ^ sw) * 16), psrc + cq * 16);
            cpasync16(base + (unsigned)(((cq + 8) ^ sw) * 16), psrc + (cq + 8) * 16);
        }
        if (cq == 0) spsb[b][row] = sp;        // slot map for convert
        // dst ids for epilogue
        if (tid < TE2 / 4) {
            int o = tid * 4;
            if (e0 + o + 3 < E) {
                cpasync16(si_s[b] + o * 4, dsts + e0 + o);
            } else {
                for (int j = 0; j < 4; j++)
                    sib[b][o + j] = (e0 + o + j < E) ? dsts[e0 + o + j] : -1;
            }
        }
        cpcommit();
    };

    // prologue: indices for tile0, load tile0, indices for tile1
    if (blockIdx.x < ntiles) {
        prefetch(blockIdx.x);
        load_tile(blockIdx.x, 0);
        prefetch(blockIdx.x + gridDim.x < ntiles ? blockIdx.x + gridDim.x : blockIdx.x);
    } else {
        cpcommit();
    }

    int i = 0;
    for (int tile = blockIdx.x; tile < ntiles; tile += gridDim.x, i++) {
        int cur = i & 1;
        int nt = tile + gridDim.x;
        if (nt < ntiles) {
            load_tile(nt, cur ^ 1);
            int nnt = nt + gridDim.x;
            prefetch(nnt < ntiles ? nnt : nt);   // for next iteration's loader
        } else {
            cpcommit();
        }
        cpwait1();
        __syncthreads();

        // convert: h[e][ch] = relu(p16[slot] + q16[e])
        {
            int e = row;
            const uint4* stp = (const uint4*)stg[cur];
            __half* hrow = h_s + e * HST;
            int sp = spsb[cur][e];
            int swp = sp & 7, swq = e & 7;
            const __half2 z2 = __floats2half2_rn(0.f, 0.f);
#pragma unroll
            for (int j = 0; j < 2; j++) {
                int c = cq + 8 * j;   // quad index 0..15
                uint4 pv = stp[sp * 16 + (c ^ swp)];
                uint4 qv = stp[(64 + e) * 16 + (c ^ swq)];
                __half2* p2 = (__half2*)&pv;
                __half2* q2 = (__half2*)&qv;
                uint4 out;
                __half2* o2 = (__half2*)&out;
#pragma unroll
                for (int k = 0; k < 4; k++)
                    o2[k] = __hmax2(__hadd2(p2[k], q2[k]), z2);
                *(uint4*)(hrow + c * 8) = out;
            }
        }
        __syncthreads();

        // MMA: 4 edge-subtiles of 8 per warp, K=128, 2 terms
#pragma unroll 1
        for (int et = 0; et < 4; et++) {
            int e0t = ebase + et * 8;
            float d0 = 0.f, d1 = 0.f, d2 = 0.f, d3 = 0.f;
#pragma unroll
            for (int ks = 0; ks < 8; ks++) {
                int k0 = ks * 16;
                const unsigned* bp = (const unsigned*)(h_s + (e0t + g) * HST + k0 + tig * 2);
                unsigned b0 = bp[0], b1 = bp[4];
                mma16816(d0, d1, d2, d3, ah[ks][0], ah[ks][1], ah[ks][2], ah[ks][3], b0, b1);
                mma16816(d0, d1, d2, d3, al[ks][0], al[ks][1], al[ks][2], al[ks][3], b0, b1);
            }
            int eA = e0t + tig * 2, eB = eA + 1;
            DT[eA * DSTE + m0 + g]     = d0;
            DT[eB * DSTE + m0 + g]     = d1;
            DT[eA * DSTE + m0 + g + 8] = d2;
            DT[eB * DSTE + m0 + g + 8] = d3;
        }
        __syncthreads();

        // fused segmented max: thread = (channel, 16-edge group)
        {
            const int* si = sib[cur];
            int ch = tid & 127;
            int grp = tid >> 7;
            int base = grp * 16;
            int prev = si[base];
            float runmax = DT[base * DSTE + ch];
#pragma unroll
            for (int ii = 1; ii < 16; ii++) {
                int d = si[base + ii];
                float v = DT[(base + ii) * DSTE + ch];
                if (d != prev) {
                    if (prev >= 0) atomicMaxF(agg + (size_t)prev * C + ch, runmax);
                    prev = d;
                    runmax = v;
                } else {
                    runmax = fmaxf(runmax, v);
                }
            }
            if (prev >= 0) atomicMaxF(agg + (size_t)prev * C + ch, runmax);
        }
        __syncthreads();
    }
}

// ---------------- finalize: empty nodes -> 0, +b2, optional relu ---------------
__global__ void finalize_kernel(const float* __restrict__ agg,
                                const float* __restrict__ b2,
                                float* __restrict__ out, int N, int do_relu)
{
    int idx = blockIdx.x * blockDim.x + threadIdx.x;
    if (idx >= N * C) return;
    int c = idx & (C - 1);
    float v = agg[idx];
    float o = isfinite(v) ? (v + b2[c]) : 0.f;
    if (do_relu) o = fmaxf(o, 0.f);
    out[idx] = o;
}

// ---------------- launch -------------------------------------------------------
extern "C" void kernel_launch(void* const* d_in, const int* in_sizes, int n_in,
                              void* d_out, int out_size)
{
    const float* x  = (const float*)d_in[0];
    const int*   ei = (const int*)d_in[1];
    int N = in_sizes[0] / C;
    int E = in_sizes[1] / 2;
    const int* srcp = ei;
    const int* dstp = ei + E;

    float *aggp, *xcur, *Wc;
    __half *pq, *wchi, *wclo, *w2hi, *w2lo;
    int *off, *curp, *bsum, *srcs, *dsts;
    cudaGetSymbolAddress((void**)&pq,   g_pq);
    cudaGetSymbolAddress((void**)&aggp, g_agg);
    cudaGetSymbolAddress((void**)&xcur, g_x);
    cudaGetSymbolAddress((void**)&Wc,   g_Wc);
    cudaGetSymbolAddress((void**)&wchi, g_wchi);
    cudaGetSymbolAddress((void**)&wclo, g_wclo);
    cudaGetSymbolAddress((void**)&w2hi, g_w2hi);
    cudaGetSymbolAddress((void**)&w2lo, g_w2lo);
    cudaGetSymbolAddress((void**)&off,  g_off);
    cudaGetSymbolAddress((void**)&curp, g_cur);
    cudaGetSymbolAddress((void**)&bsum, g_bsum);
    cudaGetSymbolAddress((void**)&srcs, g_srcs);
    cudaGetSymbolAddress((void**)&dsts, g_dsts);

    // ---- sort edges by dst (once; reused by all 3 layers) ----
    int nscan = N + 1;
    int nb = (nscan + 1023) / 1024;
    cudaMemsetAsync(off, 0, (size_t)(N + 1) * sizeof(int));
    hist_kernel<<<(E + 255) / 256, 256>>>(dstp, off, E);
    scan1_kernel<<<nb, 1024>>>(off, bsum, nscan);
    scan2_kernel<<<1, 1>>>(bsum, nb);
    scan3_kernel<<<nb, 1024>>>(off, bsum, curp, nscan, N);
    scatter_kernel<<<(E + 255) / 256, 256>>>(srcp, dstp, curp, srcs, dsts, E);

    const size_t SMEM_E = (size_t)(TE2 * DSTE) * sizeof(float)        // DT
                        + (size_t)(TE2 * HST) * sizeof(__half)        // h
                        + (size_t)(2 * 128 * 128) * sizeof(__half)    // 2 stage bufs
                        + 4 * TE2 * sizeof(int);                      // sidx + sps
    cudaFuncSetAttribute(edge_fused_kernel, cudaFuncAttributeMaxDynamicSharedMemorySize, (int)SMEM_E);
    const size_t SMEM_N = (size_t)(2 * 128 * HST) * sizeof(__half);
    cudaFuncSetAttribute(node_mma_kernel, cudaFuncAttributeMaxDynamicSharedMemorySize, (int)SMEM_N);

    const float* Ws[3][4] = {
        {(const float*)d_in[2],  (const float*)d_in[3],  (const float*)d_in[4],  (const float*)d_in[5]},
        {(const float*)d_in[6],  (const float*)d_in[7],  (const float*)d_in[8],  (const float*)d_in[9]},
        {(const float*)d_in[10], (const float*)d_in[11], (const float*)d_in[12], (const float*)d_in[13]},
    };

    const float* xin = x;
    for (int l = 0; l < 3; l++) {
        const float* W1 = Ws[l][0];
        const float* b1 = Ws[l][1];
        const float* W2 = Ws[l][2];
        const float* b2 = Ws[l][3];
        float* xout = (l == 2) ? (float*)d_out : xcur;

        prep_kernel<<<C, 256>>>(W1, Wc);
        wcsplit_kernel<<<256, C>>>(Wc, wchi, wclo);
        w2split_kernel<<<C, C>>>(W2, w2hi, w2lo);
        node_mma_kernel<<<(N + 127) / 128, 512, SMEM_N>>>(xin, wchi, wclo, b1, pq, N);
        cudaMemsetAsync(aggp, 0xFF, (size_t)N * C * sizeof(float));
        edge_fused_kernel<<<148, 512, SMEM_E>>>(pq, srcs, dsts, off, w2hi, w2lo, aggp, E);
        finalize_kernel<<<(N * C + 255) / 256, 256>>>(aggp, b2, xout, N, (l < 2) ? 1 : 0);

        xin = xcur;
    }
}

// round 13
// speedup vs baseline: 3.4651x; 1.0480x over previous
#include <cuda_runtime.h>
#include <cuda_fp16.h>
#include <math.h>

#define N_NODES 50000
#define N_EDGES 800000
#define C 128
#define TE2 64           // edge tile (edges)
#define HST 136          // h tile stride (halfs): conflict-free B-frag LDS
#define DSTE 132         // D tile stride (floats), edge-major [e][ch]
#define STAGE_B 33792    // stage buffer bytes (>= 64*16*16 staged, == DT bytes)

// ---------------- scratch (static device globals; no allocations) -------------
__device__ __half g_pq[(size_t)N_NODES * 256];     // [N][256] fp16: p (+b1) | q
__device__ float g_agg[(size_t)N_NODES * C];       // max-aggregation buffer
__device__ float g_x[(size_t)N_NODES * C];         // inter-layer node features
__device__ float g_Wc[C * 256];                    // node-gemm combined W1 (fp32)
__device__ __half g_wchi[256 * C];                 // Wc^T hi plane [out][k]
__device__ __half g_wclo[256 * C];                 // Wc^T lo plane [out][k]
__device__ __half g_w2hi[C * C];                   // W2^T hi plane [n][k]
__device__ __half g_w2lo[C * C];                   // W2^T lo plane [n][k]
__device__ int g_off[N_NODES + 1];                 // CSR row pointers (by dst)
__device__ int g_cur[N_NODES];                     // scatter cursors
__device__ int g_bsum[64];                         // scan block sums
__device__ int g_srcs[N_EDGES];                    // src sorted by dst
__device__ int g_dsts[N_EDGES];                    // dst sorted (ascending)

// ---------------- float atomic max (signed-max / unsigned-min trick) ----------
__device__ __forceinline__ void atomicMaxF(float* a, float v) {
    if (v >= 0.0f) atomicMax((int*)a, __float_as_int(v));
    else           atomicMin((unsigned int*)a, __float_as_uint(v));
}

// ---------------- HMMA m16n8k16 fp16 ------------------------------------------
__device__ __forceinline__ void mma16816(float& d0, float& d1, float& d2, float& d3,
                                         unsigned a0, unsigned a1, unsigned a2, unsigned a3,
                                         unsigned b0, unsigned b1)
{
    asm volatile(
        "mma.sync.aligned.m16n8k16.row.col.f32.f16.f16.f32 "
        "{%0,%1,%2,%3},{%4,%5,%6,%7},{%8,%9},{%0,%1,%2,%3};\n"
        : "+f"(d0), "+f"(d1), "+f"(d2), "+f"(d3)
        : "r"(a0), "r"(a1), "r"(a2), "r"(a3), "r"(b0), "r"(b1));
}

// ---------------- cp.async helpers ---------------------------------------------
__device__ __forceinline__ void cpasync16(unsigned saddr, const void* gptr) {
    asm volatile("cp.async.cg.shared.global [%0], [%1], 16;\n" :: "r"(saddr), "l"(gptr));
}
__device__ __forceinline__ void cpcommit() { asm volatile("cp.async.commit_group;\n"); }
__device__ __forceinline__ void cpwait1()  { asm volatile("cp.async.wait_group 1;\n"); }

// ---------------- A-fragment preload (W^T hi/lo, 8 k-steps) --------------------
// i00 = row*64 + k0/2 + tig  (tig term is load-bearing: per-lane k offset)
__device__ __forceinline__ void load_a_frags(const __half* Whi, const __half* Wlo,
                                             int row, int tig,
                                             unsigned ah[8][4], unsigned al[8][4])
{
    const unsigned* Hp = (const unsigned*)Whi;
    const unsigned* Lp = (const unsigned*)Wlo;
#pragma unroll
    for (int ks = 0; ks < 8; ks++) {
        int k0 = ks * 16;
        int i00 = row * (C / 2) + (k0 >> 1) + tig;
        ah[ks][0] = Hp[i00];
        ah[ks][1] = Hp[i00 + 8 * (C / 2)];
        ah[ks][2] = Hp[i00 + 4];
        ah[ks][3] = Hp[i00 + 8 * (C / 2) + 4];
        al[ks][0] = Lp[i00];
        al[ks][1] = Lp[i00 + 8 * (C / 2)];
        al[ks][2] = Lp[i00 + 4];
        al[ks][3] = Lp[i00 + 8 * (C / 2) + 4];
    }
}

// ---------------- sort-by-dst preprocessing ------------------------------------
__global__ void hist_kernel(const int* __restrict__ dst, int* __restrict__ off, int E) {
    int e = blockIdx.x * blockDim.x + threadIdx.x;
    if (e < E) atomicAdd(&off[dst[e] + 1], 1);
}

__global__ void scan1_kernel(int* __restrict__ a, int* __restrict__ bsum, int n) {
    __shared__ int s[1024];
    int i = blockIdx.x * 1024 + threadIdx.x;
    int v = (i < n) ? a[i] : 0;
    s[threadIdx.x] = v;
    __syncthreads();
    for (int d = 1; d < 1024; d <<= 1) {
        int t = (threadIdx.x >= d) ? s[threadIdx.x - d] : 0;
        __syncthreads();
        s[threadIdx.x] += t;
        __syncthreads();
    }
    if (i < n) a[i] = s[threadIdx.x];
    if (threadIdx.x == 1023) bsum[blockIdx.x] = s[1023];
}

__global__ void scan2_kernel(int* __restrict__ bsum, int nb) {
    int acc = 0;
    for (int i = 0; i < nb; i++) { int t = bsum[i]; bsum[i] = acc; acc += t; }
}

__global__ void scan3_kernel(int* __restrict__ a, const int* __restrict__ bsum,
                             int* __restrict__ cur, int n, int N) {
    int i = blockIdx.x * 1024 + threadIdx.x;
    if (i < n) {
        int v = a[i] + bsum[blockIdx.x];
        a[i] = v;
        if (i < N) cur[i] = v;
    }
}

__global__ void scatter_kernel(const int* __restrict__ src, const int* __restrict__ dst,
                               int* __restrict__ cur, int* __restrict__ ssrc,
                               int* __restrict__ sdst, int E) {
    int e = blockIdx.x * blockDim.x + threadIdx.x;
    if (e < E) {
        int d = dst[e];
        int pos = atomicAdd(&cur[d], 1);
        sdst[pos] = d;
        ssrc[pos] = src[e];
    }
}

// ---------------- prep: Wc from W1 (fp32) --------------------------------------
__global__ void prep_kernel(const float* __restrict__ W1, float* __restrict__ Wc) {
    int k = blockIdx.x;
    int j = threadIdx.x;
    if (j < C) Wc[k * 256 + j] = W1[k * C + j] - W1[(C + k) * C + j];
    else       Wc[k * 256 + j] = W1[(C + k) * C + (j - C)];
}

// ---------------- prep: split Wc^T into fp16 hi/lo -----------------------------
__global__ void wcsplit_kernel(const float* __restrict__ Wc,
                               __half* __restrict__ hi, __half* __restrict__ lo) {
    int j = blockIdx.x;   // out channel 0..255
    int k = threadIdx.x;  // in channel 0..127
    float w = Wc[k * 256 + j];
    __half h = __float2half_rn(w);
    hi[j * C + k] = h;
    lo[j * C + k] = __float2half_rn(w - __half2float(h));
}

// ---------------- prep: split W2^T into fp16 hi/lo -----------------------------
__global__ void w2split_kernel(const float* __restrict__ W2,
                               __half* __restrict__ hi, __half* __restrict__ lo) {
    int n = blockIdx.x;
    int k = threadIdx.x;
    float w = W2[k * C + n];
    __half h = __float2half_rn(w);
    hi[n * C + k] = h;
    lo[n * C + k] = __float2half_rn(w - __half2float(h));
}

// ---------------- node GEMM (tensor, 3-term split): pq = fp16(x @ Wc + b1) -----
__global__ void __launch_bounds__(512, 1) node_mma_kernel(
    const float* __restrict__ x,
    const __half* __restrict__ Whi, const __half* __restrict__ Wlo,
    const float* __restrict__ b1, __half* __restrict__ pq, int N)
{
    extern __shared__ char sm[];
    __half* xh = (__half*)sm;          // [128][HST]
    __half* xl = xh + 128 * HST;       // [128][HST]

    int tid = threadIdx.x;
    int wid = tid >> 5, lane = tid & 31;
    int g = lane >> 2, tig = lane & 3;
    int m0 = wid * 16;

    unsigned ah[8][4], al[8][4];
    load_a_frags(Whi, Wlo, m0 + g, tig, ah, al);

    float bias0 = (m0 + g < C) ? b1[m0 + g] : 0.f;
    float bias1 = (m0 + g + 8 < C) ? b1[m0 + g + 8] : 0.f;

    int n0 = blockIdx.x * 128;

    {
        int e = tid >> 2;
        int part = tid & 3;
        int node = n0 + e;
        const float4* xr = (const float4*)(x + (size_t)node * C + part * 32);
        unsigned* xhp = (unsigned*)(xh + e * HST + part * 32);
        unsigned* xlp = (unsigned*)(xl + e * HST + part * 32);
#pragma unroll
        for (int i = 0; i < 8; i++) {
            float4 v = (node < N) ? xr[i] : make_float4(0.f, 0.f, 0.f, 0.f);
            __half2 hA = __floats2half2_rn(v.x, v.y);
            __half2 hB = __floats2half2_rn(v.z, v.w);
            __half2 lA = __floats2half2_rn(v.x - __half2float(hA.x), v.y - __half2float(hA.y));
            __half2 lB = __floats2half2_rn(v.z - __half2float(hB.x), v.w - __half2float(hB.y));
            xhp[i * 2 + 0] = *(unsigned*)&hA;
            xhp[i * 2 + 1] = *(unsigned*)&hB;
            xlp[i * 2 + 0] = *(unsigned*)&lA;
            xlp[i * 2 + 1] = *(unsigned*)&lB;
        }
    }
    __syncthreads();

#pragma unroll 1
    for (int et = 0; et < 16; et++) {
        int e0t = et * 8;
        float d0 = 0.f, d1 = 0.f, d2 = 0.f, d3 = 0.f;
#pragma unroll
        for (int ks = 0; ks < 8; ks++) {
            int k0 = ks * 16;
            const unsigned* bhp = (const unsigned*)(xh + (e0t + g) * HST + k0 + tig * 2);
            const unsigned* blp = (const unsigned*)(xl + (e0t + g) * HST + k0 + tig * 2);
            unsigned bh0 = bhp[0], bh1 = bhp[4];
            unsigned bl0 = blp[0], bl1 = blp[4];
            mma16816(d0, d1, d2, d3, ah[ks][0], ah[ks][1], ah[ks][2], ah[ks][3], bh0, bh1);
            mma16816(d0, d1, d2, d3, ah[ks][0], ah[ks][1], ah[ks][2], ah[ks][3], bl0, bl1);
            mma16816(d0, d1, d2, d3, al[ks][0], al[ks][1], al[ks][2], al[ks][3], bh0, bh1);
        }
        int eA = n0 + e0t + tig * 2;
        int eB = eA + 1;
        if (eA < N) {
            pq[(size_t)eA * 256 + m0 + g]     = __float2half_rn(d0 + bias0);
            pq[(size_t)eA * 256 + m0 + g + 8] = __float2half_rn(d2 + bias1);
        }
        if (eB < N) {
            pq[(size_t)eB * 256 + m0 + g]     = __float2half_rn(d1 + bias0);
            pq[(size_t)eB * 256 + m0 + g + 8] = __float2half_rn(d3 + bias1);
        }
    }
}

// ---------------- fused edge kernel, 2 CTAs/SM, DT aliases dead stage buffer ----
// 256 threads / 8 warps. Warp w: channels w*16..+16, ALL 64 edges (8 subtiles).
// stage[cur] is dead after convert -> MMA writes DT into it (fp32, DSTE=132).
__global__ void __launch_bounds__(256, 2) edge_fused_kernel(
    const __half* __restrict__ pq,
    const int* __restrict__ srcs, const int* __restrict__ dsts,
    const int* __restrict__ off,
    const __half* __restrict__ W2hi, const __half* __restrict__ W2lo,
    float* __restrict__ agg, int E)
{
    extern __shared__ char smraw[];
    __half* h_s = (__half*)smraw;                       // [TE2][HST] 17408B
    char* stage0 = (char*)(h_s + TE2 * HST);            // STAGE_B each; staged rows
    char* stage1 = stage0 + STAGE_B;                    //   + DT alias after convert
    int* sidx0 = (int*)(stage1 + STAGE_B);              // [TE2]
    int* sidx1 = sidx0 + TE2;
    int* sps0 = sidx1 + TE2;                            // [TE2] p slot per edge
    int* sps1 = sps0 + TE2;

    int tid = threadIdx.x;
    int wid = tid >> 5, lane = tid & 31;
    int g = lane >> 2, tig = lane & 3;
    int m0 = wid * 16;

    int row = tid >> 2;        // edge row this thread stages/converts (0..63)
    int q4 = (tid & 3) * 4;    // first of 4 owned quads

    char* stg[2] = {stage0, stage1};
    int* sib[2] = {sidx0, sidx1};
    int* spsb[2] = {sps0, sps1};
    unsigned st_s[2] = {(unsigned)__cvta_generic_to_shared(stage0),
                        (unsigned)__cvta_generic_to_shared(stage1)};
    unsigned si_s[2] = {(unsigned)__cvta_generic_to_shared(sidx0),
                        (unsigned)__cvta_generic_to_shared(sidx1)};

    unsigned ah[8][4], al[8][4];
    load_a_frags(W2hi, W2lo, m0 + g, tig, ah, al);

    int ntiles = (E + TE2 - 1) / TE2;

    // register prefetch of indices for a tile (chained LDG: dst -> off[dst])
    int pd, ps, po;
    auto prefetch = [&](int tile) {
        int ego = tile * TE2 + row;
        if (ego > E - 1) ego = E - 1;
        pd = __ldg(dsts + ego);
        ps = __ldg(srcs + ego);
        po = __ldg(off + pd);
    };

    auto load_tile = [&](int tile, int b) {
        int e0 = tile * TE2;
        // q row (slot 64+row): 4 quads per thread
        {
            const char* qsrc = (const char*)(pq + (size_t)ps * 256 + C);
            unsigned base = st_s[b] + (unsigned)((64 + row) * 16) * 16;
            int sw = row & 7;
#pragma unroll
            for (int j = 0; j < 4; j++) {
                int c = q4 + j;
                cpasync16(base + (unsigned)((c ^ sw) * 16), qsrc + c * 16);
            }
        }
        // p row: only the run-start edge stages it
        int sp = po - e0;
        if (sp < 0) sp = 0;
        if (row == sp) {
            const char* psrc = (const char*)(pq + (size_t)pd * 256);
            unsigned base = st_s[b] + (unsigned)(sp * 16) * 16;
            int sw = sp & 7;
#pragma unroll
            for (int j = 0; j < 4; j++) {
                int c = q4 + j;
                cpasync16(base + (unsigned)((c ^ sw) * 16), psrc + c * 16);
            }
        }
        if ((tid & 3) == 0) spsb[b][row] = sp;
        if (tid < TE2 / 4) {
            int o = tid * 4;
            if (e0 + o + 3 < E) {
                cpasync16(si_s[b] + o * 4, dsts + e0 + o);
            } else {
                for (int j = 0; j < 4; j++)
                    sib[b][o + j] = (e0 + o + j < E) ? dsts[e0 + o + j] : -1;
            }
        }
        cpcommit();
    };

    if (blockIdx.x < ntiles) {
        prefetch(blockIdx.x);
        load_tile(blockIdx.x, 0);
        prefetch(blockIdx.x + gridDim.x < ntiles ? blockIdx.x + gridDim.x : blockIdx.x);
    } else {
        cpcommit();
    }

    int i = 0;
    for (int tile = blockIdx.x; tile < ntiles; tile += gridDim.x, i++) {
        int cur = i & 1;
        int nt = tile + gridDim.x;
        if (nt < ntiles) {
            load_tile(nt, cur ^ 1);
            int nnt = nt + gridDim.x;
            prefetch(nnt < ntiles ? nnt : nt);
        } else {
            cpcommit();
        }
        cpwait1();
        __syncthreads();

        // convert: h[e][ch] = relu(p16[slot] + q16[e]); 4 quads per thread
        {
            int e = row;
            const uint4* stp = (const uint4*)stg[cur];
            __half* hrow = h_s + e * HST;
            int sp = spsb[cur][e];
            int swp = sp & 7, swq = e & 7;
            const __half2 z2 = __floats2half2_rn(0.f, 0.f);
#pragma unroll
            for (int j = 0; j < 4; j++) {
                int c = q4 + j;   // quad index 0..15
                uint4 pv = stp[sp * 16 + (c ^ swp)];
                uint4 qv = stp[(64 + e) * 16 + (c ^ swq)];
                __half2* p2 = (__half2*)&pv;
                __half2* q2 = (__half2*)&qv;
                uint4 out;
                __half2* o2 = (__half2*)&out;
#pragma unroll
                for (int k = 0; k < 4; k++)
                    o2[k] = __hmax2(__hadd2(p2[k], q2[k]), z2);
                *(uint4*)(hrow + c * 8) = out;
            }
        }
        __syncthreads();
        // stage[cur] is now dead -> reuse as DT (fp32 edge-major [e][DSTE])
        float* DT = (float*)stg[cur];

        // MMA: 8 edge-subtiles of 8 (all 64 edges), K=128, 2 terms
#pragma unroll 1
        for (int et = 0; et < 8; et++) {
            int e0t = et * 8;
            float d0 = 0.f, d1 = 0.f, d2 = 0.f, d3 = 0.f;
#pragma unroll
            for (int ks = 0; ks < 8; ks++) {
                int k0 = ks * 16;
                const unsigned* bp = (const unsigned*)(h_s + (e0t + g) * HST + k0 + tig * 2);
                unsigned b0 = bp[0], b1 = bp[4];
                mma16816(d0, d1, d2, d3, ah[ks][0], ah[ks][1], ah[ks][2], ah[ks][3], b0, b1);
                mma16816(d0, d1, d2, d3, al[ks][0], al[ks][1], al[ks][2], al[ks][3], b0, b1);
            }
            int eA = e0t + tig * 2, eB = eA + 1;
            DT[eA * DSTE + m0 + g]     = d0;
            DT[eB * DSTE + m0 + g]     = d1;
            DT[eA * DSTE + m0 + g + 8] = d2;
            DT[eB * DSTE + m0 + g + 8] = d3;
        }
        __syncthreads();

        // fused segmented max: thread = (channel, 32-edge half)
        {
            const int* si = sib[cur];
            int ch = tid & 127;
            int grp = tid >> 7;
            int base = grp * 32;
            int prev = si[base];
            float runmax = DT[base * DSTE + ch];
#pragma unroll
            for (int ii = 1; ii < 32; ii++) {
                int d = si[base + ii];
                float v = DT[(base + ii) * DSTE + ch];
                if (d != prev) {
                    if (prev >= 0) atomicMaxF(agg + (size_t)prev * C + ch, runmax);
                    prev = d;
                    runmax = v;
                } else {
                    runmax = fmaxf(runmax, v);
                }
            }
            if (prev >= 0) atomicMaxF(agg + (size_t)prev * C + ch, runmax);
        }
        __syncthreads();
    }
}

// ---------------- finalize: empty nodes -> 0, +b2, optional relu ---------------
__global__ void finalize_kernel(const float* __restrict__ agg,
                                const float* __restrict__ b2,
                                float* __restrict__ out, int N, int do_relu)
{
    int idx = blockIdx.x * blockDim.x + threadIdx.x;
    if (idx >= N * C) return;
    int c = idx & (C - 1);
    float v = agg[idx];
    float o = isfinite(v) ? (v + b2[c]) : 0.f;
    if (do_relu) o = fmaxf(o, 0.f);
    out[idx] = o;
}

// ---------------- launch -------------------------------------------------------
extern "C" void kernel_launch(void* const* d_in, const int* in_sizes, int n_in,
                              void* d_out, int out_size)
{
    const float* x  = (const float*)d_in[0];
    const int*   ei = (const int*)d_in[1];
    int N = in_sizes[0] / C;
    int E = in_sizes[1] / 2;
    const int* srcp = ei;
    const int* dstp = ei + E;

    float *aggp, *xcur, *Wc;
    __half *pq, *wchi, *wclo, *w2hi, *w2lo;
    int *off, *curp, *bsum, *srcs, *dsts;
    cudaGetSymbolAddress((void**)&pq,   g_pq);
    cudaGetSymbolAddress((void**)&aggp, g_agg);
    cudaGetSymbolAddress((void**)&xcur, g_x);
    cudaGetSymbolAddress((void**)&Wc,   g_Wc);
    cudaGetSymbolAddress((void**)&wchi, g_wchi);
    cudaGetSymbolAddress((void**)&wclo, g_wclo);
    cudaGetSymbolAddress((void**)&w2hi, g_w2hi);
    cudaGetSymbolAddress((void**)&w2lo, g_w2lo);
    cudaGetSymbolAddress((void**)&off,  g_off);
    cudaGetSymbolAddress((void**)&curp, g_cur);
    cudaGetSymbolAddress((void**)&bsum, g_bsum);
    cudaGetSymbolAddress((void**)&srcs, g_srcs);
    cudaGetSymbolAddress((void**)&dsts, g_dsts);

    // ---- sort edges by dst (once; reused by all 3 layers) ----
    int nscan = N + 1;
    int nb = (nscan + 1023) / 1024;
    cudaMemsetAsync(off, 0, (size_t)(N + 1) * sizeof(int));
    hist_kernel<<<(E + 255) / 256, 256>>>(dstp, off, E);
    scan1_kernel<<<nb, 1024>>>(off, bsum, nscan);
    scan2_kernel<<<1, 1>>>(bsum, nb);
    scan3_kernel<<<nb, 1024>>>(off, bsum, curp, nscan, N);
    scatter_kernel<<<(E + 255) / 256, 256>>>(srcp, dstp, curp, srcs, dsts, E);

    const size_t SMEM_E = (size_t)(TE2 * HST) * sizeof(__half)   // h
                        + 2 * (size_t)STAGE_B                    // stage/DT x2
                        + 4 * TE2 * sizeof(int);                 // sidx + sps
    cudaFuncSetAttribute(edge_fused_kernel, cudaFuncAttributeMaxDynamicSharedMemorySize, (int)SMEM_E);
    const size_t SMEM_N = (size_t)(2 * 128 * HST) * sizeof(__half);
    cudaFuncSetAttribute(node_mma_kernel, cudaFuncAttributeMaxDynamicSharedMemorySize, (int)SMEM_N);

    const float* Ws[3][4] = {
        {(const float*)d_in[2],  (const float*)d_in[3],  (const float*)d_in[4],  (const float*)d_in[5]},
        {(const float*)d_in[6],  (const float*)d_in[7],  (const float*)d_in[8],  (const float*)d_in[9]},
        {(const float*)d_in[10], (const float*)d_in[11], (const float*)d_in[12], (const float*)d_in[13]},
    };

    const float* xin = x;
    for (int l = 0; l < 3; l++) {
        const float* W1 = Ws[l][0];
        const float* b1 = Ws[l][1];
        const float* W2 = Ws[l][2];
        const float* b2 = Ws[l][3];
        float* xout = (l == 2) ? (float*)d_out : xcur;

        prep_kernel<<<C, 256>>>(W1, Wc);
        wcsplit_kernel<<<256, C>>>(Wc, wchi, wclo);
        w2split_kernel<<<C, C>>>(W2, w2hi, w2lo);
        node_mma_kernel<<<(N + 127) / 128, 512, SMEM_N>>>(xin, wchi, wclo, b1, pq, N);
        cudaMemsetAsync(aggp, 0xFF, (size_t)N * C * sizeof(float));
        edge_fused_kernel<<<296, 256, SMEM_E>>>(pq, srcs, dsts, off, w2hi, w2lo, aggp, E);
        finalize_kernel<<<(N * C + 255) / 256, 256>>>(aggp, b2, xout, N, (l < 2) ? 1 : 0);

        xin = xcur;
    }
}

// round 14
// speedup vs baseline: 3.5948x; 1.0374x over previous
#include <cuda_runtime.h>
#include <cuda_fp16.h>
#include <math.h>

#define N_NODES 50000
#define N_EDGES 800000
#define C 128
#define TE2 64           // edge tile (edges)
#define HST 136          // h tile stride (halfs): conflict-free B-frag LDS
#define DSTE 132         // D tile stride (floats), edge-major [e][ch]
#define STAGE_B 33792    // stage buffer bytes (>= 64*16*16 staged, == DT bytes)

// ---------------- scratch (static device globals; no allocations) -------------
__device__ __half g_pq[(size_t)N_NODES * 256];     // [N][256] fp16: p (+b1) | q
__device__ float g_agg[(size_t)N_NODES * C];       // max-aggregation buffer
__device__ __half g_wchi[256 * C];                 // Wc^T hi plane [out][k]
__device__ __half g_wclo[256 * C];                 // Wc^T lo plane [out][k]
__device__ __half g_w2hi[C * C];                   // W2^T hi plane [n][k]
__device__ __half g_w2lo[C * C];                   // W2^T lo plane [n][k]
__device__ int g_off[N_NODES + 1];                 // CSR row pointers (by dst)
__device__ int g_cur[N_NODES];                     // scatter cursors
__device__ int g_bsum[64];                         // scan block sums
__device__ int g_srcs[N_EDGES];                    // src sorted by dst
__device__ int g_dsts[N_EDGES];                    // dst sorted (ascending)

// ---------------- float atomic max (signed-max / unsigned-min trick) ----------
__device__ __forceinline__ void atomicMaxF(float* a, float v) {
    if (v >= 0.0f) atomicMax((int*)a, __float_as_int(v));
    else           atomicMin((unsigned int*)a, __float_as_uint(v));
}

// ---------------- HMMA m16n8k16 fp16 ------------------------------------------
__device__ __forceinline__ void mma16816(float& d0, float& d1, float& d2, float& d3,
                                         unsigned a0, unsigned a1, unsigned a2, unsigned a3,
                                         unsigned b0, unsigned b1)
{
    asm volatile(
        "mma.sync.aligned.m16n8k16.row.col.f32.f16.f16.f32 "
        "{%0,%1,%2,%3},{%4,%5,%6,%7},{%8,%9},{%0,%1,%2,%3};\n"
        : "+f"(d0), "+f"(d1), "+f"(d2), "+f"(d3)
        : "r"(a0), "r"(a1), "r"(a2), "r"(a3), "r"(b0), "r"(b1));
}

// ---------------- cp.async helpers ---------------------------------------------
__device__ __forceinline__ void cpasync16(unsigned saddr, const void* gptr) {
    asm volatile("cp.async.cg.shared.global [%0], [%1], 16;\n" :: "r"(saddr), "l"(gptr));
}
__device__ __forceinline__ void cpcommit() { asm volatile("cp.async.commit_group;\n"); }
__device__ __forceinline__ void cpwait1()  { asm volatile("cp.async.wait_group 1;\n"); }

// ---------------- A-fragment preload (W^T hi/lo, 8 k-steps) --------------------
// i00 = row*64 + k0/2 + tig  (tig term is load-bearing: per-lane k offset)
__device__ __forceinline__ void load_a_frags(const __half* Whi, const __half* Wlo,
                                             int row, int tig,
                                             unsigned ah[8][4], unsigned al[8][4])
{
    const unsigned* Hp = (const unsigned*)Whi;
    const unsigned* Lp = (const unsigned*)Wlo;
#pragma unroll
    for (int ks = 0; ks < 8; ks++) {
        int k0 = ks * 16;
        int i00 = row * (C / 2) + (k0 >> 1) + tig;
        ah[ks][0] = Hp[i00];
        ah[ks][1] = Hp[i00 + 8 * (C / 2)];
        ah[ks][2] = Hp[i00 + 4];
        ah[ks][3] = Hp[i00 + 8 * (C / 2) + 4];
        al[ks][0] = Lp[i00];
        al[ks][1] = Lp[i00 + 8 * (C / 2)];
        al[ks][2] = Lp[i00 + 4];
        al[ks][3] = Lp[i00 + 8 * (C / 2) + 4];
    }
}

// ---------------- sort-by-dst preprocessing ------------------------------------
__global__ void hist_kernel(const int* __restrict__ dst, int* __restrict__ off, int E) {
    int e = blockIdx.x * blockDim.x + threadIdx.x;
    if (e < E) atomicAdd(&off[dst[e] + 1], 1);
}

__global__ void scan1_kernel(int* __restrict__ a, int* __restrict__ bsum, int n) {
    __shared__ int s[1024];
    int i = blockIdx.x * 1024 + threadIdx.x;
    int v = (i < n) ? a[i] : 0;
    s[threadIdx.x] = v;
    __syncthreads();
    for (int d = 1; d < 1024; d <<= 1) {
        int t = (threadIdx.x >= d) ? s[threadIdx.x - d] : 0;
        __syncthreads();
        s[threadIdx.x] += t;
        __syncthreads();
    }
    if (i < n) a[i] = s[threadIdx.x];
    if (threadIdx.x == 1023) bsum[blockIdx.x] = s[1023];
}

__global__ void scan2_kernel(int* __restrict__ bsum, int nb) {
    int acc = 0;
    for (int i = 0; i < nb; i++) { int t = bsum[i]; bsum[i] = acc; acc += t; }
}

__global__ void scan3_kernel(int* __restrict__ a, const int* __restrict__ bsum,
                             int* __restrict__ cur, int n, int N) {
    int i = blockIdx.x * 1024 + threadIdx.x;
    if (i < n) {
        int v = a[i] + bsum[blockIdx.x];
        a[i] = v;
        if (i < N) cur[i] = v;
    }
}

__global__ void scatter_kernel(const int* __restrict__ src, const int* __restrict__ dst,
                               int* __restrict__ cur, int* __restrict__ ssrc,
                               int* __restrict__ sdst, int E) {
    int e = blockIdx.x * blockDim.x + threadIdx.x;
    if (e < E) {
        int d = dst[e];
        int pos = atomicAdd(&cur[d], 1);
        sdst[pos] = d;
        ssrc[pos] = src[e];
    }
}

// ---------------- fused prep: Wc^T + W2^T fp16 hi/lo splits (one launch) -------
__global__ void prep_fused_kernel(const float* __restrict__ W1,
                                  const float* __restrict__ W2,
                                  __half* __restrict__ wchi, __half* __restrict__ wclo,
                                  __half* __restrict__ w2hi, __half* __restrict__ w2lo)
{
    int j = blockIdx.x;   // out channel 0..255
    int k = threadIdx.x;  // in channel 0..127
    float w = (j < C) ? (W1[k * C + j] - W1[(C + k) * C + j])
                      : W1[(C + k) * C + (j - C)];
    __half h = __float2half_rn(w);
    wchi[j * C + k] = h;
    wclo[j * C + k] = __float2half_rn(w - __half2float(h));
    if (j < C) {
        float w2 = W2[k * C + j];
        __half h2 = __float2half_rn(w2);
        w2hi[j * C + k] = h2;
        w2lo[j * C + k] = __float2half_rn(w2 - __half2float(h2));
    }
}

// ---------------- node GEMM (tensor, 3-term split): pq = fp16(in @ Wc + b1) ----
// mode 0: in = x (fp32 features).  mode 1: in = agg (apply isfinite->0, +b2p, relu).
__global__ void __launch_bounds__(512, 1) node_mma_kernel(
    const float* __restrict__ in,
    const __half* __restrict__ Whi, const __half* __restrict__ Wlo,
    const float* __restrict__ b1, const float* __restrict__ b2p,
    __half* __restrict__ pq, int N, int mode)
{
    extern __shared__ char sm[];
    __half* xh = (__half*)sm;          // [128][HST]
    __half* xl = xh + 128 * HST;       // [128][HST]

    int tid = threadIdx.x;
    int wid = tid >> 5, lane = tid & 31;
    int g = lane >> 2, tig = lane & 3;
    int m0 = wid * 16;

    unsigned ah[8][4], al[8][4];
    load_a_frags(Whi, Wlo, m0 + g, tig, ah, al);

    float bias0 = (m0 + g < C) ? b1[m0 + g] : 0.f;
    float bias1 = (m0 + g + 8 < C) ? b1[m0 + g + 8] : 0.f;

    int n0 = blockIdx.x * 128;

    {
        int e = tid >> 2;
        int part = tid & 3;
        int node = n0 + e;
        const float4* xr = (const float4*)(in + (size_t)node * C + part * 32);
        const float4* b2r = (const float4*)(b2p + part * 32);
        unsigned* xhp = (unsigned*)(xh + e * HST + part * 32);
        unsigned* xlp = (unsigned*)(xl + e * HST + part * 32);
#pragma unroll
        for (int i = 0; i < 8; i++) {
            float4 v = (node < N) ? xr[i] : make_float4(0.f, 0.f, 0.f, 0.f);
            if (mode) {
                float4 bb = b2r[i];
                v.x = isfinite(v.x) ? fmaxf(v.x + bb.x, 0.f) : 0.f;
                v.y = isfinite(v.y) ? fmaxf(v.y + bb.y, 0.f) : 0.f;
                v.z = isfinite(v.z) ? fmaxf(v.z + bb.z, 0.f) : 0.f;
                v.w = isfinite(v.w) ? fmaxf(v.w + bb.w, 0.f) : 0.f;
            }
            __half2 hA = __floats2half2_rn(v.x, v.y);
            __half2 hB = __floats2half2_rn(v.z, v.w);
            __half2 lA = __floats2half2_rn(v.x - __half2float(hA.x), v.y - __half2float(hA.y));
            __half2 lB = __floats2half2_rn(v.z - __half2float(hB.x), v.w - __half2float(hB.y));
            xhp[i * 2 + 0] = *(unsigned*)&hA;
            xhp[i * 2 + 1] = *(unsigned*)&hB;
            xlp[i * 2 + 0] = *(unsigned*)&lA;
            xlp[i * 2 + 1] = *(unsigned*)&lB;
        }
    }
    __syncthreads();

#pragma unroll 1
    for (int et = 0; et < 16; et++) {
        int e0t = et * 8;
        float d0 = 0.f, d1 = 0.f, d2 = 0.f, d3 = 0.f;
#pragma unroll
        for (int ks = 0; ks < 8; ks++) {
            int k0 = ks * 16;
            const unsigned* bhp = (const unsigned*)(xh + (e0t + g) * HST + k0 + tig * 2);
            const unsigned* blp = (const unsigned*)(xl + (e0t + g) * HST + k0 + tig * 2);
            unsigned bh0 = bhp[0], bh1 = bhp[4];
            unsigned bl0 = blp[0], bl1 = blp[4];
            mma16816(d0, d1, d2, d3, ah[ks][0], ah[ks][1], ah[ks][2], ah[ks][3], bh0, bh1);
            mma16816(d0, d1, d2, d3, ah[ks][0], ah[ks][1], ah[ks][2], ah[ks][3], bl0, bl1);
            mma16816(d0, d1, d2, d3, al[ks][0], al[ks][1], al[ks][2], al[ks][3], bh0, bh1);
        }
        int eA = n0 + e0t + tig * 2;
        int eB = eA + 1;
        if (eA < N) {
            pq[(size_t)eA * 256 + m0 + g]     = __float2half_rn(d0 + bias0);
            pq[(size_t)eA * 256 + m0 + g + 8] = __float2half_rn(d2 + bias1);
        }
        if (eB < N) {
            pq[(size_t)eB * 256 + m0 + g]     = __float2half_rn(d1 + bias0);
            pq[(size_t)eB * 256 + m0 + g + 8] = __float2half_rn(d3 + bias1);
        }
    }
}

// ---------------- fused edge kernel, 2 CTAs/SM, DT aliases dead stage buffer ----
__global__ void __launch_bounds__(256, 2) edge_fused_kernel(
    const __half* __restrict__ pq,
    const int* __restrict__ srcs, const int* __restrict__ dsts,
    const int* __restrict__ off,
    const __half* __restrict__ W2hi, const __half* __restrict__ W2lo,
    float* __restrict__ agg, int E)
{
    extern __shared__ char smraw[];
    __half* h_s = (__half*)smraw;                       // [TE2][HST] 17408B
    char* stage0 = (char*)(h_s + TE2 * HST);            // STAGE_B each; staged rows
    char* stage1 = stage0 + STAGE_B;                    //   + DT alias after convert
    int* sidx0 = (int*)(stage1 + STAGE_B);              // [TE2]
    int* sidx1 = sidx0 + TE2;
    int* sps0 = sidx1 + TE2;                            // [TE2] p slot per edge
    int* sps1 = sps0 + TE2;

    int tid = threadIdx.x;
    int wid = tid >> 5, lane = tid & 31;
    int g = lane >> 2, tig = lane & 3;
    int m0 = wid * 16;

    int row = tid >> 2;        // edge row this thread stages/converts (0..63)
    int q4 = (tid & 3) * 4;    // first of 4 owned quads

    char* stg[2] = {stage0, stage1};
    int* sib[2] = {sidx0, sidx1};
    int* spsb[2] = {sps0, sps1};
    unsigned st_s[2] = {(unsigned)__cvta_generic_to_shared(stage0),
                        (unsigned)__cvta_generic_to_shared(stage1)};
    unsigned si_s[2] = {(unsigned)__cvta_generic_to_shared(sidx0),
                        (unsigned)__cvta_generic_to_shared(sidx1)};

    unsigned ah[8][4], al[8][4];
    load_a_frags(W2hi, W2lo, m0 + g, tig, ah, al);

    int ntiles = (E + TE2 - 1) / TE2;

    int pd, ps, po;
    auto prefetch = [&](int tile) {
        int ego = tile * TE2 + row;
        if (ego > E - 1) ego = E - 1;
        pd = __ldg(dsts + ego);
        ps = __ldg(srcs + ego);
        po = __ldg(off + pd);
    };

    auto load_tile = [&](int tile, int b) {
        int e0 = tile * TE2;
        {
            const char* qsrc = (const char*)(pq + (size_t)ps * 256 + C);
            unsigned base = st_s[b] + (unsigned)((64 + row) * 16) * 16;
            int sw = row & 7;
#pragma unroll
            for (int j = 0; j < 4; j++) {
                int c = q4 + j;
                cpasync16(base + (unsigned)((c ^ sw) * 16), qsrc + c * 16);
            }
        }
        int sp = po - e0;
        if (sp < 0) sp = 0;
        if (row == sp) {
            const char* psrc = (const char*)(pq + (size_t)pd * 256);
            unsigned base = st_s[b] + (unsigned)(sp * 16) * 16;
            int sw = sp & 7;
#pragma unroll
            for (int j = 0; j < 4; j++) {
                int c = q4 + j;
                cpasync16(base + (unsigned)((c ^ sw) * 16), psrc + c * 16);
            }
        }
        if ((tid & 3) == 0) spsb[b][row] = sp;
        if (tid < TE2 / 4) {
            int o = tid * 4;
            if (e0 + o + 3 < E) {
                cpasync16(si_s[b] + o * 4, dsts + e0 + o);
            } else {
                for (int j = 0; j < 4; j++)
                    sib[b][o + j] = (e0 + o + j < E) ? dsts[e0 + o + j] : -1;
            }
        }
        cpcommit();
    };

    if (blockIdx.x < ntiles) {
        prefetch(blockIdx.x);
        load_tile(blockIdx.x, 0);
        prefetch(blockIdx.x + gridDim.x < ntiles ? blockIdx.x + gridDim.x : blockIdx.x);
    } else {
        cpcommit();
    }

    int i = 0;
    for (int tile = blockIdx.x; tile < ntiles; tile += gridDim.x, i++) {
        int cur = i & 1;
        int nt = tile + gridDim.x;
        if (nt < ntiles) {
            load_tile(nt, cur ^ 1);
            int nnt = nt + gridDim.x;
            prefetch(nnt < ntiles ? nnt : nt);
        } else {
            cpcommit();
        }
        cpwait1();
        __syncthreads();

        // convert: h[e][ch] = relu(p16[slot] + q16[e]); 4 quads per thread
        {
            int e = row;
            const uint4* stp = (const uint4*)stg[cur];
            __half* hrow = h_s + e * HST;
            int sp = spsb[cur][e];
            int swp = sp & 7, swq = e & 7;
            const __half2 z2 = __floats2half2_rn(0.f, 0.f);
#pragma unroll
            for (int j = 0; j < 4; j++) {
                int c = q4 + j;
                uint4 pv = stp[sp * 16 + (c ^ swp)];
                uint4 qv = stp[(64 + e) * 16 + (c ^ swq)];
                __half2* p2 = (__half2*)&pv;
                __half2* q2 = (__half2*)&qv;
                uint4 out;
                __half2* o2 = (__half2*)&out;
#pragma unroll
                for (int k = 0; k < 4; k++)
                    o2[k] = __hmax2(__hadd2(p2[k], q2[k]), z2);
                *(uint4*)(hrow + c * 8) = out;
            }
        }
        __syncthreads();
        float* DT = (float*)stg[cur];   // stage[cur] dead -> DT alias

        // MMA: 8 edge-subtiles of 8 (all 64 edges), K=128, 2 terms
#pragma unroll 1
        for (int et = 0; et < 8; et++) {
            int e0t = et * 8;
            float d0 = 0.f, d1 = 0.f, d2 = 0.f, d3 = 0.f;
#pragma unroll
            for (int ks = 0; ks < 8; ks++) {
                int k0 = ks * 16;
                const unsigned* bp = (const unsigned*)(h_s + (e0t + g) * HST + k0 + tig * 2);
                unsigned b0 = bp[0], b1 = bp[4];
                mma16816(d0, d1, d2, d3, ah[ks][0], ah[ks][1], ah[ks][2], ah[ks][3], b0, b1);
                mma16816(d0, d1, d2, d3, al[ks][0], al[ks][1], al[ks][2], al[ks][3], b0, b1);
            }
            int eA = e0t + tig * 2, eB = eA + 1;
            DT[eA * DSTE + m0 + g]     = d0;
            DT[eB * DSTE + m0 + g]     = d1;
            DT[eA * DSTE + m0 + g + 8] = d2;
            DT[eB * DSTE + m0 + g + 8] = d3;
        }
        __syncthreads();

        // fused segmented max: thread = (channel, 32-edge half)
        {
            const int* si = sib[cur];
            int ch = tid & 127;
            int grp = tid >> 7;
            int base = grp * 32;
            int prev = si[base];
            float runmax = DT[base * DSTE + ch];
#pragma unroll
            for (int ii = 1; ii < 32; ii++) {
                int d = si[base + ii];
                float v = DT[(base + ii) * DSTE + ch];
                if (d != prev) {
                    if (prev >= 0) atomicMaxF(agg + (size_t)prev * C + ch, runmax);
                    prev = d;
                    runmax = v;
                } else {
                    runmax = fmaxf(runmax, v);
                }
            }
            if (prev >= 0) atomicMaxF(agg + (size_t)prev * C + ch, runmax);
        }
        __syncthreads();
    }
}

// ---------------- finalize (last layer only): empty->0, +b2 --------------------
__global__ void finalize_kernel(const float* __restrict__ agg,
                                const float* __restrict__ b2,
                                float* __restrict__ out, int N)
{
    int idx = blockIdx.x * blockDim.x + threadIdx.x;
    if (idx >= N * C) return;
    int c = idx & (C - 1);
    float v = agg[idx];
    out[idx] = isfinite(v) ? (v + b2[c]) : 0.f;
}

// ---------------- launch -------------------------------------------------------
extern "C" void kernel_launch(void* const* d_in, const int* in_sizes, int n_in,
                              void* d_out, int out_size)
{
    const float* x  = (const float*)d_in[0];
    const int*   ei = (const int*)d_in[1];
    int N = in_sizes[0] / C;
    int E = in_sizes[1] / 2;
    const int* srcp = ei;
    const int* dstp = ei + E;

    float *aggp;
    __half *pq, *wchi, *wclo, *w2hi, *w2lo;
    int *off, *curp, *bsum, *srcs, *dsts;
    cudaGetSymbolAddress((void**)&pq,   g_pq);
    cudaGetSymbolAddress((void**)&aggp, g_agg);
    cudaGetSymbolAddress((void**)&wchi, g_wchi);
    cudaGetSymbolAddress((void**)&wclo, g_wclo);
    cudaGetSymbolAddress((void**)&w2hi, g_w2hi);
    cudaGetSymbolAddress((void**)&w2lo, g_w2lo);
    cudaGetSymbolAddress((void**)&off,  g_off);
    cudaGetSymbolAddress((void**)&curp, g_cur);
    cudaGetSymbolAddress((void**)&bsum, g_bsum);
    cudaGetSymbolAddress((void**)&srcs, g_srcs);
    cudaGetSymbolAddress((void**)&dsts, g_dsts);

    // ---- sort edges by dst (once; reused by all 3 layers) ----
    int nscan = N + 1;
    int nb = (nscan + 1023) / 1024;
    cudaMemsetAsync(off, 0, (size_t)(N + 1) * sizeof(int));
    hist_kernel<<<(E + 255) / 256, 256>>>(dstp, off, E);
    scan1_kernel<<<nb, 1024>>>(off, bsum, nscan);
    scan2_kernel<<<1, 1>>>(bsum, nb);
    scan3_kernel<<<nb, 1024>>>(off, bsum, curp, nscan, N);
    scatter_kernel<<<(E + 255) / 256, 256>>>(srcp, dstp, curp, srcs, dsts, E);

    const size_t SMEM_E = (size_t)(TE2 * HST) * sizeof(__half)
                        + 2 * (size_t)STAGE_B
                        + 4 * TE2 * sizeof(int);
    cudaFuncSetAttribute(edge_fused_kernel, cudaFuncAttributeMaxDynamicSharedMemorySize, (int)SMEM_E);
    const size_t SMEM_N = (size_t)(2 * 128 * HST) * sizeof(__half);
    cudaFuncSetAttribute(node_mma_kernel, cudaFuncAttributeMaxDynamicSharedMemorySize, (int)SMEM_N);

    const float* Ws[3][4] = {
        {(const float*)d_in[2],  (const float*)d_in[3],  (const float*)d_in[4],  (const float*)d_in[5]},
        {(const float*)d_in[6],  (const float*)d_in[7],  (const float*)d_in[8],  (const float*)d_in[9]},
        {(const float*)d_in[10], (const float*)d_in[11], (const float*)d_in[12], (const float*)d_in[13]},
    };

    for (int l = 0; l < 3; l++) {
        const float* W1 = Ws[l][0];
        const float* b1 = Ws[l][1];
        const float* W2 = Ws[l][2];

        prep_fused_kernel<<<256, C>>>(W1, W2, wchi, wclo, w2hi, w2lo);
        if (l == 0) {
            node_mma_kernel<<<(N + 127) / 128, 512, SMEM_N>>>(
                x, wchi, wclo, b1, b1 /*unused*/, pq, N, 0);
        } else {
            // reads agg from previous layer; applies isfinite->0, +b2_prev, relu
            node_mma_kernel<<<(N + 127) / 128, 512, SMEM_N>>>(
                aggp, wchi, wclo, b1, Ws[l - 1][3], pq, N, 1);
        }
        cudaMemsetAsync(aggp, 0xFF, (size_t)N * C * sizeof(float));
        edge_fused_kernel<<<296, 256, SMEM_E>>>(pq, srcs, dsts, off, w2hi, w2lo, aggp, E);
    }
    finalize_kernel<<<(N * C + 255) / 256, 256>>>(aggp, Ws[2][3], (float*)d_out, N);
}

// round 15
// speedup vs baseline: 3.7088x; 1.0317x over previous
#include <cuda_runtime.h>
#include <cuda_fp16.h>
#include <math.h>

#define N_NODES 50000
#define N_EDGES 800000
#define C 128
#define TE2 64           // edge tile (edges)
#define HST 136          // h tile stride (halfs): conflict-free B-frag ldmatrix
#define DSTE 132         // D tile stride (floats), edge-major [e][ch]
#define STAGE_B 33792    // stage buffer bytes (>= 64*16*16 staged, == DT bytes)

// ---------------- scratch (static device globals; no allocations) -------------
__device__ __half g_pq[(size_t)N_NODES * 256];     // [N][256] fp16: p (+b1) | q
__device__ float g_agg[(size_t)N_NODES * C];       // max-aggregation buffer
__device__ __half g_wchi[256 * C];                 // Wc^T hi plane [out][k]
__device__ __half g_wclo[256 * C];                 // Wc^T lo plane [out][k]
__device__ __half g_w2hi[C * C];                   // W2^T hi plane [n][k]
__device__ __half g_w2lo[C * C];                   // W2^T lo plane [n][k]
__device__ int g_off[N_NODES + 1];                 // CSR row pointers (by dst)
__device__ int g_cur[N_NODES];                     // scatter cursors
__device__ int g_bsum[64];                         // scan block sums
__device__ int g_srcs[N_EDGES];                    // src sorted by dst
__device__ int g_dsts[N_EDGES];                    // dst sorted (ascending)

// ---------------- float atomic max (signed-max / unsigned-min trick) ----------
__device__ __forceinline__ void atomicMaxF(float* a, float v) {
    if (v >= 0.0f) atomicMax((int*)a, __float_as_int(v));
    else           atomicMin((unsigned int*)a, __float_as_uint(v));
}

// ---------------- HMMA m16n8k16 fp16 ------------------------------------------
__device__ __forceinline__ void mma16816(float& d0, float& d1, float& d2, float& d3,
                                         unsigned a0, unsigned a1, unsigned a2, unsigned a3,
                                         unsigned b0, unsigned b1)
{
    asm volatile(
        "mma.sync.aligned.m16n8k16.row.col.f32.f16.f16.f32 "
        "{%0,%1,%2,%3},{%4,%5,%6,%7},{%8,%9},{%0,%1,%2,%3};\n"
        : "+f"(d0), "+f"(d1), "+f"(d2), "+f"(d3)
        : "r"(a0), "r"(a1), "r"(a2), "r"(a3), "r"(b0), "r"(b1));
}

// ---------------- ldmatrix x4: B-frags for 2 k-steps ----------------------------
__device__ __forceinline__ void ldmx4(unsigned addr, unsigned& r0, unsigned& r1,
                                      unsigned& r2, unsigned& r3)
{
    asm volatile("ldmatrix.sync.aligned.m8n8.x4.shared.b16 {%0,%1,%2,%3}, [%4];\n"
                 : "=r"(r0), "=r"(r1), "=r"(r2), "=r"(r3) : "r"(addr));
}

// ---------------- cp.async helpers ---------------------------------------------
__device__ __forceinline__ void cpasync16(unsigned saddr, const void* gptr) {
    asm volatile("cp.async.cg.shared.global [%0], [%1], 16;\n" :: "r"(saddr), "l"(gptr));
}
__device__ __forceinline__ void cpcommit() { asm volatile("cp.async.commit_group;\n"); }
__device__ __forceinline__ void cpwait0()  { asm volatile("cp.async.wait_group 0;\n"); }

// ---------------- A-fragment preload (W^T hi/lo, 8 k-steps) --------------------
// i00 = row*64 + k0/2 + tig  (tig term is load-bearing: per-lane k offset)
__device__ __forceinline__ void load_a_frags(const __half* Whi, const __half* Wlo,
                                             int row, int tig,
                                             unsigned ah[8][4], unsigned al[8][4])
{
    const unsigned* Hp = (const unsigned*)Whi;
    const unsigned* Lp = (const unsigned*)Wlo;
#pragma unroll
    for (int ks = 0; ks < 8; ks++) {
        int k0 = ks * 16;
        int i00 = row * (C / 2) + (k0 >> 1) + tig;
        ah[ks][0] = Hp[i00];
        ah[ks][1] = Hp[i00 + 8 * (C / 2)];
        ah[ks][2] = Hp[i00 + 4];
        ah[ks][3] = Hp[i00 + 8 * (C / 2) + 4];
        al[ks][0] = Lp[i00];
        al[ks][1] = Lp[i00 + 8 * (C / 2)];
        al[ks][2] = Lp[i00 + 4];
        al[ks][3] = Lp[i00 + 8 * (C / 2) + 4];
    }
}

// ---------------- sort-by-dst preprocessing ------------------------------------
__global__ void hist_kernel(const int* __restrict__ dst, int* __restrict__ off, int E) {
    int e = blockIdx.x * blockDim.x + threadIdx.x;
    if (e < E) atomicAdd(&off[dst[e] + 1], 1);
}

__global__ void scan1_kernel(int* __restrict__ a, int* __restrict__ bsum, int n) {
    __shared__ int s[1024];
    int i = blockIdx.x * 1024 + threadIdx.x;
    int v = (i < n) ? a[i] : 0;
    s[threadIdx.x] = v;
    __syncthreads();
    for (int d = 1; d < 1024; d <<= 1) {
        int t = (threadIdx.x >= d) ? s[threadIdx.x - d] : 0;
        __syncthreads();
        s[threadIdx.x] += t;
        __syncthreads();
    }
    if (i < n) a[i] = s[threadIdx.x];
    if (threadIdx.x == 1023) bsum[blockIdx.x] = s[1023];
}

__global__ void scan2_kernel(int* __restrict__ bsum, int nb) {
    int acc = 0;
    for (int i = 0; i < nb; i++) { int t = bsum[i]; bsum[i] = acc; acc += t; }
}

__global__ void scan3_kernel(int* __restrict__ a, const int* __restrict__ bsum,
                             int* __restrict__ cur, int n, int N) {
    int i = blockIdx.x * 1024 + threadIdx.x;
    if (i < n) {
        int v = a[i] + bsum[blockIdx.x];
        a[i] = v;
        if (i < N) cur[i] = v;
    }
}

__global__ void scatter_kernel(const int* __restrict__ src, const int* __restrict__ dst,
                               int* __restrict__ cur, int* __restrict__ ssrc,
                               int* __restrict__ sdst, int E) {
    int e = blockIdx.x * blockDim.x + threadIdx.x;
    if (e < E) {
        int d = dst[e];
        int pos = atomicAdd(&cur[d], 1);
        sdst[pos] = d;
        ssrc[pos] = src[e];
    }
}

// ---------------- fused prep: Wc^T + W2^T fp16 hi/lo splits (one launch) -------
__global__ void prep_fused_kernel(const float* __restrict__ W1,
                                  const float* __restrict__ W2,
                                  __half* __restrict__ wchi, __half* __restrict__ wclo,
                                  __half* __restrict__ w2hi, __half* __restrict__ w2lo)
{
    int j = blockIdx.x;   // out channel 0..255
    int k = threadIdx.x;  // in channel 0..127
    float w = (j < C) ? (W1[k * C + j] - W1[(C + k) * C + j])
                      : W1[(C + k) * C + (j - C)];
    __half h = __float2half_rn(w);
    wchi[j * C + k] = h;
    wclo[j * C + k] = __float2half_rn(w - __half2float(h));
    if (j < C) {
        float w2 = W2[k * C + j];
        __half h2 = __float2half_rn(w2);
        w2hi[j * C + k] = h2;
        w2lo[j * C + k] = __float2half_rn(w2 - __half2float(h2));
    }
}

// ---------------- node GEMM (tensor, 3-term split): pq = fp16(in @ Wc + b1) ----
// mode 0: in = x (fp32).  mode 1: in = agg (apply isfinite->0, +b2p, relu).
__global__ void __launch_bounds__(512, 1) node_mma_kernel(
    const float* __restrict__ in,
    const __half* __restrict__ Whi, const __half* __restrict__ Wlo,
    const float* __restrict__ b1, const float* __restrict__ b2p,
    __half* __restrict__ pq, int N, int mode)
{
    extern __shared__ char sm[];
    __half* xh = (__half*)sm;          // [128][HST]
    __half* xl = xh + 128 * HST;       // [128][HST]

    int tid = threadIdx.x;
    int wid = tid >> 5, lane = tid & 31;
    int g = lane >> 2, tig = lane & 3;
    int m0 = wid * 16;

    unsigned ah[8][4], al[8][4];
    load_a_frags(Whi, Wlo, m0 + g, tig, ah, al);

    float bias0 = (m0 + g < C) ? b1[m0 + g] : 0.f;
    float bias1 = (m0 + g + 8 < C) ? b1[m0 + g + 8] : 0.f;

    int n0 = blockIdx.x * 128;

    {
        int e = tid >> 2;
        int part = tid & 3;
        int node = n0 + e;
        const float4* xr = (const float4*)(in + (size_t)node * C + part * 32);
        const float4* b2r = (const float4*)(b2p + part * 32);
        unsigned* xhp = (unsigned*)(xh + e * HST + part * 32);
        unsigned* xlp = (unsigned*)(xl + e * HST + part * 32);
#pragma unroll
        for (int i = 0; i < 8; i++) {
            float4 v = (node < N) ? xr[i] : make_float4(0.f, 0.f, 0.f, 0.f);
            if (mode) {
                float4 bb = b2r[i];
                v.x = isfinite(v.x) ? fmaxf(v.x + bb.x, 0.f) : 0.f;
                v.y = isfinite(v.y) ? fmaxf(v.y + bb.y, 0.f) : 0.f;
                v.z = isfinite(v.z) ? fmaxf(v.z + bb.z, 0.f) : 0.f;
                v.w = isfinite(v.w) ? fmaxf(v.w + bb.w, 0.f) : 0.f;
            }
            __half2 hA = __floats2half2_rn(v.x, v.y);
            __half2 hB = __floats2half2_rn(v.z, v.w);
            __half2 lA = __floats2half2_rn(v.x - __half2float(hA.x), v.y - __half2float(hA.y));
            __half2 lB = __floats2half2_rn(v.z - __half2float(hB.x), v.w - __half2float(hB.y));
            xhp[i * 2 + 0] = *(unsigned*)&hA;
            xhp[i * 2 + 1] = *(unsigned*)&hB;
            xlp[i * 2 + 0] = *(unsigned*)&lA;
            xlp[i * 2 + 1] = *(unsigned*)&lB;
        }
    }
    __syncthreads();

    // ldmatrix lane address bases (row8 = lane&7, matrix idx = lane>>3)
    unsigned xh_lm = (unsigned)__cvta_generic_to_shared(xh)
                   + (unsigned)(((lane & 7) * HST + (lane >> 3) * 8) * 2);
    unsigned xl_lm = (unsigned)__cvta_generic_to_shared(xl)
                   + (unsigned)(((lane & 7) * HST + (lane >> 3) * 8) * 2);

#pragma unroll 1
    for (int et = 0; et < 16; et++) {
        int e0t = et * 8;
        unsigned eoff = (unsigned)(e0t * HST * 2);
        float d0 = 0.f, d1 = 0.f, d2 = 0.f, d3 = 0.f;
#pragma unroll
        for (int kb = 0; kb < 4; kb++) {
            unsigned koff = (unsigned)(kb * 64);
            unsigned bh0e, bh1e, bh0o, bh1o, bl0e, bl1e, bl0o, bl1o;
            ldmx4(xh_lm + eoff + koff, bh0e, bh1e, bh0o, bh1o);
            ldmx4(xl_lm + eoff + koff, bl0e, bl1e, bl0o, bl1o);
            int ks = kb * 2;
            mma16816(d0, d1, d2, d3, ah[ks][0], ah[ks][1], ah[ks][2], ah[ks][3], bh0e, bh1e);
            mma16816(d0, d1, d2, d3, ah[ks][0], ah[ks][1], ah[ks][2], ah[ks][3], bl0e, bl1e);
            mma16816(d0, d1, d2, d3, al[ks][0], al[ks][1], al[ks][2], al[ks][3], bh0e, bh1e);
            mma16816(d0, d1, d2, d3, ah[ks+1][0], ah[ks+1][1], ah[ks+1][2], ah[ks+1][3], bh0o, bh1o);
            mma16816(d0, d1, d2, d3, ah[ks+1][0], ah[ks+1][1], ah[ks+1][2], ah[ks+1][3], bl0o, bl1o);
            mma16816(d0, d1, d2, d3, al[ks+1][0], al[ks+1][1], al[ks+1][2], al[ks+1][3], bh0o, bh1o);
        }
        int eA = n0 + e0t + tig * 2;
        int eB = eA + 1;
        if (eA < N) {
            pq[(size_t)eA * 256 + m0 + g]     = __float2half_rn(d0 + bias0);
            pq[(size_t)eA * 256 + m0 + g + 8] = __float2half_rn(d2 + bias1);
        }
        if (eB < N) {
            pq[(size_t)eB * 256 + m0 + g]     = __float2half_rn(d1 + bias0);
            pq[(size_t)eB * 256 + m0 + g + 8] = __float2half_rn(d3 + bias1);
        }
    }
}

// ---------------- fused edge kernel: ldmatrix MMA + deferred epilogue -----------
// 256 threads / 8 warps, 2 CTAs/SM. Pipeline: wait -> convert(i) -> MMA(i)->DT[cur]
// -> epilogue(i-1) on DT[cur^1] -> sync -> load(i+1) into stage[cur^1].
__global__ void __launch_bounds__(256, 2) edge_fused_kernel(
    const __half* __restrict__ pq,
    const int* __restrict__ srcs, const int* __restrict__ dsts,
    const int* __restrict__ off,
    const __half* __restrict__ W2hi, const __half* __restrict__ W2lo,
    float* __restrict__ agg, int E)
{
    extern __shared__ char smraw[];
    __half* h_s = (__half*)smraw;                       // [TE2][HST] 17408B
    char* stage0 = (char*)(h_s + TE2 * HST);            // STAGE_B each; staged rows
    char* stage1 = stage0 + STAGE_B;                    //   + DT alias after convert
    int* sidx0 = (int*)(stage1 + STAGE_B);              // [TE2]
    int* sidx1 = sidx0 + TE2;
    int* sps0 = sidx1 + TE2;                            // [TE2] p slot per edge
    int* sps1 = sps0 + TE2;

    int tid = threadIdx.x;
    int wid = tid >> 5, lane = tid & 31;
    int g = lane >> 2, tig = lane & 3;
    int m0 = wid * 16;

    int row = tid >> 2;        // edge row this thread stages/converts (0..63)
    int q4 = (tid & 3) * 4;    // first of 4 owned quads

    char* stg[2] = {stage0, stage1};
    int* sib[2] = {sidx0, sidx1};
    int* spsb[2] = {sps0, sps1};
    unsigned st_s[2] = {(unsigned)__cvta_generic_to_shared(stage0),
                        (unsigned)__cvta_generic_to_shared(stage1)};
    unsigned si_s[2] = {(unsigned)__cvta_generic_to_shared(sidx0),
                        (unsigned)__cvta_generic_to_shared(sidx1)};
    unsigned h_lm = (unsigned)__cvta_generic_to_shared(h_s)
                  + (unsigned)(((lane & 7) * HST + (lane >> 3) * 8) * 2);

    unsigned ah[8][4], al[8][4];
    load_a_frags(W2hi, W2lo, m0 + g, tig, ah, al);

    int ntiles = (E + TE2 - 1) / TE2;

    int pd, ps, po;
    auto prefetch = [&](int tile) {
        int ego = tile * TE2 + row;
        if (ego > E - 1) ego = E - 1;
        pd = __ldg(dsts + ego);
        ps = __ldg(srcs + ego);
        po = __ldg(off + pd);
    };

    auto load_tile = [&](int tile, int b) {
        int e0 = tile * TE2;
        {
            const char* qsrc = (const char*)(pq + (size_t)ps * 256 + C);
            unsigned base = st_s[b] + (unsigned)((64 + row) * 16) * 16;
            int sw = row & 7;
#pragma unroll
            for (int j = 0; j < 4; j++) {
                int c = q4 + j;
                cpasync16(base + (unsigned)((c ^ sw) * 16), qsrc + c * 16);
            }
        }
        int sp = po - e0;
        if (sp < 0) sp = 0;
        if (row == sp) {
            const char* psrc = (const char*)(pq + (size_t)pd * 256);
            unsigned base = st_s[b] + (unsigned)(sp * 16) * 16;
            int sw = sp & 7;
#pragma unroll
            for (int j = 0; j < 4; j++) {
                int c = q4 + j;
                cpasync16(base + (unsigned)((c ^ sw) * 16), psrc + c * 16);
            }
        }
        if ((tid & 3) == 0) spsb[b][row] = sp;
        if (tid < TE2 / 4) {
            int o = tid * 4;
            if (e0 + o + 3 < E) {
                cpasync16(si_s[b] + o * 4, dsts + e0 + o);
            } else {
                for (int j = 0; j < 4; j++)
                    sib[b][o + j] = (e0 + o + j < E) ? dsts[e0 + o + j] : -1;
            }
        }
        cpcommit();
    };

    // epilogue for buffer b: fused segmented max, thread = (channel, 32-edge half)
    auto epilogue = [&](int b) {
        const int* si = sib[b];
        const float* DT = (const float*)stg[b];
        int ch = tid & 127;
        int grp = tid >> 7;
        int base = grp * 32;
        int prev = si[base];
        float runmax = DT[base * DSTE + ch];
#pragma unroll
        for (int ii = 1; ii < 32; ii++) {
            int d = si[base + ii];
            float v = DT[(base + ii) * DSTE + ch];
            if (d != prev) {
                if (prev >= 0) atomicMaxF(agg + (size_t)prev * C + ch, runmax);
                prev = d;
                runmax = v;
            } else {
                runmax = fmaxf(runmax, v);
            }
        }
        if (prev >= 0) atomicMaxF(agg + (size_t)prev * C + ch, runmax);
    };

    if (blockIdx.x < ntiles) {
        prefetch(blockIdx.x);
        load_tile(blockIdx.x, 0);
        prefetch(blockIdx.x + gridDim.x < ntiles ? blockIdx.x + gridDim.x : blockIdx.x);
    }

    int have = 0, pb = 0;
    int i = 0;
    for (int tile = blockIdx.x; tile < ntiles; tile += gridDim.x, i++) {
        int cur = i & 1;
        cpwait0();
        __syncthreads();   // B1: stage[cur] + sidx visible; prev MMA complete

        // convert: h[e][ch] = relu(p16[slot] + q16[e]); 4 quads per thread
        {
            int e = row;
            const uint4* stp = (const uint4*)stg[cur];
            __half* hrow = h_s + e * HST;
            int sp = spsb[cur][e];
            int swp = sp & 7, swq = e & 7;
            const __half2 z2 = __floats2half2_rn(0.f, 0.f);
#pragma unroll
            for (int j = 0; j < 4; j++) {
                int c = q4 + j;
                uint4 pv = stp[sp * 16 + (c ^ swp)];
                uint4 qv = stp[(64 + e) * 16 + (c ^ swq)];
                __half2* p2 = (__half2*)&pv;
                __half2* q2 = (__half2*)&qv;
                uint4 out;
                __half2* o2 = (__half2*)&out;
#pragma unroll
                for (int k = 0; k < 4; k++)
                    o2[k] = __hmax2(__hadd2(p2[k], q2[k]), z2);
                *(uint4*)(hrow + c * 8) = out;
            }
        }
        __syncthreads();   // B2: h_s ready; stage[cur] free for DT alias
        float* DT = (float*)stg[cur];

        // MMA: 8 edge-subtiles of 8, K=128 via 4 ldmatrix.x4 pairs, 2 terms
#pragma unroll 1
        for (int et = 0; et < 8; et++) {
            int e0t = et * 8;
            unsigned eoff = (unsigned)(e0t * HST * 2);
            float d0 = 0.f, d1 = 0.f, d2 = 0.f, d3 = 0.f;
#pragma unroll
            for (int kb = 0; kb < 4; kb++) {
                unsigned b0e, b1e, b0o, b1o;
                ldmx4(h_lm + eoff + (unsigned)(kb * 64), b0e, b1e, b0o, b1o);
                int ks = kb * 2;
                mma16816(d0, d1, d2, d3, ah[ks][0], ah[ks][1], ah[ks][2], ah[ks][3], b0e, b1e);
                mma16816(d0, d1, d2, d3, al[ks][0], al[ks][1], al[ks][2], al[ks][3], b0e, b1e);
                mma16816(d0, d1, d2, d3, ah[ks+1][0], ah[ks+1][1], ah[ks+1][2], ah[ks+1][3], b0o, b1o);
                mma16816(d0, d1, d2, d3, al[ks+1][0], al[ks+1][1], al[ks+1][2], al[ks+1][3], b0o, b1o);
            }
            int eA = e0t + tig * 2, eB = eA + 1;
            DT[eA * DSTE + m0 + g]     = d0;
            DT[eB * DSTE + m0 + g]     = d1;
            DT[eA * DSTE + m0 + g + 8] = d2;
            DT[eB * DSTE + m0 + g + 8] = d3;
        }

        // deferred epilogue of previous tile (overlaps with other warps' MMA)
        if (have) epilogue(pb);
        __syncthreads();   // B3: epilogue done reading stage[pb]; MMA writes visible

        int nt = tile + gridDim.x;
        if (nt < ntiles) {
            load_tile(nt, cur ^ 1);
            int nnt = nt + gridDim.x;
            prefetch(nnt < ntiles ? nnt : nt);
        }
        have = 1;
        pb = cur;
    }
    if (have) epilogue(pb);   // DT[pb] visible: all warps passed B3 of last iter
}

// ---------------- finalize (last layer only): empty->0, +b2 --------------------
__global__ void finalize_kernel(const float* __restrict__ agg,
                                const float* __restrict__ b2,
                                float* __restrict__ out, int N)
{
    int idx = blockIdx.x * blockDim.x + threadIdx.x;
    if (idx >= N * C) return;
    int c = idx & (C - 1);
    float v = agg[idx];
    out[idx] = isfinite(v) ? (v + b2[c]) : 0.f;
}

// ---------------- launch -------------------------------------------------------
extern "C" void kernel_launch(void* const* d_in, const int* in_sizes, int n_in,
                              void* d_out, int out_size)
{
    const float* x  = (const float*)d_in[0];
    const int*   ei = (const int*)d_in[1];
    int N = in_sizes[0] / C;
    int E = in_sizes[1] / 2;
    const int* srcp = ei;
    const int* dstp = ei + E;

    float *aggp;
    __half *pq, *wchi, *wclo, *w2hi, *w2lo;
    int *off, *curp, *bsum, *srcs, *dsts;
    cudaGetSymbolAddress((void**)&pq,   g_pq);
    cudaGetSymbolAddress((void**)&aggp, g_agg);
    cudaGetSymbolAddress((void**)&wchi, g_wchi);
    cudaGetSymbolAddress((void**)&wclo, g_wclo);
    cudaGetSymbolAddress((void**)&w2hi, g_w2hi);
    cudaGetSymbolAddress((void**)&w2lo, g_w2lo);
    cudaGetSymbolAddress((void**)&off,  g_off);
    cudaGetSymbolAddress((void**)&curp, g_cur);
    cudaGetSymbolAddress((void**)&bsum, g_bsum);
    cudaGetSymbolAddress((void**)&srcs, g_srcs);
    cudaGetSymbolAddress((void**)&dsts, g_dsts);

    // ---- sort edges by dst (once; reused by all 3 layers) ----
    int nscan = N + 1;
    int nb = (nscan + 1023) / 1024;
    cudaMemsetAsync(off, 0, (size_t)(N + 1) * sizeof(int));
    hist_kernel<<<(E + 255) / 256, 256>>>(dstp, off, E);
    scan1_kernel<<<nb, 1024>>>(off, bsum, nscan);
    scan2_kernel<<<1, 1>>>(bsum, nb);
    scan3_kernel<<<nb, 1024>>>(off, bsum, curp, nscan, N);
    scatter_kernel<<<(E + 255) / 256, 256>>>(srcp, dstp, curp, srcs, dsts, E);

    const size_t SMEM_E = (size_t)(TE2 * HST) * sizeof(__half)
                        + 2 * (size_t)STAGE_B
                        + 4 * TE2 * sizeof(int);
    cudaFuncSetAttribute(edge_fused_kernel, cudaFuncAttributeMaxDynamicSharedMemorySize, (int)SMEM_E);
    const size_t SMEM_N = (size_t)(2 * 128 * HST) * sizeof(__half);
    cudaFuncSetAttribute(node_mma_kernel, cudaFuncAttributeMaxDynamicSharedMemorySize, (int)SMEM_N);

    const float* Ws[3][4] = {
        {(const float*)d_in[2],  (const float*)d_in[3],  (const float*)d_in[4],  (const float*)d_in[5]},
        {(const float*)d_in[6],  (const float*)d_in[7],  (const float*)d_in[8],  (const float*)d_in[9]},
        {(const float*)d_in[10], (const float*)d_in[11], (const float*)d_in[12], (const float*)d_in[13]},
    };

    for (int l = 0; l < 3; l++) {
        const float* W1 = Ws[l][0];
        const float* b1 = Ws[l][1];
        const float* W2 = Ws[l][2];

        prep_fused_kernel<<<256, C>>>(W1, W2, wchi, wclo, w2hi, w2lo);
        if (l == 0) {
            node_mma_kernel<<<(N + 127) / 128, 512, SMEM_N>>>(
                x, wchi, wclo, b1, b1 /*unused*/, pq, N, 0);
        } else {
            node_mma_kernel<<<(N + 127) / 128, 512, SMEM_N>>>(
                aggp, wchi, wclo, b1, Ws[l - 1][3], pq, N, 1);
        }
        cudaMemsetAsync(aggp, 0xFF, (size_t)N * C * sizeof(float));
        edge_fused_kernel<<<296, 256, SMEM_E>>>(pq, srcs, dsts, off, w2hi, w2lo, aggp, E);
    }
    finalize_kernel<<<(N * C + 255) / 256, 256>>>(aggp, Ws[2][3], (float*)d_out, N);
}

// round 16
// speedup vs baseline: 3.7167x; 1.0021x over previous
#include <cuda_runtime.h>
#include <cuda_fp16.h>
#include <math.h>

#define N_NODES 50000
#define N_EDGES 800000
#define C 128
#define TE2 64           // edge tile (edges)
#define HST 136          // h tile stride (halfs): conflict-free B-frag ldmatrix
#define DSTE 132         // D tile stride (floats), edge-major [e][ch]
#define STAGE_B 33792    // stage buffer bytes (>= staged rows, == DT bytes)

// ---------------- scratch (static device globals; no allocations) -------------
__device__ __half g_pq[(size_t)N_NODES * 256];     // [N][256] fp16: p (+b1) | q
__device__ float g_agg[(size_t)N_NODES * C];       // max-aggregation buffer
__device__ int g_off[N_NODES + 1];                 // CSR row pointers (by dst)
__device__ int g_cur[N_NODES];                     // scatter cursors
__device__ int g_bsum[64];                         // scan block sums
__device__ int g_srcs[N_EDGES];                    // src sorted by dst
__device__ int g_dsts[N_EDGES];                    // dst sorted (ascending)

// ---------------- float atomic max (signed-max / unsigned-min trick) ----------
__device__ __forceinline__ void atomicMaxF(float* a, float v) {
    if (v >= 0.0f) atomicMax((int*)a, __float_as_int(v));
    else           atomicMin((unsigned int*)a, __float_as_uint(v));
}

// ---------------- HMMA m16n8k16 fp16 ------------------------------------------
__device__ __forceinline__ void mma16816(float& d0, float& d1, float& d2, float& d3,
                                         unsigned a0, unsigned a1, unsigned a2, unsigned a3,
                                         unsigned b0, unsigned b1)
{
    asm volatile(
        "mma.sync.aligned.m16n8k16.row.col.f32.f16.f16.f32 "
        "{%0,%1,%2,%3},{%4,%5,%6,%7},{%8,%9},{%0,%1,%2,%3};\n"
        : "+f"(d0), "+f"(d1), "+f"(d2), "+f"(d3)
        : "r"(a0), "r"(a1), "r"(a2), "r"(a3), "r"(b0), "r"(b1));
}

// ---------------- ldmatrix x4: B-frags for 2 k-steps ----------------------------
__device__ __forceinline__ void ldmx4(unsigned addr, unsigned& r0, unsigned& r1,
                                      unsigned& r2, unsigned& r3)
{
    asm volatile("ldmatrix.sync.aligned.m8n8.x4.shared.b16 {%0,%1,%2,%3}, [%4];\n"
                 : "=r"(r0), "=r"(r1), "=r"(r2), "=r"(r3) : "r"(addr));
}

// ---------------- cp.async helpers ---------------------------------------------
__device__ __forceinline__ void cpasync16(unsigned saddr, const void* gptr) {
    asm volatile("cp.async.cg.shared.global [%0], [%1], 16;\n" :: "r"(saddr), "l"(gptr));
}
__device__ __forceinline__ void cpcommit() { asm volatile("cp.async.commit_group;\n"); }
__device__ __forceinline__ void cpwait0()  { asm volatile("cp.async.wait_group 0;\n"); }

// ---------------- fp32 pair -> fp16 hi plane (ret) + lo plane (out param) ------
__device__ __forceinline__ unsigned pack2(float w0, float w1, unsigned& lo) {
    __half h0 = __float2half_rn(w0), h1 = __float2half_rn(w1);
    __half l0 = __float2half_rn(w0 - __half2float(h0));
    __half l1 = __float2half_rn(w1 - __half2float(h1));
    lo = ((unsigned)__half_as_ushort(l1) << 16) | (unsigned)__half_as_ushort(l0);
    return ((unsigned)__half_as_ushort(h1) << 16) | (unsigned)__half_as_ushort(h0);
}

// ---------------- A-fragments from fp32 W2 [k][n] (edge GEMM, W2^T row) --------
__device__ __forceinline__ void load_a_frags_w2(const float* __restrict__ W2,
                                                int row, int tig,
                                                unsigned ah[8][4], unsigned al[8][4])
{
#pragma unroll
    for (int ks = 0; ks < 8; ks++) {
        int k = ks * 16 + tig * 2;
        ah[ks][0] = pack2(W2[k * C + row],           W2[(k + 1) * C + row],           al[ks][0]);
        ah[ks][1] = pack2(W2[k * C + row + 8],       W2[(k + 1) * C + row + 8],       al[ks][1]);
        ah[ks][2] = pack2(W2[(k + 8) * C + row],     W2[(k + 9) * C + row],           al[ks][2]);
        ah[ks][3] = pack2(W2[(k + 8) * C + row + 8], W2[(k + 9) * C + row + 8],       al[ks][3]);
    }
}

// ---------------- Wc element from fp32 W1 [2C][C] (node GEMM) ------------------
__device__ __forceinline__ float wc_elem(const float* __restrict__ W1, int j, int k) {
    return (j < C) ? (W1[k * C + j] - W1[(C + k) * C + j])
                   : W1[(C + k) * C + (j - C)];
}

__device__ __forceinline__ void load_a_frags_wc(const float* __restrict__ W1,
                                                int row, int tig,
                                                unsigned ah[8][4], unsigned al[8][4])
{
#pragma unroll
    for (int ks = 0; ks < 8; ks++) {
        int k = ks * 16 + tig * 2;
        ah[ks][0] = pack2(wc_elem(W1, row, k),         wc_elem(W1, row, k + 1),         al[ks][0]);
        ah[ks][1] = pack2(wc_elem(W1, row + 8, k),     wc_elem(W1, row + 8, k + 1),     al[ks][1]);
        ah[ks][2] = pack2(wc_elem(W1, row, k + 8),     wc_elem(W1, row, k + 9),         al[ks][2]);
        ah[ks][3] = pack2(wc_elem(W1, row + 8, k + 8), wc_elem(W1, row + 8, k + 9),     al[ks][3]);
    }
}

// ---------------- sort-by-dst preprocessing ------------------------------------
__global__ void hist_kernel(const int* __restrict__ dst, int* __restrict__ off, int E) {
    int e = blockIdx.x * blockDim.x + threadIdx.x;
    if (e < E) atomicAdd(&off[dst[e] + 1], 1);
}

__global__ void scan1_kernel(int* __restrict__ a, int* __restrict__ bsum, int n) {
    __shared__ int s[1024];
    int i = blockIdx.x * 1024 + threadIdx.x;
    int v = (i < n) ? a[i] : 0;
    s[threadIdx.x] = v;
    __syncthreads();
    for (int d = 1; d < 1024; d <<= 1) {
        int t = (threadIdx.x >= d) ? s[threadIdx.x - d] : 0;
        __syncthreads();
        s[threadIdx.x] += t;
        __syncthreads();
    }
    if (i < n) a[i] = s[threadIdx.x];
    if (threadIdx.x == 1023) bsum[blockIdx.x] = s[1023];
}

__global__ void scan2_kernel(int* __restrict__ bsum, int nb) {
    int acc = 0;
    for (int i = 0; i < nb; i++) { int t = bsum[i]; bsum[i] = acc; acc += t; }
}

__global__ void scan3_kernel(int* __restrict__ a, const int* __restrict__ bsum,
                             int* __restrict__ cur, int n, int N) {
    int i = blockIdx.x * 1024 + threadIdx.x;
    if (i < n) {
        int v = a[i] + bsum[blockIdx.x];
        a[i] = v;
        if (i < N) cur[i] = v;
    }
}

__global__ void scatter_kernel(const int* __restrict__ src, const int* __restrict__ dst,
                               int* __restrict__ cur, int* __restrict__ ssrc,
                               int* __restrict__ sdst, int E) {
    int e = blockIdx.x * blockDim.x + threadIdx.x;
    if (e < E) {
        int d = dst[e];
        int pos = atomicAdd(&cur[d], 1);
        sdst[pos] = d;
        ssrc[pos] = src[e];
    }
}

// ---------------- node GEMM (tensor, 3-term split): pq = fp16(in @ Wc + b1) ----
// Weight split done in registers from fp32 W1. mode 1: in = agg (finalize fused).
__global__ void __launch_bounds__(512, 1) node_mma_kernel(
    const float* __restrict__ in, const float* __restrict__ W1,
    const float* __restrict__ b1, const float* __restrict__ b2p,
    __half* __restrict__ pq, int N, int mode)
{
    extern __shared__ char sm[];
    __half* xh = (__half*)sm;          // [128][HST]
    __half* xl = xh + 128 * HST;       // [128][HST]

    int tid = threadIdx.x;
    int wid = tid >> 5, lane = tid & 31;
    int g = lane >> 2, tig = lane & 3;
    int m0 = wid * 16;

    unsigned ah[8][4], al[8][4];
    load_a_frags_wc(W1, m0 + g, tig, ah, al);

    float bias0 = (m0 + g < C) ? b1[m0 + g] : 0.f;
    float bias1 = (m0 + g + 8 < C) ? b1[m0 + g + 8] : 0.f;

    int n0 = blockIdx.x * 128;

    {
        int e = tid >> 2;
        int part = tid & 3;
        int node = n0 + e;
        const float4* xr = (const float4*)(in + (size_t)node * C + part * 32);
        const float4* b2r = (const float4*)(b2p + part * 32);
        unsigned* xhp = (unsigned*)(xh + e * HST + part * 32);
        unsigned* xlp = (unsigned*)(xl + e * HST + part * 32);
#pragma unroll
        for (int i = 0; i < 8; i++) {
            float4 v = (node < N) ? xr[i] : make_float4(0.f, 0.f, 0.f, 0.f);
            if (mode) {
                float4 bb = b2r[i];
                v.x = isfinite(v.x) ? fmaxf(v.x + bb.x, 0.f) : 0.f;
                v.y = isfinite(v.y) ? fmaxf(v.y + bb.y, 0.f) : 0.f;
                v.z = isfinite(v.z) ? fmaxf(v.z + bb.z, 0.f) : 0.f;
                v.w = isfinite(v.w) ? fmaxf(v.w + bb.w, 0.f) : 0.f;
            }
            unsigned lA, lB;
            unsigned hA = pack2(v.x, v.y, lA);
            unsigned hB = pack2(v.z, v.w, lB);
            xhp[i * 2 + 0] = hA;
            xhp[i * 2 + 1] = hB;
            xlp[i * 2 + 0] = lA;
            xlp[i * 2 + 1] = lB;
        }
    }
    __syncthreads();

    unsigned xh_lm = (unsigned)__cvta_generic_to_shared(xh)
                   + (unsigned)(((lane & 7) * HST + (lane >> 3) * 8) * 2);
    unsigned xl_lm = (unsigned)__cvta_generic_to_shared(xl)
                   + (unsigned)(((lane & 7) * HST + (lane >> 3) * 8) * 2);

#pragma unroll 1
    for (int et = 0; et < 16; et++) {
        int e0t = et * 8;
        unsigned eoff = (unsigned)(e0t * HST * 2);
        float d0 = 0.f, d1 = 0.f, d2 = 0.f, d3 = 0.f;
#pragma unroll
        for (int kb = 0; kb < 4; kb++) {
            unsigned koff = (unsigned)(kb * 64);
            unsigned bh0e, bh1e, bh0o, bh1o, bl0e, bl1e, bl0o, bl1o;
            ldmx4(xh_lm + eoff + koff, bh0e, bh1e, bh0o, bh1o);
            ldmx4(xl_lm + eoff + koff, bl0e, bl1e, bl0o, bl1o);
            int ks = kb * 2;
            mma16816(d0, d1, d2, d3, ah[ks][0], ah[ks][1], ah[ks][2], ah[ks][3], bh0e, bh1e);
            mma16816(d0, d1, d2, d3, ah[ks][0], ah[ks][1], ah[ks][2], ah[ks][3], bl0e, bl1e);
            mma16816(d0, d1, d2, d3, al[ks][0], al[ks][1], al[ks][2], al[ks][3], bh0e, bh1e);
            mma16816(d0, d1, d2, d3, ah[ks+1][0], ah[ks+1][1], ah[ks+1][2], ah[ks+1][3], bh0o, bh1o);
            mma16816(d0, d1, d2, d3, ah[ks+1][0], ah[ks+1][1], ah[ks+1][2], ah[ks+1][3], bl0o, bl1o);
            mma16816(d0, d1, d2, d3, al[ks+1][0], al[ks+1][1], al[ks+1][2], al[ks+1][3], bh0o, bh1o);
        }
        int eA = n0 + e0t + tig * 2;
        int eB = eA + 1;
        if (eA < N) {
            pq[(size_t)eA * 256 + m0 + g]     = __float2half_rn(d0 + bias0);
            pq[(size_t)eA * 256 + m0 + g + 8] = __float2half_rn(d2 + bias1);
        }
        if (eB < N) {
            pq[(size_t)eB * 256 + m0 + g]     = __float2half_rn(d1 + bias0);
            pq[(size_t)eB * 256 + m0 + g + 8] = __float2half_rn(d3 + bias1);
        }
    }
}

// ---------------- fused edge kernel: 2-barrier pipeline -------------------------
// 256 threads / 8 warps, 2 CTAs/SM. Per tile:
//   B1(cpwait+sync) -> [epilogue(i-1) on stage[cur^1] || convert(i) from stage[cur]]
//   -> B2 -> [load(i+1) -> stage[cur^1]; MMA(i) -> DT alias of stage[cur]]
__global__ void __launch_bounds__(256, 2) edge_fused_kernel(
    const __half* __restrict__ pq,
    const int* __restrict__ srcs, const int* __restrict__ dsts,
    const int* __restrict__ off, const float* __restrict__ W2,
    float* __restrict__ agg, int E)
{
    extern __shared__ char smraw[];
    __half* h_s = (__half*)smraw;                       // [TE2][HST] 17408B
    char* stage0 = (char*)(h_s + TE2 * HST);            // STAGE_B each
    char* stage1 = stage0 + STAGE_B;
    int* sidx0 = (int*)(stage1 + STAGE_B);              // [TE2]
    int* sidx1 = sidx0 + TE2;
    int* sps0 = sidx1 + TE2;                            // [TE2] p slot per edge
    int* sps1 = sps0 + TE2;

    int tid = threadIdx.x;
    int wid = tid >> 5, lane = tid & 31;
    int g = lane >> 2, tig = lane & 3;
    int m0 = wid * 16;

    int row = tid >> 2;        // edge row this thread stages/converts (0..63)
    int q4 = (tid & 3) * 4;    // first of 4 owned quads

    char* stg[2] = {stage0, stage1};
    int* sib[2] = {sidx0, sidx1};
    int* spsb[2] = {sps0, sps1};
    unsigned st_s[2] = {(unsigned)__cvta_generic_to_shared(stage0),
                        (unsigned)__cvta_generic_to_shared(stage1)};
    unsigned si_s[2] = {(unsigned)__cvta_generic_to_shared(sidx0),
                        (unsigned)__cvta_generic_to_shared(sidx1)};
    unsigned h_lm = (unsigned)__cvta_generic_to_shared(h_s)
                  + (unsigned)(((lane & 7) * HST + (lane >> 3) * 8) * 2);

    unsigned ah[8][4], al[8][4];
    load_a_frags_w2(W2, m0 + g, tig, ah, al);

    int ntiles = (E + TE2 - 1) / TE2;

    int pd, ps, po;
    auto prefetch = [&](int tile) {
        int ego = tile * TE2 + row;
        if (ego > E - 1) ego = E - 1;
        pd = __ldg(dsts + ego);
        ps = __ldg(srcs + ego);
        po = __ldg(off + pd);
    };

    auto load_tile = [&](int tile, int b) {
        int e0 = tile * TE2;
        {
            const char* qsrc = (const char*)(pq + (size_t)ps * 256 + C);
            unsigned base = st_s[b] + (unsigned)((64 + row) * 16) * 16;
            int sw = row & 7;
#pragma unroll
            for (int j = 0; j < 4; j++) {
                int c = q4 + j;
                cpasync16(base + (unsigned)((c ^ sw) * 16), qsrc + c * 16);
            }
        }
        int sp = po - e0;
        if (sp < 0) sp = 0;
        if (row == sp) {
            const char* psrc = (const char*)(pq + (size_t)pd * 256);
            unsigned base = st_s[b] + (unsigned)(sp * 16) * 16;
            int sw = sp & 7;
#pragma unroll
            for (int j = 0; j < 4; j++) {
                int c = q4 + j;
                cpasync16(base + (unsigned)((c ^ sw) * 16), psrc + c * 16);
            }
        }
        if ((tid & 3) == 0) spsb[b][row] = sp;
        if (tid < TE2 / 4) {
            int o = tid * 4;
            if (e0 + o + 3 < E) {
                cpasync16(si_s[b] + o * 4, dsts + e0 + o);
            } else {
                for (int j = 0; j < 4; j++)
                    sib[b][o + j] = (e0 + o + j < E) ? dsts[e0 + o + j] : -1;
            }
        }
        cpcommit();
    };

    auto epilogue = [&](int b) {
        const int* si = sib[b];
        const float* DT = (const float*)stg[b];
        int ch = tid & 127;
        int grp = tid >> 7;
        int base = grp * 32;
        int prev = si[base];
        float runmax = DT[base * DSTE + ch];
#pragma unroll
        for (int ii = 1; ii < 32; ii++) {
            int d = si[base + ii];
            float v = DT[(base + ii) * DSTE + ch];
            if (d != prev) {
                if (prev >= 0) atomicMaxF(agg + (size_t)prev * C + ch, runmax);
                prev = d;
                runmax = v;
            } else {
                runmax = fmaxf(runmax, v);
            }
        }
        if (prev >= 0) atomicMaxF(agg + (size_t)prev * C + ch, runmax);
    };

    if (blockIdx.x < ntiles) {
        prefetch(blockIdx.x);
        load_tile(blockIdx.x, 0);
        prefetch(blockIdx.x + gridDim.x < ntiles ? blockIdx.x + gridDim.x : blockIdx.x);
    }

    int have = 0, pb = 0;
    int i = 0;
    for (int tile = blockIdx.x; tile < ntiles; tile += gridDim.x, i++) {
        int cur = i & 1;
        cpwait0();
        __syncthreads();   // B1: load(i) visible; MMA(i-1) writes to DT[cur^1] done

        // deferred epilogue of tile i-1 (stage[cur^1]) — overlaps convert's loads
        if (have) epilogue(pb);

        // convert: h[e][ch] = relu(p16[slot] + q16[e]); 4 quads per thread
        {
            int e = row;
            const uint4* stp = (const uint4*)stg[cur];
            __half* hrow = h_s + e * HST;
            int sp = spsb[cur][e];
            int swp = sp & 7, swq = e & 7;
            const __half2 z2 = __floats2half2_rn(0.f, 0.f);
#pragma unroll
            for (int j = 0; j < 4; j++) {
                int c = q4 + j;
                uint4 pv = stp[sp * 16 + (c ^ swp)];
                uint4 qv = stp[(64 + e) * 16 + (c ^ swq)];
                __half2* p2 = (__half2*)&pv;
                __half2* q2 = (__half2*)&qv;
                uint4 out;
                __half2* o2 = (__half2*)&out;
#pragma unroll
                for (int k = 0; k < 4; k++)
                    o2[k] = __hmax2(__hadd2(p2[k], q2[k]), z2);
                *(uint4*)(hrow + c * 8) = out;
            }
        }
        __syncthreads();   // B2: h_s ready; stage[cur] (convert) + stage[cur^1] (epi) free

        // issue next tile's loads first (maximum latency cover under MMA)
        int nt = tile + gridDim.x;
        if (nt < ntiles) {
            load_tile(nt, cur ^ 1);
            int nnt = nt + gridDim.x;
            prefetch(nnt < ntiles ? nnt : nt);
        }

        float* DT = (float*)stg[cur];   // stage[cur] dead -> DT alias

        // MMA: 8 edge-subtiles of 8, K=128 via 4 ldmatrix.x4, 2 terms
#pragma unroll 1
        for (int et = 0; et < 8; et++) {
            int e0t = et * 8;
            unsigned eoff = (unsigned)(e0t * HST * 2);
            float d0 = 0.f, d1 = 0.f, d2 = 0.f, d3 = 0.f;
#pragma unroll
            for (int kb = 0; kb < 4; kb++) {
                unsigned b0e, b1e, b0o, b1o;
                ldmx4(h_lm + eoff + (unsigned)(kb * 64), b0e, b1e, b0o, b1o);
                int ks = kb * 2;
                mma16816(d0, d1, d2, d3, ah[ks][0], ah[ks][1], ah[ks][2], ah[ks][3], b0e, b1e);
                mma16816(d0, d1, d2, d3, al[ks][0], al[ks][1], al[ks][2], al[ks][3], b0e, b1e);
                mma16816(d0, d1, d2, d3, ah[ks+1][0], ah[ks+1][1], ah[ks+1][2], ah[ks+1][3], b0o, b1o);
                mma16816(d0, d1, d2, d3, al[ks+1][0], al[ks+1][1], al[ks+1][2], al[ks+1][3], b0o, b1o);
            }
            int eA = e0t + tig * 2, eB = eA + 1;
            DT[eA * DSTE + m0 + g]     = d0;
            DT[eB * DSTE + m0 + g]     = d1;
            DT[eA * DSTE + m0 + g + 8] = d2;
            DT[eB * DSTE + m0 + g + 8] = d3;
        }

        have = 1;
        pb = cur;
    }
    __syncthreads();           // last MMA's DT writes visible
    if (have) epilogue(pb);
}

// ---------------- finalize (last layer only): empty->0, +b2 --------------------
__global__ void finalize_kernel(const float* __restrict__ agg,
                                const float* __restrict__ b2,
                                float* __restrict__ out, int N)
{
    int idx = blockIdx.x * blockDim.x + threadIdx.x;
    if (idx >= N * C) return;
    int c = idx & (C - 1);
    float v = agg[idx];
    out[idx] = isfinite(v) ? (v + b2[c]) : 0.f;
}

// ---------------- launch -------------------------------------------------------
extern "C" void kernel_launch(void* const* d_in, const int* in_sizes, int n_in,
                              void* d_out, int out_size)
{
    const float* x  = (const float*)d_in[0];
    const int*   ei = (const int*)d_in[1];
    int N = in_sizes[0] / C;
    int E = in_sizes[1] / 2;
    const int* srcp = ei;
    const int* dstp = ei + E;

    float *aggp;
    __half *pq;
    int *off, *curp, *bsum, *srcs, *dsts;
    cudaGetSymbolAddress((void**)&pq,   g_pq);
    cudaGetSymbolAddress((void**)&aggp, g_agg);
    cudaGetSymbolAddress((void**)&off,  g_off);
    cudaGetSymbolAddress((void**)&curp, g_cur);
    cudaGetSymbolAddress((void**)&bsum, g_bsum);
    cudaGetSymbolAddress((void**)&srcs, g_srcs);
    cudaGetSymbolAddress((void**)&dsts, g_dsts);

    // ---- sort edges by dst (once; reused by all 3 layers) ----
    int nscan = N + 1;
    int nb = (nscan + 1023) / 1024;
    cudaMemsetAsync(off, 0, (size_t)(N + 1) * sizeof(int));
    hist_kernel<<<(E + 255) / 256, 256>>>(dstp, off, E);
    scan1_kernel<<<nb, 1024>>>(off, bsum, nscan);
    scan2_kernel<<<1, 1>>>(bsum, nb);
    scan3_kernel<<<nb, 1024>>>(off, bsum, curp, nscan, N);
    scatter_kernel<<<(E + 255) / 256, 256>>>(srcp, dstp, curp, srcs, dsts, E);

    const size_t SMEM_E = (size_t)(TE2 * HST) * sizeof(__half)
                        + 2 * (size_t)STAGE_B
                        + 4 * TE2 * sizeof(int);
    cudaFuncSetAttribute(edge_fused_kernel, cudaFuncAttributeMaxDynamicSharedMemorySize, (int)SMEM_E);
    const size_t SMEM_N = (size_t)(2 * 128 * HST) * sizeof(__half);
    cudaFuncSetAttribute(node_mma_kernel, cudaFuncAttributeMaxDynamicSharedMemorySize, (int)SMEM_N);

    const float* Ws[3][4] = {
        {(const float*)d_in[2],  (const float*)d_in[3],  (const float*)d_in[4],  (const float*)d_in[5]},
        {(const float*)d_in[6],  (const float*)d_in[7],  (const float*)d_in[8],  (const float*)d_in[9]},
        {(const float*)d_in[10], (const float*)d_in[11], (const float*)d_in[12], (const float*)d_in[13]},
    };

    for (int l = 0; l < 3; l++) {
        const float* W1 = Ws[l][0];
        const float* b1 = Ws[l][1];
        const float* W2 = Ws[l][2];

        if (l == 0) {
            node_mma_kernel<<<(N + 127) / 128, 512, SMEM_N>>>(
                x, W1, b1, b1 /*unused*/, pq, N, 0);
        } else {
            node_mma_kernel<<<(N + 127) / 128, 512, SMEM_N>>>(
                aggp, W1, b1, Ws[l - 1][3], pq, N, 1);
        }
        cudaMemsetAsync(aggp, 0xFF, (size_t)N * C * sizeof(float));
        edge_fused_kernel<<<296, 256, SMEM_E>>>(pq, srcs, dsts, off, W2, aggp, E);
    }
    finalize_kernel<<<(N * C + 255) / 256, 256>>>(aggp, Ws[2][3], (float*)d_out, N);
}